// round 8
// baseline (speedup 1.0000x reference)
#include <cuda_runtime.h>
#include <math.h>

#define Bn 4
#define CIN 8
#define HH 252
#define WW 2048
#define CM 16
#define DD 12
#define FF 84
#define LL (FF*WW)          /* 172032 */
#define EPSf 1.01e-8f
#define HROW 2056           /* padded row: 4 zero cols each side */
#define HOFF 4
#define CSH 8.0f            /* fixed softmax shift */

typedef unsigned long long u64;

__device__ __forceinline__ u64 fma2(u64 a, u64 b, u64 c){
    u64 d; asm("fma.rn.f32x2 %0, %1, %2, %3;" : "=l"(d) : "l"(a), "l"(b), "l"(c)); return d;
}
__device__ __forceinline__ u64 pk2(float lo, float hi){
    u64 r; asm("mov.b64 %0, {%1, %2};" : "=l"(r) : "f"(lo), "f"(hi)); return r;
}
__device__ __forceinline__ void upk2(u64 v, float& lo, float& hi){
    asm("mov.b64 {%0, %1}, %2;" : "=f"(lo), "=f"(hi) : "l"(v));
}
__device__ __forceinline__ float wredsum(float v){
    #pragma unroll
    for (int o = 16; o > 0; o >>= 1) v += __shfl_xor_sync(0xffffffffu, v, o);
    return v;
}
__device__ __forceinline__ float sigm(float x){
    float t;
    asm("tanh.approx.f32 %0, %1;" : "=f"(t) : "f"(x*0.5f));
    return fmaf(0.5f, t, 0.5f);
}
__device__ __forceinline__ float lrelu(float v){ return v >= 0.f ? v : 0.01f*v; }

// ------------- scratch (device globals; zero-initialized at load) -------------
__device__ __align__(16) float g_h [(size_t)Bn*CM*HH*HROW];  // padded, borders stay 0
// channel-major: [b][d][L]
__device__ __align__(16) float g_q [(size_t)Bn*DD*LL];
__device__ __align__(16) float g_k [(size_t)Bn*DD*LL];
__device__ __align__(16) float g_v [(size_t)Bn*DD*LL];
__device__ __align__(16) float g_si[(size_t)Bn*LL];
__device__ float g_msum[Bn], g_sumexp[Bn];
__device__ float g_qsum[Bn][DD], g_ksum[Bn][DD], g_sq[Bn][DD], g_skv[Bn][DD];
__device__ float g_kvm[Bn][DD*DD];
__device__ float g_M[Bn][DD*DD];

// ------------- K0: zero accumulators -------------
__global__ void k_init(){
    int t = threadIdx.x;
    if (t < Bn){ g_msum[t]=0.f; g_sumexp[t]=0.f; }
    if (t < Bn*DD){
        ((float*)g_qsum)[t]=0.f; ((float*)g_ksum)[t]=0.f;
        ((float*)g_sq)[t]=0.f;   ((float*)g_skv)[t]=0.f;
    }
    if (t < Bn*DD*DD) ((float*)g_kvm)[t]=0.f;
}

// ------------- mask sum per batch -------------
__global__ void __launch_bounds__(256) k_msum(const float* __restrict__ frame){
    int b = blockIdx.y;
    int i = (blockIdx.x*256 + threadIdx.x)*4;
    float4 v = *(const float4*)(frame + (size_t)b*LL + i);
    float s = v.x + v.y + v.z + v.w;
    s = wredsum(s);
    __shared__ float sr;
    if (threadIdx.x == 0) sr = 0.f;
    __syncthreads();
    if ((threadIdx.x & 31) == 0) atomicAdd(&sr, s);
    __syncthreads();
    if (threadIdx.x == 0) atomicAdd(&g_msum[b], sr);
}

// ------------- K1: conv5x5(same) + BN + LeakyReLU, f32x2-packed -------------
__global__ void __launch_bounds__(256,2) k_conv1(
    const float* __restrict__ x, const float* __restrict__ wpre,
    const float* __restrict__ bpre, const float* __restrict__ gam,
    const float* __restrict__ bet,  const float* __restrict__ mean,
    const float* __restrict__ var)
{
    extern __shared__ float sm1[];
    float* xs = sm1;                        // 8*12*132 = 12672 floats
    u64*   ws = (u64*)(sm1 + 12672);        // 3200 u64, 16B-aligned
    int b = blockIdx.z, r0 = blockIdx.y*8, c0 = blockIdx.x*128;
    int tid = threadIdx.x;

    for (int i = tid; i < 3200; i += 256){
        int o = i & 15, rest = i >> 4;
        int kw = rest % 5, kh = (rest/5) % 5, c = rest/25;
        float w = wpre[((o*CIN + c)*5 + kh)*5 + kw];
        ws[i] = pk2(w, w);
    }
    for (int i = tid; i < 12672; i += 256){
        int cc = i % 132; int t2 = i / 132; int rr = t2 % 12; int c = t2 / 12;
        int gr = r0 - 2 + rr, gc = c0 - 2 + cc;
        float v = 0.f;
        if (gr >= 0 && gr < HH && gc >= 0 && gc < WW)
            v = x[(((size_t)b*CIN + c)*HH + gr)*WW + gc];
        xs[i] = v;
    }
    __syncthreads();

    int r = tid >> 5, cg = tid & 31, col0 = cg*4;
    u64 acc[16][2];
    #pragma unroll
    for (int o = 0; o < 16; o++){ acc[o][0]=0ull; acc[o][1]=0ull; }

    #pragma unroll 1
    for (int c = 0; c < 8; c++){
        #pragma unroll
        for (int kh = 0; kh < 5; kh++){
            const float* row = xs + (c*12 + r + kh)*132 + col0;
            float4 A = *(const float4*)row;
            float4 Bv = *(const float4*)(row + 4);
            float a0=A.x,a1=A.y,a2=A.z,a3=A.w,a4=Bv.x,a5=Bv.y,a6=Bv.z,a7=Bv.w;
            u64 P0[5] = {pk2(a0,a1),pk2(a1,a2),pk2(a2,a3),pk2(a3,a4),pk2(a4,a5)};
            u64 P1[5] = {pk2(a2,a3),pk2(a3,a4),pk2(a4,a5),pk2(a5,a6),pk2(a6,a7)};
            const u64* wbase = ws + (c*5 + kh)*80;
            #pragma unroll
            for (int kw = 0; kw < 5; kw++){
                const ulonglong2* wrow = (const ulonglong2*)(wbase + kw*16);
                #pragma unroll
                for (int o2 = 0; o2 < 8; o2++){
                    ulonglong2 wv = wrow[o2];
                    acc[2*o2  ][0] = fma2(P0[kw], wv.x, acc[2*o2  ][0]);
                    acc[2*o2  ][1] = fma2(P1[kw], wv.x, acc[2*o2  ][1]);
                    acc[2*o2+1][0] = fma2(P0[kw], wv.y, acc[2*o2+1][0]);
                    acc[2*o2+1][1] = fma2(P1[kw], wv.y, acc[2*o2+1][1]);
                }
            }
        }
    }
    int orow = r0 + r;
    if (orow < HH){
        #pragma unroll
        for (int o = 0; o < 16; o++){
            float s  = gam[o] * rsqrtf(var[o] + 1e-5f);
            float c2 = bet[o] + (bpre[o] - mean[o]) * s;
            float v0,v1,v2,v3;
            upk2(acc[o][0], v0, v1); upk2(acc[o][1], v2, v3);
            float4 o4;
            o4.x = lrelu(v0*s + c2); o4.y = lrelu(v1*s + c2);
            o4.z = lrelu(v2*s + c2); o4.w = lrelu(v3*s + c2);
            *(float4*)(g_h + (((size_t)b*CM + o)*HH + orow)*HROW + HOFF + c0 + col0) = o4;
        }
    }
}

// ------------- K2: FUSED Q/KV convs + masknorm + projections + sums -------------
// grid (4, 84, 4), block 256. Phase 1: conv 4 pos/thread (warps 0-3 q, 4-7 kv).
// Phase 2: 2 pos/thread; outputs stored channel-major [b][d][L] as STG.64.
#define QKV_SMEM (3456*8 + 432*8 + 12288*4 + 96*4)
__global__ void __launch_bounds__(256,2) k_qkv2(
    const float* __restrict__ wq,  const float* __restrict__ bqc,
    const float* __restrict__ wkv, const float* __restrict__ bkvc,
    const float* __restrict__ frame, const float* __restrict__ Tp,
    const float* __restrict__ fwq, const float* __restrict__ fbq,
    const float* __restrict__ fwk, const float* __restrict__ fbk,
    const float* __restrict__ fwv, const float* __restrict__ fbv)
{
    extern __shared__ __align__(16) char smraw[];
    u64*   ws  = (u64*)smraw;                  // 3456
    u64*   fwT = ws + 3456;                    // 432, [proj][j][d] packed (w,w)
    float* ex  = (float*)(fwT + 432);          // 24*512 floats
    float* cbs = ex + 12288;                   // 24
    float* fbs = cbs + 24;                     // 36
    float* red = fbs + 36;                     // 24

    int b = blockIdx.z, f = blockIdx.y;
    int tid = threadIdx.x;

    for (int i = tid; i < 3456; i += 256){
        int half2 = i / 1728, rem = i % 1728;
        int d = rem % 12, r2 = rem / 12;
        int kw = r2 % 3, kh = (r2/3) % 3, c = r2/9;
        const float* srcw = half2 ? wkv : wq;
        float w = srcw[((d*CM + c)*3 + kh)*3 + kw];
        ws[i] = pk2(w, w);
    }
    for (int i = tid; i < 432; i += 256){
        int wsel = i / 144, rem = i % 144, j = rem / 12, d = rem % 12;
        float w = (wsel == 0 ? fwq : (wsel == 1 ? fwk : fwv))[d*12 + j];
        fwT[i] = pk2(w, w);
    }
    if (tid < 24) cbs[tid] = (tid < 12) ? bqc[tid] : bkvc[tid-12];
    if (tid < 36) fbs[tid] = (tid < 12) ? fbq[tid] : (tid < 24 ? fbk[tid-12] : fbv[tid-24]);
    if (tid < 24) red[tid] = 0.f;
    __syncthreads();

    // ---- Phase 1: conv, 4 positions/thread ----
    {
        int half = tid >> 7, pt = tid & 127, lane = tid & 31;
        int t0 = blockIdx.x*512 + pt*4;
        u64 acc[12][2];
        #pragma unroll
        for (int d = 0; d < 12; d++){
            u64 bb = pk2(cbs[half*12+d], cbs[half*12+d]);
            acc[d][0] = bb; acc[d][1] = bb;
        }
        const float* hb = g_h + (((size_t)b*CM)*HH + 3*f)*HROW + HOFF + t0;
        const u64* wsh = ws + half*1728;
        #pragma unroll 1
        for (int c = 0; c < 16; c++){
            #pragma unroll
            for (int kh = 0; kh < 3; kh++){
                const float* row = hb + ((size_t)c*HH + kh)*HROW;
                float4 F = *(const float4*)row;
                float xm1 = __shfl_up_sync(0xffffffffu, F.w, 1);
                if (lane == 0)  xm1 = row[-1];
                float xp4 = __shfl_down_sync(0xffffffffu, F.x, 1);
                if (lane == 31) xp4 = row[4];
                u64 P[3][2];
                P[0][0] = pk2(xm1, F.x); P[0][1] = pk2(F.y, F.z);
                P[1][0] = pk2(F.x, F.y); P[1][1] = pk2(F.z, F.w);
                P[2][0] = pk2(F.y, F.z); P[2][1] = pk2(F.w, xp4);
                const u64* wp = wsh + (c*3 + kh)*36;
                #pragma unroll
                for (int kw = 0; kw < 3; kw++){
                    const ulonglong2* w2 = (const ulonglong2*)(wp + kw*12);
                    #pragma unroll
                    for (int dp = 0; dp < 6; dp++){
                        ulonglong2 wv = w2[dp];
                        acc[2*dp  ][0] = fma2(P[kw][0], wv.x, acc[2*dp  ][0]);
                        acc[2*dp  ][1] = fma2(P[kw][1], wv.x, acc[2*dp  ][1]);
                        acc[2*dp+1][0] = fma2(P[kw][0], wv.y, acc[2*dp+1][0]);
                        acc[2*dp+1][1] = fma2(P[kw][1], wv.y, acc[2*dp+1][1]);
                    }
                }
            }
        }
        float* exb = ex + (half*12)*512 + pt*4;
        #pragma unroll
        for (int d = 0; d < 12; d++){
            float v0,v1,v2,v3;
            upk2(acc[d][0], v0, v1); upk2(acc[d][1], v2, v3);
            *(float4*)(exb + d*512) = make_float4(v0,v1,v2,v3);
        }
    }
    __syncthreads();

    // ---- Phase 2: masknorm + projections (2 positions/thread, packed) ----
    {
        int lp = tid*2;
        size_t l0 = (size_t)f*WW + blockIdx.x*512 + lp;
        u64 inq[12], ckv[12];
        #pragma unroll
        for (int d = 0; d < 12; d++) inq[d] = *(const u64*)(ex + d*512 + lp);
        u64 s2p = pk2(EPSf, EPSf);
        #pragma unroll
        for (int d = 0; d < 12; d++){
            ckv[d] = *(const u64*)(ex + (12+d)*512 + lp);
            s2p = fma2(ckv[d], ckv[d], s2p);
        }
        float s20, s21; upk2(s2p, s20, s21);
        float cf = Tp[0] / g_msum[b];
        float2 mk = *(const float2*)(frame + (size_t)b*LL + l0);
        u64 sc2 = pk2(mk.x*cf*rsqrtf(s20), mk.y*cf*rsqrtf(s21));

        // Q projection + sigmoid
        {
            float qs[12];
            #pragma unroll
            for (int j = 0; j < 12; j++){
                u64 a = pk2(fbs[j], fbs[j]);
                const ulonglong2* wv = (const ulonglong2*)(fwT + j*12);
                #pragma unroll
                for (int dp = 0; dp < 6; dp++){
                    ulonglong2 w = wv[dp];
                    a = fma2(inq[2*dp  ], w.x, a);
                    a = fma2(inq[2*dp+1], w.y, a);
                }
                float x0, x1; upk2(a, x0, x1);
                x0 = sigm(x0); x1 = sigm(x1);
                *(u64*)(g_q + ((size_t)b*DD + j)*LL + l0) = pk2(x0, x1);
                qs[j] = x0 + x1;
            }
            #pragma unroll
            for (int j = 0; j < 12; j++){
                float s = wredsum(qs[j]);
                if ((tid & 31) == 0) atomicAdd(&red[j], s);
            }
        }
        #pragma unroll
        for (int d = 0; d < 12; d++) ckv[d] = fma2(ckv[d], sc2, 0ull);
        // K projection + sigmoid
        {
            float ks[12];
            #pragma unroll
            for (int j = 0; j < 12; j++){
                u64 a = pk2(fbs[12+j], fbs[12+j]);
                const ulonglong2* wv = (const ulonglong2*)(fwT + 144 + j*12);
                #pragma unroll
                for (int dp = 0; dp < 6; dp++){
                    ulonglong2 w = wv[dp];
                    a = fma2(ckv[2*dp  ], w.x, a);
                    a = fma2(ckv[2*dp+1], w.y, a);
                }
                float x0, x1; upk2(a, x0, x1);
                x0 = sigm(x0); x1 = sigm(x1);
                *(u64*)(g_k + ((size_t)b*DD + j)*LL + l0) = pk2(x0, x1);
                ks[j] = x0 + x1;
            }
            #pragma unroll
            for (int j = 0; j < 12; j++){
                float s = wredsum(ks[j]);
                if ((tid & 31) == 0) atomicAdd(&red[12+j], s);
            }
        }
        // V projection
        #pragma unroll
        for (int j = 0; j < 12; j++){
            u64 a = pk2(fbs[24+j], fbs[24+j]);
            const ulonglong2* wv = (const ulonglong2*)(fwT + 288 + j*12);
            #pragma unroll
            for (int dp = 0; dp < 6; dp++){
                ulonglong2 w = wv[dp];
                a = fma2(ckv[2*dp  ], w.x, a);
                a = fma2(ckv[2*dp+1], w.y, a);
            }
            *(u64*)(g_v + ((size_t)b*DD + j)*LL + l0) = a;
        }
    }
    __syncthreads();
    if (tid < 12)       atomicAdd(&g_qsum[b][tid], red[tid]);
    else if (tid < 24)  atomicAdd(&g_ksum[b][tid-12], red[tid]);
}

// ------------- K3: sink_in / src_out + sq/skv sums (4 pos/thread, coalesced) -------------
__global__ void __launch_bounds__(256) k3(){
    int b = blockIdx.y;
    int tid = threadIdx.x;
    int l0 = (blockIdx.x*256 + tid)*4;
    __shared__ float kE[12], qE[12], red[24];
    if (tid < 12){ kE[tid] = g_ksum[b][tid] + EPSf; qE[tid] = g_qsum[b][tid] + EPSf; }
    if (tid < 24) red[tid] = 0.f;
    __syncthreads();
    float4 q4[12], k4[12];
    #pragma unroll
    for (int d = 0; d < 12; d++){
        q4[d] = *(const float4*)(g_q + ((size_t)b*DD + d)*LL + l0);
        k4[d] = *(const float4*)(g_k + ((size_t)b*DD + d)*LL + l0);
    }
    float4 si = make_float4(0,0,0,0), so = make_float4(0,0,0,0);
    #pragma unroll
    for (int d = 0; d < 12; d++){
        si.x += (q4[d].x+EPSf)*kE[d]; si.y += (q4[d].y+EPSf)*kE[d];
        si.z += (q4[d].z+EPSf)*kE[d]; si.w += (q4[d].w+EPSf)*kE[d];
        so.x += (k4[d].x+EPSf)*qE[d]; so.y += (k4[d].y+EPSf)*qE[d];
        so.z += (k4[d].z+EPSf)*qE[d]; so.w += (k4[d].w+EPSf)*qE[d];
    }
    si.x = 1.f/si.x; si.y = 1.f/si.y; si.z = 1.f/si.z; si.w = 1.f/si.w;
    so.x = 1.f/so.x; so.y = 1.f/so.y; so.z = 1.f/so.z; so.w = 1.f/so.w;
    *(float4*)(g_si + (size_t)b*LL + l0) = si;
    #pragma unroll
    for (int d = 0; d < 12; d++){
        float sqv  = q4[d].x*si.x + q4[d].y*si.y + q4[d].z*si.z + q4[d].w*si.w;
        float skvv = k4[d].x*so.x + k4[d].y*so.y + k4[d].z*so.z + k4[d].w*so.w;
        sqv = wredsum(sqv); skvv = wredsum(skvv);
        if ((tid & 31) == 0){ atomicAdd(&red[d], sqv); atomicAdd(&red[12+d], skvv); }
    }
    __syncthreads();
    if (tid < 12)      atomicAdd(&g_sq[b][tid], red[tid]);
    else if (tid < 24) atomicAdd(&g_skv[b][tid-12], red[tid]);
}

// ------------- K456: cons + exp(cons-CSH) + sumexp + kv outer product -------------
__global__ void __launch_bounds__(256,1) k456(){
    int b = blockIdx.y;
    int tid = threadIdx.x;
    __shared__ float sqE[12];
    if (tid < 12) sqE[tid] = g_sq[b][tid] + EPSf;
    __syncthreads();
    float acc[12][12];
    #pragma unroll
    for (int d = 0; d < 12; d++)
        #pragma unroll
        for (int m = 0; m < 12; m++) acc[d][m] = 0.f;
    float se = 0.f;

    for (int l = blockIdx.x*256 + tid; l < LL; l += 96*256){
        float k[12], v[12];
        #pragma unroll
        for (int d = 0; d < 12; d++){
            k[d] = g_k[((size_t)b*DD + d)*LL + l];
            v[d] = g_v[((size_t)b*DD + d)*LL + l];
        }
        float cons = 0.f;
        #pragma unroll
        for (int d = 0; d < 12; d++) cons += (k[d]+EPSf)*sqE[d];
        float e = __expf(cons - CSH);
        se += e;
        #pragma unroll
        for (int m = 0; m < 12; m++) v[m] *= e;
        #pragma unroll
        for (int d = 0; d < 12; d++)
            #pragma unroll
            for (int m = 0; m < 12; m++) acc[d][m] += k[d]*v[m];
    }
    __shared__ float red[144];
    __shared__ float sred;
    for (int i = tid; i < 144; i += 256) red[i] = 0.f;
    if (tid == 0) sred = 0.f;
    __syncthreads();
    se = wredsum(se);
    if ((tid & 31) == 0) atomicAdd(&sred, se);
    #pragma unroll
    for (int d = 0; d < 12; d++)
        #pragma unroll
        for (int m = 0; m < 12; m++){
            float v = wredsum(acc[d][m]);
            if ((tid & 31) == 0) atomicAdd(&red[d*12+m], v);
        }
    __syncthreads();
    if (tid < 144) atomicAdd(&g_kvm[b][tid], red[tid]);
    if (tid == 0)  atomicAdd(&g_sumexp[b], sred);
}

// ------------- Kmm: M = kv_norm @ Wo -------------
__global__ void kmm(const float* __restrict__ fwo){
    int b = blockIdx.x, tid = threadIdx.x;
    float norm = 172032.0f / g_sumexp[b];
    int d = tid/12, j = tid%12;
    float s = 0.f;
    #pragma unroll
    for (int m = 0; m < 12; m++) s += g_kvm[b][d*12+m]*fwo[m*12+j];
    g_M[b][tid] = s * norm;
}

// ------------- K7: epilogue (4 pos/thread, coalesced) -------------
__global__ void __launch_bounds__(256) k7(const float* __restrict__ fbo, float* __restrict__ out){
    int b = blockIdx.y;
    int tid = threadIdx.x;
    int l0 = (blockIdx.x*256 + tid)*4;
    __shared__ float Ms[144], skvE[12], bos[12];
    if (tid < 144) Ms[tid] = g_M[b][tid];
    if (tid < 12){ skvE[tid] = g_skv[b][tid] + EPSf; bos[tid] = fbo[tid]; }
    __syncthreads();
    float4 q4[12];
    #pragma unroll
    for (int d = 0; d < 12; d++)
        q4[d] = *(const float4*)(g_q + ((size_t)b*DD + d)*LL + l0);
    float4 cs = make_float4(0,0,0,0);
    #pragma unroll
    for (int d = 0; d < 12; d++){
        cs.x += (q4[d].x+EPSf)*skvE[d]; cs.y += (q4[d].y+EPSf)*skvE[d];
        cs.z += (q4[d].z+EPSf)*skvE[d]; cs.w += (q4[d].w+EPSf)*skvE[d];
    }
    float4 si = *(const float4*)(g_si + (size_t)b*LL + l0);
    float4 sc;
    sc.x = si.x*sigm(cs.x); sc.y = si.y*sigm(cs.y);
    sc.z = si.z*sigm(cs.z); sc.w = si.w*sigm(cs.w);
    #pragma unroll
    for (int j = 0; j < 12; j++){
        float4 o = make_float4(0,0,0,0);
        #pragma unroll
        for (int d = 0; d < 12; d++){
            float w = Ms[d*12+j];
            o.x += q4[d].x*w; o.y += q4[d].y*w;
            o.z += q4[d].z*w; o.w += q4[d].w*w;
        }
        float4 r;
        r.x = bos[j] + sc.x*o.x; r.y = bos[j] + sc.y*o.y;
        r.z = bos[j] + sc.z*o.z; r.w = bos[j] + sc.w*o.w;
        *(float4*)(out + ((size_t)b*DD + j)*LL + l0) = r;
    }
}

extern "C" void kernel_launch(void* const* d_in, const int* in_sizes, int n_in,
                              void* d_out, int out_size){
    const float* x     = (const float*)d_in[0];
    const float* frame = (const float*)d_in[1];
    const float* wpre  = (const float*)d_in[2];
    const float* bpre  = (const float*)d_in[3];
    const float* gam   = (const float*)d_in[4];
    const float* bet   = (const float*)d_in[5];
    const float* mean  = (const float*)d_in[6];
    const float* var   = (const float*)d_in[7];
    const float* Tp    = (const float*)d_in[8];
    const float* wq    = (const float*)d_in[9];
    const float* bqc   = (const float*)d_in[10];
    const float* wkv   = (const float*)d_in[11];
    const float* bkvc  = (const float*)d_in[12];
    const float* fwq   = (const float*)d_in[13];
    const float* fbq   = (const float*)d_in[14];
    const float* fwk   = (const float*)d_in[15];
    const float* fbk   = (const float*)d_in[16];
    const float* fwv   = (const float*)d_in[17];
    const float* fbv   = (const float*)d_in[18];
    const float* fwo   = (const float*)d_in[19];
    const float* fbo   = (const float*)d_in[20];
    float* out = (float*)d_out;

    cudaFuncSetAttribute(k_conv1, cudaFuncAttributeMaxDynamicSharedMemorySize, 76288);
    cudaFuncSetAttribute(k_qkv2,  cudaFuncAttributeMaxDynamicSharedMemorySize, QKV_SMEM);

    k_init  <<<1, 1024>>>();
    k_msum  <<<dim3(168, Bn), 256>>>(frame);
    k_conv1 <<<dim3(16, 32, Bn), 256, 76288>>>(x, wpre, bpre, gam, bet, mean, var);
    k_qkv2  <<<dim3(4, FF, Bn), 256, QKV_SMEM>>>(wq, bqc, wkv, bkvc, frame, Tp,
                                                 fwq, fbq, fwk, fbk, fwv, fbv);
    k3   <<<dim3(168, Bn), 256>>>();
    k456 <<<dim3(96, Bn), 256>>>();
    kmm  <<<Bn, 144>>>(fwo);
    k7   <<<dim3(168, Bn), 256>>>(fbo, out);
    (void)in_sizes; (void)n_in; (void)out_size;
}

// round 9
// speedup vs baseline: 1.0455x; 1.0455x over previous
#include <cuda_runtime.h>
#include <math.h>

#define Bn 4
#define CIN 8
#define HH 252
#define WW 2048
#define CM 16
#define DD 12
#define FF 84
#define LL (FF*WW)          /* 172032 */
#define EPSf 1.01e-8f
#define HROW 2056           /* padded row: 4 zero cols each side */
#define HOFF 4
#define CSH 8.0f            /* fixed softmax shift */

typedef unsigned long long u64;

__device__ __forceinline__ u64 fma2(u64 a, u64 b, u64 c){
    u64 d; asm("fma.rn.f32x2 %0, %1, %2, %3;" : "=l"(d) : "l"(a), "l"(b), "l"(c)); return d;
}
__device__ __forceinline__ u64 pk2(float lo, float hi){
    u64 r; asm("mov.b64 %0, {%1, %2};" : "=l"(r) : "f"(lo), "f"(hi)); return r;
}
__device__ __forceinline__ void upk2(u64 v, float& lo, float& hi){
    asm("mov.b64 {%0, %1}, %2;" : "=f"(lo), "=f"(hi) : "l"(v));
}
__device__ __forceinline__ float wredsum(float v){
    #pragma unroll
    for (int o = 16; o > 0; o >>= 1) v += __shfl_xor_sync(0xffffffffu, v, o);
    return v;
}
__device__ __forceinline__ float sigm(float x){
    float t;
    asm("tanh.approx.f32 %0, %1;" : "=f"(t) : "f"(x*0.5f));
    return fmaf(0.5f, t, 0.5f);
}
__device__ __forceinline__ float lrelu(float v){ return v >= 0.f ? v : 0.01f*v; }

// ------------- scratch (device globals; zero-initialized at load) -------------
__device__ __align__(16) float g_h [(size_t)Bn*CM*HH*HROW];  // padded, borders stay 0
// channel-major: [b][d][L]
__device__ __align__(16) float g_q [(size_t)Bn*DD*LL];
__device__ __align__(16) float g_k [(size_t)Bn*DD*LL];
__device__ __align__(16) float g_v [(size_t)Bn*DD*LL];
__device__ float g_msum[Bn], g_sumexp[Bn];
__device__ float g_qsum[Bn][DD], g_ksum[Bn][DD], g_sq[Bn][DD], g_skv[Bn][DD];
__device__ float g_kvm[Bn][DD*DD];
__device__ float g_M[Bn][DD*DD];

// ------------- K0: zero accumulators -------------
__global__ void k_init(){
    int t = threadIdx.x;
    if (t < Bn){ g_msum[t]=0.f; g_sumexp[t]=0.f; }
    if (t < Bn*DD){
        ((float*)g_qsum)[t]=0.f; ((float*)g_ksum)[t]=0.f;
        ((float*)g_sq)[t]=0.f;   ((float*)g_skv)[t]=0.f;
    }
    if (t < Bn*DD*DD) ((float*)g_kvm)[t]=0.f;
}

// ------------- mask sum per batch -------------
__global__ void __launch_bounds__(256) k_msum(const float* __restrict__ frame){
    int b = blockIdx.y;
    int i = (blockIdx.x*256 + threadIdx.x)*4;
    float4 v = *(const float4*)(frame + (size_t)b*LL + i);
    float s = v.x + v.y + v.z + v.w;
    s = wredsum(s);
    __shared__ float sr;
    if (threadIdx.x == 0) sr = 0.f;
    __syncthreads();
    if ((threadIdx.x & 31) == 0) atomicAdd(&sr, s);
    __syncthreads();
    if (threadIdx.x == 0) atomicAdd(&g_msum[b], sr);
}

// ------------- K1: conv5x5 + BN + LeakyReLU, split-channel f32x2 -------------
// grid (16, 32, 4), block 256. tile 8 rows x 128 cols.
// warp-halves: half 0 -> out ch 0-7, half 1 -> out ch 8-15; 8 cols/thread.
__global__ void __launch_bounds__(256,2) k_conv1(
    const float* __restrict__ x, const float* __restrict__ wpre,
    const float* __restrict__ bpre, const float* __restrict__ gam,
    const float* __restrict__ bet,  const float* __restrict__ mean,
    const float* __restrict__ var)
{
    extern __shared__ float sm1[];
    float* xs = sm1;                        // 8*12*132 = 12672 floats
    u64*   ws = (u64*)(sm1 + 12672);        // 3200 u64, 16B-aligned
    int b = blockIdx.z, r0 = blockIdx.y*8, c0 = blockIdx.x*128;
    int tid = threadIdx.x;

    for (int i = tid; i < 3200; i += 256){
        int o = i & 15, rest = i >> 4;
        int kw = rest % 5, kh = (rest/5) % 5, c = rest/25;
        float w = wpre[((o*CIN + c)*5 + kh)*5 + kw];
        ws[i] = pk2(w, w);
    }
    for (int i = tid; i < 12672; i += 256){
        int cc = i % 132; int t2 = i / 132; int rr = t2 % 12; int c = t2 / 12;
        int gr = r0 - 2 + rr, gc = c0 - 2 + cc;
        float v = 0.f;
        if (gr >= 0 && gr < HH && gc >= 0 && gc < WW)
            v = x[(((size_t)b*CIN + c)*HH + gr)*WW + gc];
        xs[i] = v;
    }
    __syncthreads();

    int half = tid >> 7, pt = tid & 127;
    int r = pt >> 4, cg = pt & 15, col0 = cg*8;
    u64 acc[8][4];
    #pragma unroll
    for (int o = 0; o < 8; o++)
        #pragma unroll
        for (int i = 0; i < 4; i++) acc[o][i] = 0ull;

    #pragma unroll 1
    for (int c = 0; c < 8; c++){
        #pragma unroll
        for (int kh = 0; kh < 5; kh++){
            const float* row = xs + (c*12 + r + kh)*132 + col0;
            float4 A = *(const float4*)row;
            float4 Bv = *(const float4*)(row + 4);
            float4 C = *(const float4*)(row + 8);
            u64 E[6] = {pk2(A.x,A.y),  pk2(A.z,A.w),  pk2(Bv.x,Bv.y),
                        pk2(Bv.z,Bv.w),pk2(C.x,C.y),  pk2(C.z,C.w)};
            u64 O[5] = {pk2(A.y,A.z),  pk2(A.w,Bv.x), pk2(Bv.y,Bv.z),
                        pk2(Bv.w,C.x), pk2(C.y,C.z)};
            const u64* wb = ws + ((c*5 + kh)*5)*16 + half*8;
            #pragma unroll
            for (int kw = 0; kw < 5; kw++){
                const u64* Pk = (kw==0) ? E : (kw==1) ? O : (kw==2) ? E+1
                              : (kw==3) ? O+1 : E+2;
                const ulonglong2* wv = (const ulonglong2*)(wb + kw*16);
                #pragma unroll
                for (int o2 = 0; o2 < 4; o2++){
                    ulonglong2 w = wv[o2];
                    #pragma unroll
                    for (int i = 0; i < 4; i++){
                        acc[2*o2  ][i] = fma2(Pk[i], w.x, acc[2*o2  ][i]);
                        acc[2*o2+1][i] = fma2(Pk[i], w.y, acc[2*o2+1][i]);
                    }
                }
            }
        }
    }
    int orow = r0 + r;
    if (orow < HH){
        #pragma unroll
        for (int oc = 0; oc < 8; oc++){
            int o = half*8 + oc;
            float s  = gam[o] * rsqrtf(var[o] + 1e-5f);
            float c2 = bet[o] + (bpre[o] - mean[o]) * s;
            float v0,v1,v2,v3,v4,v5,v6,v7;
            upk2(acc[oc][0], v0, v1); upk2(acc[oc][1], v2, v3);
            upk2(acc[oc][2], v4, v5); upk2(acc[oc][3], v6, v7);
            float* dst = g_h + (((size_t)b*CM + o)*HH + orow)*HROW + HOFF + c0 + col0;
            *(float4*)dst       = make_float4(lrelu(v0*s+c2), lrelu(v1*s+c2),
                                              lrelu(v2*s+c2), lrelu(v3*s+c2));
            *(float4*)(dst + 4) = make_float4(lrelu(v4*s+c2), lrelu(v5*s+c2),
                                              lrelu(v6*s+c2), lrelu(v7*s+c2));
        }
    }
}

// ------------- K2: FUSED Q/KV convs + masknorm + projections + sums -------------
// grid (4, 84, 4), block 256. Phase 1: conv 4 pos/thread (warps 0-3 q, 4-7 kv).
// Phase 2: 2 pos/thread; outputs stored channel-major [b][d][L] as STG.64.
#define QKV_SMEM (3456*8 + 432*8 + 12288*4 + 96*4)
__global__ void __launch_bounds__(256,2) k_qkv2(
    const float* __restrict__ wq,  const float* __restrict__ bqc,
    const float* __restrict__ wkv, const float* __restrict__ bkvc,
    const float* __restrict__ frame, const float* __restrict__ Tp,
    const float* __restrict__ fwq, const float* __restrict__ fbq,
    const float* __restrict__ fwk, const float* __restrict__ fbk,
    const float* __restrict__ fwv, const float* __restrict__ fbv)
{
    extern __shared__ __align__(16) char smraw[];
    u64*   ws  = (u64*)smraw;                  // 3456
    u64*   fwT = ws + 3456;                    // 432, [proj][j][d] packed (w,w)
    float* ex  = (float*)(fwT + 432);          // 24*512 floats
    float* cbs = ex + 12288;                   // 24
    float* fbs = cbs + 24;                     // 36
    float* red = fbs + 36;                     // 24

    int b = blockIdx.z, f = blockIdx.y;
    int tid = threadIdx.x;

    for (int i = tid; i < 3456; i += 256){
        int half2 = i / 1728, rem = i % 1728;
        int d = rem % 12, r2 = rem / 12;
        int kw = r2 % 3, kh = (r2/3) % 3, c = r2/9;
        const float* srcw = half2 ? wkv : wq;
        float w = srcw[((d*CM + c)*3 + kh)*3 + kw];
        ws[i] = pk2(w, w);
    }
    for (int i = tid; i < 432; i += 256){
        int wsel = i / 144, rem = i % 144, j = rem / 12, d = rem % 12;
        float w = (wsel == 0 ? fwq : (wsel == 1 ? fwk : fwv))[d*12 + j];
        fwT[i] = pk2(w, w);
    }
    if (tid < 24) cbs[tid] = (tid < 12) ? bqc[tid] : bkvc[tid-12];
    if (tid < 36) fbs[tid] = (tid < 12) ? fbq[tid] : (tid < 24 ? fbk[tid-12] : fbv[tid-24]);
    if (tid < 24) red[tid] = 0.f;
    __syncthreads();

    // ---- Phase 1: conv, 4 positions/thread ----
    {
        int half = tid >> 7, pt = tid & 127, lane = tid & 31;
        int t0 = blockIdx.x*512 + pt*4;
        u64 acc[12][2];
        #pragma unroll
        for (int d = 0; d < 12; d++){
            u64 bb = pk2(cbs[half*12+d], cbs[half*12+d]);
            acc[d][0] = bb; acc[d][1] = bb;
        }
        const float* hb = g_h + (((size_t)b*CM)*HH + 3*f)*HROW + HOFF + t0;
        const u64* wsh = ws + half*1728;
        #pragma unroll 1
        for (int c = 0; c < 16; c++){
            #pragma unroll
            for (int kh = 0; kh < 3; kh++){
                const float* row = hb + ((size_t)c*HH + kh)*HROW;
                float4 F = *(const float4*)row;
                float xm1 = __shfl_up_sync(0xffffffffu, F.w, 1);
                if (lane == 0)  xm1 = row[-1];
                float xp4 = __shfl_down_sync(0xffffffffu, F.x, 1);
                if (lane == 31) xp4 = row[4];
                u64 P[3][2];
                P[0][0] = pk2(xm1, F.x); P[0][1] = pk2(F.y, F.z);
                P[1][0] = pk2(F.x, F.y); P[1][1] = pk2(F.z, F.w);
                P[2][0] = pk2(F.y, F.z); P[2][1] = pk2(F.w, xp4);
                const u64* wp = wsh + (c*3 + kh)*36;
                #pragma unroll
                for (int kw = 0; kw < 3; kw++){
                    const ulonglong2* w2 = (const ulonglong2*)(wp + kw*12);
                    #pragma unroll
                    for (int dp = 0; dp < 6; dp++){
                        ulonglong2 wv = w2[dp];
                        acc[2*dp  ][0] = fma2(P[kw][0], wv.x, acc[2*dp  ][0]);
                        acc[2*dp  ][1] = fma2(P[kw][1], wv.x, acc[2*dp  ][1]);
                        acc[2*dp+1][0] = fma2(P[kw][0], wv.y, acc[2*dp+1][0]);
                        acc[2*dp+1][1] = fma2(P[kw][1], wv.y, acc[2*dp+1][1]);
                    }
                }
            }
        }
        float* exb = ex + (half*12)*512 + pt*4;
        #pragma unroll
        for (int d = 0; d < 12; d++){
            float v0,v1,v2,v3;
            upk2(acc[d][0], v0, v1); upk2(acc[d][1], v2, v3);
            *(float4*)(exb + d*512) = make_float4(v0,v1,v2,v3);
        }
    }
    __syncthreads();

    // ---- Phase 2: masknorm + projections (2 positions/thread, packed) ----
    {
        int lp = tid*2;
        size_t l0 = (size_t)f*WW + blockIdx.x*512 + lp;
        u64 inq[12], ckv[12];
        #pragma unroll
        for (int d = 0; d < 12; d++) inq[d] = *(const u64*)(ex + d*512 + lp);
        u64 s2p = pk2(EPSf, EPSf);
        #pragma unroll
        for (int d = 0; d < 12; d++){
            ckv[d] = *(const u64*)(ex + (12+d)*512 + lp);
            s2p = fma2(ckv[d], ckv[d], s2p);
        }
        float s20, s21; upk2(s2p, s20, s21);
        float cf = Tp[0] / g_msum[b];
        float2 mk = *(const float2*)(frame + (size_t)b*LL + l0);
        u64 sc2 = pk2(mk.x*cf*rsqrtf(s20), mk.y*cf*rsqrtf(s21));

        // Q projection + sigmoid
        {
            float qs[12];
            #pragma unroll
            for (int j = 0; j < 12; j++){
                u64 a = pk2(fbs[j], fbs[j]);
                const ulonglong2* wv = (const ulonglong2*)(fwT + j*12);
                #pragma unroll
                for (int dp = 0; dp < 6; dp++){
                    ulonglong2 w = wv[dp];
                    a = fma2(inq[2*dp  ], w.x, a);
                    a = fma2(inq[2*dp+1], w.y, a);
                }
                float x0, x1; upk2(a, x0, x1);
                x0 = sigm(x0); x1 = sigm(x1);
                *(u64*)(g_q + ((size_t)b*DD + j)*LL + l0) = pk2(x0, x1);
                qs[j] = x0 + x1;
            }
            #pragma unroll
            for (int j = 0; j < 12; j++){
                float s = wredsum(qs[j]);
                if ((tid & 31) == 0) atomicAdd(&red[j], s);
            }
        }
        #pragma unroll
        for (int d = 0; d < 12; d++) ckv[d] = fma2(ckv[d], sc2, 0ull);
        // K projection + sigmoid
        {
            float ks[12];
            #pragma unroll
            for (int j = 0; j < 12; j++){
                u64 a = pk2(fbs[12+j], fbs[12+j]);
                const ulonglong2* wv = (const ulonglong2*)(fwT + 144 + j*12);
                #pragma unroll
                for (int dp = 0; dp < 6; dp++){
                    ulonglong2 w = wv[dp];
                    a = fma2(ckv[2*dp  ], w.x, a);
                    a = fma2(ckv[2*dp+1], w.y, a);
                }
                float x0, x1; upk2(a, x0, x1);
                x0 = sigm(x0); x1 = sigm(x1);
                *(u64*)(g_k + ((size_t)b*DD + j)*LL + l0) = pk2(x0, x1);
                ks[j] = x0 + x1;
            }
            #pragma unroll
            for (int j = 0; j < 12; j++){
                float s = wredsum(ks[j]);
                if ((tid & 31) == 0) atomicAdd(&red[12+j], s);
            }
        }
        // V projection
        #pragma unroll
        for (int j = 0; j < 12; j++){
            u64 a = pk2(fbs[24+j], fbs[24+j]);
            const ulonglong2* wv = (const ulonglong2*)(fwT + 288 + j*12);
            #pragma unroll
            for (int dp = 0; dp < 6; dp++){
                ulonglong2 w = wv[dp];
                a = fma2(ckv[2*dp  ], w.x, a);
                a = fma2(ckv[2*dp+1], w.y, a);
            }
            *(u64*)(g_v + ((size_t)b*DD + j)*LL + l0) = a;
        }
    }
    __syncthreads();
    if (tid < 12)       atomicAdd(&g_qsum[b][tid], red[tid]);
    else if (tid < 24)  atomicAdd(&g_ksum[b][tid-12], red[tid]);
}

// ------------- K3: sq/skv sums (4 pos/thread, coalesced; si recomputed later) -------------
__global__ void __launch_bounds__(256) k3(){
    int b = blockIdx.y;
    int tid = threadIdx.x;
    int l0 = (blockIdx.x*256 + tid)*4;
    __shared__ float kE[12], qE[12], red[24];
    if (tid < 12){ kE[tid] = g_ksum[b][tid] + EPSf; qE[tid] = g_qsum[b][tid] + EPSf; }
    if (tid < 24) red[tid] = 0.f;
    __syncthreads();
    float4 q4[12], k4[12];
    #pragma unroll
    for (int d = 0; d < 12; d++){
        q4[d] = *(const float4*)(g_q + ((size_t)b*DD + d)*LL + l0);
        k4[d] = *(const float4*)(g_k + ((size_t)b*DD + d)*LL + l0);
    }
    float4 si = make_float4(0,0,0,0), so = make_float4(0,0,0,0);
    #pragma unroll
    for (int d = 0; d < 12; d++){
        si.x += (q4[d].x+EPSf)*kE[d]; si.y += (q4[d].y+EPSf)*kE[d];
        si.z += (q4[d].z+EPSf)*kE[d]; si.w += (q4[d].w+EPSf)*kE[d];
        so.x += (k4[d].x+EPSf)*qE[d]; so.y += (k4[d].y+EPSf)*qE[d];
        so.z += (k4[d].z+EPSf)*qE[d]; so.w += (k4[d].w+EPSf)*qE[d];
    }
    si.x = 1.f/si.x; si.y = 1.f/si.y; si.z = 1.f/si.z; si.w = 1.f/si.w;
    so.x = 1.f/so.x; so.y = 1.f/so.y; so.z = 1.f/so.z; so.w = 1.f/so.w;
    #pragma unroll
    for (int d = 0; d < 12; d++){
        float sqv  = q4[d].x*si.x + q4[d].y*si.y + q4[d].z*si.z + q4[d].w*si.w;
        float skvv = k4[d].x*so.x + k4[d].y*so.y + k4[d].z*so.z + k4[d].w*so.w;
        sqv = wredsum(sqv); skvv = wredsum(skvv);
        if ((tid & 31) == 0){ atomicAdd(&red[d], sqv); atomicAdd(&red[12+d], skvv); }
    }
    __syncthreads();
    if (tid < 12)      atomicAdd(&g_sq[b][tid], red[tid]);
    else if (tid < 24) atomicAdd(&g_skv[b][tid-12], red[tid]);
}

// ------------- K456: cons + exp(cons-CSH) + sumexp + kv outer product -------------
__global__ void __launch_bounds__(256,1) k456(){
    int b = blockIdx.y;
    int tid = threadIdx.x;
    __shared__ float sqE[12];
    if (tid < 12) sqE[tid] = g_sq[b][tid] + EPSf;
    __syncthreads();
    float acc[12][12];
    #pragma unroll
    for (int d = 0; d < 12; d++)
        #pragma unroll
        for (int m = 0; m < 12; m++) acc[d][m] = 0.f;
    float se = 0.f;

    for (int l = blockIdx.x*256 + tid; l < LL; l += 96*256){
        float k[12], v[12];
        #pragma unroll
        for (int d = 0; d < 12; d++){
            k[d] = g_k[((size_t)b*DD + d)*LL + l];
            v[d] = g_v[((size_t)b*DD + d)*LL + l];
        }
        float cons = 0.f;
        #pragma unroll
        for (int d = 0; d < 12; d++) cons += (k[d]+EPSf)*sqE[d];
        float e = __expf(cons - CSH);
        se += e;
        #pragma unroll
        for (int m = 0; m < 12; m++) v[m] *= e;
        #pragma unroll
        for (int d = 0; d < 12; d++)
            #pragma unroll
            for (int m = 0; m < 12; m++) acc[d][m] += k[d]*v[m];
    }
    __shared__ float red[144];
    __shared__ float sred;
    for (int i = tid; i < 144; i += 256) red[i] = 0.f;
    if (tid == 0) sred = 0.f;
    __syncthreads();
    se = wredsum(se);
    if ((tid & 31) == 0) atomicAdd(&sred, se);
    #pragma unroll
    for (int d = 0; d < 12; d++)
        #pragma unroll
        for (int m = 0; m < 12; m++){
            float v = wredsum(acc[d][m]);
            if ((tid & 31) == 0) atomicAdd(&red[d*12+m], v);
        }
    __syncthreads();
    if (tid < 144) atomicAdd(&g_kvm[b][tid], red[tid]);
    if (tid == 0)  atomicAdd(&g_sumexp[b], sred);
}

// ------------- Kmm: M = kv_norm @ Wo -------------
__global__ void kmm(const float* __restrict__ fwo){
    int b = blockIdx.x, tid = threadIdx.x;
    float norm = 172032.0f / g_sumexp[b];
    int d = tid/12, j = tid%12;
    float s = 0.f;
    #pragma unroll
    for (int m = 0; m < 12; m++) s += g_kvm[b][d*12+m]*fwo[m*12+j];
    g_M[b][tid] = s * norm;
}

// ------------- K7: epilogue (4 pos/thread, si recomputed inline) -------------
__global__ void __launch_bounds__(256) k7(const float* __restrict__ fbo, float* __restrict__ out){
    int b = blockIdx.y;
    int tid = threadIdx.x;
    int l0 = (blockIdx.x*256 + tid)*4;
    __shared__ float Ms[144], skvE[12], kE[12], bos[12];
    if (tid < 144) Ms[tid] = g_M[b][tid];
    if (tid < 12){
        skvE[tid] = g_skv[b][tid] + EPSf;
        kE[tid]   = g_ksum[b][tid] + EPSf;
        bos[tid]  = fbo[tid];
    }
    __syncthreads();
    float4 q4[12];
    #pragma unroll
    for (int d = 0; d < 12; d++)
        q4[d] = *(const float4*)(g_q + ((size_t)b*DD + d)*LL + l0);
    float4 cs = make_float4(0,0,0,0), si = make_float4(0,0,0,0);
    #pragma unroll
    for (int d = 0; d < 12; d++){
        cs.x += (q4[d].x+EPSf)*skvE[d]; cs.y += (q4[d].y+EPSf)*skvE[d];
        cs.z += (q4[d].z+EPSf)*skvE[d]; cs.w += (q4[d].w+EPSf)*skvE[d];
        si.x += (q4[d].x+EPSf)*kE[d];   si.y += (q4[d].y+EPSf)*kE[d];
        si.z += (q4[d].z+EPSf)*kE[d];   si.w += (q4[d].w+EPSf)*kE[d];
    }
    float4 sc;
    sc.x = sigm(cs.x)/si.x; sc.y = sigm(cs.y)/si.y;
    sc.z = sigm(cs.z)/si.z; sc.w = sigm(cs.w)/si.w;
    #pragma unroll
    for (int j = 0; j < 12; j++){
        float4 o = make_float4(0,0,0,0);
        #pragma unroll
        for (int d = 0; d < 12; d++){
            float w = Ms[d*12+j];
            o.x += q4[d].x*w; o.y += q4[d].y*w;
            o.z += q4[d].z*w; o.w += q4[d].w*w;
        }
        float4 r;
        r.x = bos[j] + sc.x*o.x; r.y = bos[j] + sc.y*o.y;
        r.z = bos[j] + sc.z*o.z; r.w = bos[j] + sc.w*o.w;
        *(float4*)(out + ((size_t)b*DD + j)*LL + l0) = r;
    }
}

extern "C" void kernel_launch(void* const* d_in, const int* in_sizes, int n_in,
                              void* d_out, int out_size){
    const float* x     = (const float*)d_in[0];
    const float* frame = (const float*)d_in[1];
    const float* wpre  = (const float*)d_in[2];
    const float* bpre  = (const float*)d_in[3];
    const float* gam   = (const float*)d_in[4];
    const float* bet   = (const float*)d_in[5];
    const float* mean  = (const float*)d_in[6];
    const float* var   = (const float*)d_in[7];
    const float* Tp    = (const float*)d_in[8];
    const float* wq    = (const float*)d_in[9];
    const float* bqc   = (const float*)d_in[10];
    const float* wkv   = (const float*)d_in[11];
    const float* bkvc  = (const float*)d_in[12];
    const float* fwq   = (const float*)d_in[13];
    const float* fbq   = (const float*)d_in[14];
    const float* fwk   = (const float*)d_in[15];
    const float* fbk   = (const float*)d_in[16];
    const float* fwv   = (const float*)d_in[17];
    const float* fbv   = (const float*)d_in[18];
    const float* fwo   = (const float*)d_in[19];
    const float* fbo   = (const float*)d_in[20];
    float* out = (float*)d_out;

    cudaFuncSetAttribute(k_conv1, cudaFuncAttributeMaxDynamicSharedMemorySize, 76288);
    cudaFuncSetAttribute(k_qkv2,  cudaFuncAttributeMaxDynamicSharedMemorySize, QKV_SMEM);

    k_init  <<<1, 1024>>>();
    k_msum  <<<dim3(168, Bn), 256>>>(frame);
    k_conv1 <<<dim3(16, 32, Bn), 256, 76288>>>(x, wpre, bpre, gam, bet, mean, var);
    k_qkv2  <<<dim3(4, FF, Bn), 256, QKV_SMEM>>>(wq, bqc, wkv, bkvc, frame, Tp,
                                                 fwq, fbq, fwk, fbk, fwv, fbv);
    k3   <<<dim3(168, Bn), 256>>>();
    k456 <<<dim3(96, Bn), 256>>>();
    kmm  <<<Bn, 144>>>(fwo);
    k7   <<<dim3(168, Bn), 256>>>(fbo, out);
    (void)in_sizes; (void)n_in; (void)out_size;
}

// round 10
// speedup vs baseline: 1.0460x; 1.0005x over previous
#include <cuda_runtime.h>
#include <math.h>

#define Bn 4
#define CIN 8
#define HH 252
#define WW 2048
#define CM 16
#define DD 12
#define FF 84
#define LL (FF*WW)          /* 172032 */
#define EPSf 1.01e-8f
#define HROW 2056           /* padded row: 4 zero cols each side */
#define HOFF 4
#define CSH 8.0f            /* fixed softmax shift */

typedef unsigned long long u64;

__device__ __forceinline__ u64 fma2(u64 a, u64 b, u64 c){
    u64 d; asm("fma.rn.f32x2 %0, %1, %2, %3;" : "=l"(d) : "l"(a), "l"(b), "l"(c)); return d;
}
__device__ __forceinline__ u64 pk2(float lo, float hi){
    u64 r; asm("mov.b64 %0, {%1, %2};" : "=l"(r) : "f"(lo), "f"(hi)); return r;
}
__device__ __forceinline__ void upk2(u64 v, float& lo, float& hi){
    asm("mov.b64 {%0, %1}, %2;" : "=f"(lo), "=f"(hi) : "l"(v));
}
__device__ __forceinline__ float wredsum(float v){
    #pragma unroll
    for (int o = 16; o > 0; o >>= 1) v += __shfl_xor_sync(0xffffffffu, v, o);
    return v;
}
__device__ __forceinline__ float sigm(float x){
    float t;
    asm("tanh.approx.f32 %0, %1;" : "=f"(t) : "f"(x*0.5f));
    return fmaf(0.5f, t, 0.5f);
}
__device__ __forceinline__ float lrelu(float v){ return v >= 0.f ? v : 0.01f*v; }

// ------------- scratch (device globals; zero-initialized at load) -------------
__device__ __align__(16) float g_h [(size_t)Bn*CM*HH*HROW];  // padded, borders stay 0
// channel-major: [b][d][L]
__device__ __align__(16) float g_q [(size_t)Bn*DD*LL];
__device__ __align__(16) float g_k [(size_t)Bn*DD*LL];
__device__ __align__(16) float g_v [(size_t)Bn*DD*LL];
__device__ float g_msum[Bn], g_sumexp[Bn];
__device__ float g_qsum[Bn][DD], g_ksum[Bn][DD], g_sq[Bn][DD], g_skv[Bn][DD];
__device__ float g_kvm[Bn][DD*DD];
__device__ float g_M[Bn][DD*DD];

// ------------- K0: zero accumulators -------------
__global__ void k_init(){
    int t = threadIdx.x;
    if (t < Bn){ g_msum[t]=0.f; g_sumexp[t]=0.f; }
    if (t < Bn*DD){
        ((float*)g_qsum)[t]=0.f; ((float*)g_ksum)[t]=0.f;
        ((float*)g_sq)[t]=0.f;   ((float*)g_skv)[t]=0.f;
    }
    if (t < Bn*DD*DD) ((float*)g_kvm)[t]=0.f;
}

// ------------- nop: shifts profile capture window onto k_conv1 -------------
__global__ void k_nop(){}

// ------------- mask sum per batch -------------
__global__ void __launch_bounds__(256) k_msum(const float* __restrict__ frame){
    int b = blockIdx.y;
    int i = (blockIdx.x*256 + threadIdx.x)*4;
    float4 v = *(const float4*)(frame + (size_t)b*LL + i);
    float s = v.x + v.y + v.z + v.w;
    s = wredsum(s);
    __shared__ float sr;
    if (threadIdx.x == 0) sr = 0.f;
    __syncthreads();
    if ((threadIdx.x & 31) == 0) atomicAdd(&sr, s);
    __syncthreads();
    if (threadIdx.x == 0) atomicAdd(&g_msum[b], sr);
}

// ------------- K1: conv5x5 + BN + LeakyReLU, split-channel, 3 CTAs/SM -------------
// grid (32, 32, 4), block 256, tile 8 rows x 64 cols.
// halves: half 0 -> oc 0-7, half 1 -> oc 8-15; 4 cols/thread (acc 8x2 u64).
#define C1_SMEM (6912*4 + 3200*8 + 32*4)
__global__ void __launch_bounds__(256,3) k_conv1(
    const float* __restrict__ x, const float* __restrict__ wpre,
    const float* __restrict__ bpre, const float* __restrict__ gam,
    const float* __restrict__ bet,  const float* __restrict__ mean,
    const float* __restrict__ var)
{
    extern __shared__ __align__(16) float sm1[];
    float* xs = sm1;                       // 8*12*72 = 6912 floats
    u64*   ws = (u64*)(sm1 + 6912);        // 3200 u64
    float* bns = (float*)(ws + 3200);      // 16
    float* bnc = bns + 16;                 // 16
    int b = blockIdx.z, r0 = blockIdx.y*8, c0 = blockIdx.x*64;
    int tid = threadIdx.x;

    for (int i = tid; i < 3200; i += 256){
        int o = i & 15, rest = i >> 4;
        int kw = rest % 5, kh = (rest/5) % 5, c = rest/25;
        float w = wpre[((o*CIN + c)*5 + kh)*5 + kw];
        ws[i] = pk2(w, w);
    }
    if (tid < 16){
        float s = gam[tid] * rsqrtf(var[tid] + 1e-5f);
        bns[tid] = s;
        bnc[tid] = bet[tid] + (bpre[tid] - mean[tid]) * s;
    }
    for (int i = tid; i < 6912; i += 256){
        int cc = i % 72; int t2 = i / 72; int rr = t2 % 12; int c = t2 / 12;
        int gr = r0 - 2 + rr, gc = c0 - 4 + cc;   // tile col j lives at xs col j+4
        float v = 0.f;
        if (gr >= 0 && gr < HH && gc >= 0 && gc < WW)
            v = x[(((size_t)b*CIN + c)*HH + gr)*WW + gc];
        xs[i] = v;
    }
    __syncthreads();

    int half = tid >> 7, lt = tid & 127;
    int r = lt >> 4, cg = lt & 15, col0 = cg*4;
    u64 acc[8][2];
    #pragma unroll
    for (int o = 0; o < 8; o++){ acc[o][0] = 0ull; acc[o][1] = 0ull; }

    #pragma unroll 1
    for (int c = 0; c < CIN; c++){
        #pragma unroll
        for (int kh = 0; kh < 5; kh++){
            const float* row = xs + (c*12 + r + kh)*72 + 4 + col0;
            float2 Xm = *(const float2*)(row - 2);
            float4 F  = *(const float4*)row;
            float2 Xp = *(const float2*)(row + 4);
            u64 E0 = pk2(Xm.x, Xm.y), E1 = pk2(F.x, F.y),
                E2 = pk2(F.z, F.w),   E3 = pk2(Xp.x, Xp.y);
            u64 O0 = pk2(Xm.y, F.x),  O1 = pk2(F.y, F.z),
                O2 = pk2(F.w, Xp.x);
            u64 PA[5] = {E0, O0, E1, O1, E2};
            u64 PB[5] = {E1, O1, E2, O2, E3};
            const u64* wb = ws + ((c*5 + kh)*5)*16 + half*8;
            #pragma unroll
            for (int kw = 0; kw < 5; kw++){
                const ulonglong2* wv = (const ulonglong2*)(wb + kw*16);
                ulonglong2 w0 = wv[0], w1 = wv[1], w2 = wv[2], w3 = wv[3];
                acc[0][0]=fma2(PA[kw],w0.x,acc[0][0]); acc[0][1]=fma2(PB[kw],w0.x,acc[0][1]);
                acc[1][0]=fma2(PA[kw],w0.y,acc[1][0]); acc[1][1]=fma2(PB[kw],w0.y,acc[1][1]);
                acc[2][0]=fma2(PA[kw],w1.x,acc[2][0]); acc[2][1]=fma2(PB[kw],w1.x,acc[2][1]);
                acc[3][0]=fma2(PA[kw],w1.y,acc[3][0]); acc[3][1]=fma2(PB[kw],w1.y,acc[3][1]);
                acc[4][0]=fma2(PA[kw],w2.x,acc[4][0]); acc[4][1]=fma2(PB[kw],w2.x,acc[4][1]);
                acc[5][0]=fma2(PA[kw],w2.y,acc[5][0]); acc[5][1]=fma2(PB[kw],w2.y,acc[5][1]);
                acc[6][0]=fma2(PA[kw],w3.x,acc[6][0]); acc[6][1]=fma2(PB[kw],w3.x,acc[6][1]);
                acc[7][0]=fma2(PA[kw],w3.y,acc[7][0]); acc[7][1]=fma2(PB[kw],w3.y,acc[7][1]);
            }
        }
    }
    int orow = r0 + r;
    if (orow < HH){
        #pragma unroll
        for (int oc = 0; oc < 8; oc++){
            int o = half*8 + oc;
            float s = bns[o], c2 = bnc[o];
            float v0,v1,v2,v3;
            upk2(acc[oc][0], v0, v1); upk2(acc[oc][1], v2, v3);
            *(float4*)(g_h + (((size_t)b*CM + o)*HH + orow)*HROW + HOFF + c0 + col0)
                = make_float4(lrelu(v0*s+c2), lrelu(v1*s+c2),
                              lrelu(v2*s+c2), lrelu(v3*s+c2));
        }
    }
}

// ------------- K2: FUSED Q/KV convs + masknorm + projections + sums -------------
#define QKV_SMEM (3456*8 + 432*8 + 12288*4 + 96*4)
__global__ void __launch_bounds__(256,2) k_qkv2(
    const float* __restrict__ wq,  const float* __restrict__ bqc,
    const float* __restrict__ wkv, const float* __restrict__ bkvc,
    const float* __restrict__ frame, const float* __restrict__ Tp,
    const float* __restrict__ fwq, const float* __restrict__ fbq,
    const float* __restrict__ fwk, const float* __restrict__ fbk,
    const float* __restrict__ fwv, const float* __restrict__ fbv)
{
    extern __shared__ __align__(16) char smraw[];
    u64*   ws  = (u64*)smraw;                  // 3456
    u64*   fwT = ws + 3456;                    // 432
    float* ex  = (float*)(fwT + 432);          // 24*512 floats
    float* cbs = ex + 12288;                   // 24
    float* fbs = cbs + 24;                     // 36
    float* red = fbs + 36;                     // 24

    int b = blockIdx.z, f = blockIdx.y;
    int tid = threadIdx.x;

    for (int i = tid; i < 3456; i += 256){
        int half2 = i / 1728, rem = i % 1728;
        int d = rem % 12, r2 = rem / 12;
        int kw = r2 % 3, kh = (r2/3) % 3, c = r2/9;
        const float* srcw = half2 ? wkv : wq;
        float w = srcw[((d*CM + c)*3 + kh)*3 + kw];
        ws[i] = pk2(w, w);
    }
    for (int i = tid; i < 432; i += 256){
        int wsel = i / 144, rem = i % 144, j = rem / 12, d = rem % 12;
        float w = (wsel == 0 ? fwq : (wsel == 1 ? fwk : fwv))[d*12 + j];
        fwT[i] = pk2(w, w);
    }
    if (tid < 24) cbs[tid] = (tid < 12) ? bqc[tid] : bkvc[tid-12];
    if (tid < 36) fbs[tid] = (tid < 12) ? fbq[tid] : (tid < 24 ? fbk[tid-12] : fbv[tid-24]);
    if (tid < 24) red[tid] = 0.f;
    __syncthreads();

    // ---- Phase 1: conv, 4 positions/thread ----
    {
        int half = tid >> 7, pt = tid & 127, lane = tid & 31;
        int t0 = blockIdx.x*512 + pt*4;
        u64 acc[12][2];
        #pragma unroll
        for (int d = 0; d < 12; d++){
            u64 bb = pk2(cbs[half*12+d], cbs[half*12+d]);
            acc[d][0] = bb; acc[d][1] = bb;
        }
        const float* hb = g_h + (((size_t)b*CM)*HH + 3*f)*HROW + HOFF + t0;
        const u64* wsh = ws + half*1728;
        #pragma unroll 1
        for (int c = 0; c < 16; c++){
            #pragma unroll
            for (int kh = 0; kh < 3; kh++){
                const float* row = hb + ((size_t)c*HH + kh)*HROW;
                float4 F = *(const float4*)row;
                float xm1 = __shfl_up_sync(0xffffffffu, F.w, 1);
                if (lane == 0)  xm1 = row[-1];
                float xp4 = __shfl_down_sync(0xffffffffu, F.x, 1);
                if (lane == 31) xp4 = row[4];
                u64 P[3][2];
                P[0][0] = pk2(xm1, F.x); P[0][1] = pk2(F.y, F.z);
                P[1][0] = pk2(F.x, F.y); P[1][1] = pk2(F.z, F.w);
                P[2][0] = pk2(F.y, F.z); P[2][1] = pk2(F.w, xp4);
                const u64* wp = wsh + (c*3 + kh)*36;
                #pragma unroll
                for (int kw = 0; kw < 3; kw++){
                    const ulonglong2* w2 = (const ulonglong2*)(wp + kw*12);
                    #pragma unroll
                    for (int dp = 0; dp < 6; dp++){
                        ulonglong2 wv = w2[dp];
                        acc[2*dp  ][0] = fma2(P[kw][0], wv.x, acc[2*dp  ][0]);
                        acc[2*dp  ][1] = fma2(P[kw][1], wv.x, acc[2*dp  ][1]);
                        acc[2*dp+1][0] = fma2(P[kw][0], wv.y, acc[2*dp+1][0]);
                        acc[2*dp+1][1] = fma2(P[kw][1], wv.y, acc[2*dp+1][1]);
                    }
                }
            }
        }
        float* exb = ex + (half*12)*512 + pt*4;
        #pragma unroll
        for (int d = 0; d < 12; d++){
            float v0,v1,v2,v3;
            upk2(acc[d][0], v0, v1); upk2(acc[d][1], v2, v3);
            *(float4*)(exb + d*512) = make_float4(v0,v1,v2,v3);
        }
    }
    __syncthreads();

    // ---- Phase 2: masknorm + projections (2 positions/thread, packed) ----
    {
        int lp = tid*2;
        size_t l0 = (size_t)f*WW + blockIdx.x*512 + lp;
        u64 inq[12], ckv[12];
        #pragma unroll
        for (int d = 0; d < 12; d++) inq[d] = *(const u64*)(ex + d*512 + lp);
        u64 s2p = pk2(EPSf, EPSf);
        #pragma unroll
        for (int d = 0; d < 12; d++){
            ckv[d] = *(const u64*)(ex + (12+d)*512 + lp);
            s2p = fma2(ckv[d], ckv[d], s2p);
        }
        float s20, s21; upk2(s2p, s20, s21);
        float cf = Tp[0] / g_msum[b];
        float2 mk = *(const float2*)(frame + (size_t)b*LL + l0);
        u64 sc2 = pk2(mk.x*cf*rsqrtf(s20), mk.y*cf*rsqrtf(s21));

        // Q projection + sigmoid
        {
            float qs[12];
            #pragma unroll
            for (int j = 0; j < 12; j++){
                u64 a = pk2(fbs[j], fbs[j]);
                const ulonglong2* wv = (const ulonglong2*)(fwT + j*12);
                #pragma unroll
                for (int dp = 0; dp < 6; dp++){
                    ulonglong2 w = wv[dp];
                    a = fma2(inq[2*dp  ], w.x, a);
                    a = fma2(inq[2*dp+1], w.y, a);
                }
                float x0, x1; upk2(a, x0, x1);
                x0 = sigm(x0); x1 = sigm(x1);
                *(u64*)(g_q + ((size_t)b*DD + j)*LL + l0) = pk2(x0, x1);
                qs[j] = x0 + x1;
            }
            #pragma unroll
            for (int j = 0; j < 12; j++){
                float s = wredsum(qs[j]);
                if ((tid & 31) == 0) atomicAdd(&red[j], s);
            }
        }
        #pragma unroll
        for (int d = 0; d < 12; d++) ckv[d] = fma2(ckv[d], sc2, 0ull);
        // K projection + sigmoid
        {
            float ks[12];
            #pragma unroll
            for (int j = 0; j < 12; j++){
                u64 a = pk2(fbs[12+j], fbs[12+j]);
                const ulonglong2* wv = (const ulonglong2*)(fwT + 144 + j*12);
                #pragma unroll
                for (int dp = 0; dp < 6; dp++){
                    ulonglong2 w = wv[dp];
                    a = fma2(ckv[2*dp  ], w.x, a);
                    a = fma2(ckv[2*dp+1], w.y, a);
                }
                float x0, x1; upk2(a, x0, x1);
                x0 = sigm(x0); x1 = sigm(x1);
                *(u64*)(g_k + ((size_t)b*DD + j)*LL + l0) = pk2(x0, x1);
                ks[j] = x0 + x1;
            }
            #pragma unroll
            for (int j = 0; j < 12; j++){
                float s = wredsum(ks[j]);
                if ((tid & 31) == 0) atomicAdd(&red[12+j], s);
            }
        }
        // V projection
        #pragma unroll
        for (int j = 0; j < 12; j++){
            u64 a = pk2(fbs[24+j], fbs[24+j]);
            const ulonglong2* wv = (const ulonglong2*)(fwT + 288 + j*12);
            #pragma unroll
            for (int dp = 0; dp < 6; dp++){
                ulonglong2 w = wv[dp];
                a = fma2(ckv[2*dp  ], w.x, a);
                a = fma2(ckv[2*dp+1], w.y, a);
            }
            *(u64*)(g_v + ((size_t)b*DD + j)*LL + l0) = a;
        }
    }
    __syncthreads();
    if (tid < 12)       atomicAdd(&g_qsum[b][tid], red[tid]);
    else if (tid < 24)  atomicAdd(&g_ksum[b][tid-12], red[tid]);
}

// ------------- K3: sq/skv sums (4 pos/thread, coalesced) -------------
__global__ void __launch_bounds__(256) k3(){
    int b = blockIdx.y;
    int tid = threadIdx.x;
    int l0 = (blockIdx.x*256 + tid)*4;
    __shared__ float kE[12], qE[12], red[24];
    if (tid < 12){ kE[tid] = g_ksum[b][tid] + EPSf; qE[tid] = g_qsum[b][tid] + EPSf; }
    if (tid < 24) red[tid] = 0.f;
    __syncthreads();
    float4 q4[12], k4[12];
    #pragma unroll
    for (int d = 0; d < 12; d++){
        q4[d] = *(const float4*)(g_q + ((size_t)b*DD + d)*LL + l0);
        k4[d] = *(const float4*)(g_k + ((size_t)b*DD + d)*LL + l0);
    }
    float4 si = make_float4(0,0,0,0), so = make_float4(0,0,0,0);
    #pragma unroll
    for (int d = 0; d < 12; d++){
        si.x += (q4[d].x+EPSf)*kE[d]; si.y += (q4[d].y+EPSf)*kE[d];
        si.z += (q4[d].z+EPSf)*kE[d]; si.w += (q4[d].w+EPSf)*kE[d];
        so.x += (k4[d].x+EPSf)*qE[d]; so.y += (k4[d].y+EPSf)*qE[d];
        so.z += (k4[d].z+EPSf)*qE[d]; so.w += (k4[d].w+EPSf)*qE[d];
    }
    si.x = 1.f/si.x; si.y = 1.f/si.y; si.z = 1.f/si.z; si.w = 1.f/si.w;
    so.x = 1.f/so.x; so.y = 1.f/so.y; so.z = 1.f/so.z; so.w = 1.f/so.w;
    #pragma unroll
    for (int d = 0; d < 12; d++){
        float sqv  = q4[d].x*si.x + q4[d].y*si.y + q4[d].z*si.z + q4[d].w*si.w;
        float skvv = k4[d].x*so.x + k4[d].y*so.y + k4[d].z*so.z + k4[d].w*so.w;
        sqv = wredsum(sqv); skvv = wredsum(skvv);
        if ((tid & 31) == 0){ atomicAdd(&red[d], sqv); atomicAdd(&red[12+d], skvv); }
    }
    __syncthreads();
    if (tid < 12)      atomicAdd(&g_sq[b][tid], red[tid]);
    else if (tid < 24) atomicAdd(&g_skv[b][tid-12], red[tid]);
}

// ------------- K456: cons + exp(cons-CSH) + sumexp + kv outer product -------------
__global__ void __launch_bounds__(256,1) k456(){
    int b = blockIdx.y;
    int tid = threadIdx.x;
    __shared__ float sqE[12];
    if (tid < 12) sqE[tid] = g_sq[b][tid] + EPSf;
    __syncthreads();
    float acc[12][12];
    #pragma unroll
    for (int d = 0; d < 12; d++)
        #pragma unroll
        for (int m = 0; m < 12; m++) acc[d][m] = 0.f;
    float se = 0.f;

    for (int l = blockIdx.x*256 + tid; l < LL; l += 96*256){
        float k[12], v[12];
        #pragma unroll
        for (int d = 0; d < 12; d++){
            k[d] = g_k[((size_t)b*DD + d)*LL + l];
            v[d] = g_v[((size_t)b*DD + d)*LL + l];
        }
        float cons = 0.f;
        #pragma unroll
        for (int d = 0; d < 12; d++) cons += (k[d]+EPSf)*sqE[d];
        float e = __expf(cons - CSH);
        se += e;
        #pragma unroll
        for (int m = 0; m < 12; m++) v[m] *= e;
        #pragma unroll
        for (int d = 0; d < 12; d++)
            #pragma unroll
            for (int m = 0; m < 12; m++) acc[d][m] += k[d]*v[m];
    }
    __shared__ float red[144];
    __shared__ float sred;
    for (int i = tid; i < 144; i += 256) red[i] = 0.f;
    if (tid == 0) sred = 0.f;
    __syncthreads();
    se = wredsum(se);
    if ((tid & 31) == 0) atomicAdd(&sred, se);
    #pragma unroll
    for (int d = 0; d < 12; d++)
        #pragma unroll
        for (int m = 0; m < 12; m++){
            float v = wredsum(acc[d][m]);
            if ((tid & 31) == 0) atomicAdd(&red[d*12+m], v);
        }
    __syncthreads();
    if (tid < 144) atomicAdd(&g_kvm[b][tid], red[tid]);
    if (tid == 0)  atomicAdd(&g_sumexp[b], sred);
}

// ------------- Kmm: M = kv_norm @ Wo -------------
__global__ void kmm(const float* __restrict__ fwo){
    int b = blockIdx.x, tid = threadIdx.x;
    float norm = 172032.0f / g_sumexp[b];
    int d = tid/12, j = tid%12;
    float s = 0.f;
    #pragma unroll
    for (int m = 0; m < 12; m++) s += g_kvm[b][d*12+m]*fwo[m*12+j];
    g_M[b][tid] = s * norm;
}

// ------------- K7: epilogue (4 pos/thread, si recomputed inline) -------------
__global__ void __launch_bounds__(256) k7(const float* __restrict__ fbo, float* __restrict__ out){
    int b = blockIdx.y;
    int tid = threadIdx.x;
    int l0 = (blockIdx.x*256 + tid)*4;
    __shared__ float Ms[144], skvE[12], kE[12], bos[12];
    if (tid < 144) Ms[tid] = g_M[b][tid];
    if (tid < 12){
        skvE[tid] = g_skv[b][tid] + EPSf;
        kE[tid]   = g_ksum[b][tid] + EPSf;
        bos[tid]  = fbo[tid];
    }
    __syncthreads();
    float4 q4[12];
    #pragma unroll
    for (int d = 0; d < 12; d++)
        q4[d] = *(const float4*)(g_q + ((size_t)b*DD + d)*LL + l0);
    float4 cs = make_float4(0,0,0,0), si = make_float4(0,0,0,0);
    #pragma unroll
    for (int d = 0; d < 12; d++){
        cs.x += (q4[d].x+EPSf)*skvE[d]; cs.y += (q4[d].y+EPSf)*skvE[d];
        cs.z += (q4[d].z+EPSf)*skvE[d]; cs.w += (q4[d].w+EPSf)*skvE[d];
        si.x += (q4[d].x+EPSf)*kE[d];   si.y += (q4[d].y+EPSf)*kE[d];
        si.z += (q4[d].z+EPSf)*kE[d];   si.w += (q4[d].w+EPSf)*kE[d];
    }
    float4 sc;
    sc.x = sigm(cs.x)/si.x; sc.y = sigm(cs.y)/si.y;
    sc.z = sigm(cs.z)/si.z; sc.w = sigm(cs.w)/si.w;
    #pragma unroll
    for (int j = 0; j < 12; j++){
        float4 o = make_float4(0,0,0,0);
        #pragma unroll
        for (int d = 0; d < 12; d++){
            float w = Ms[d*12+j];
            o.x += q4[d].x*w; o.y += q4[d].y*w;
            o.z += q4[d].z*w; o.w += q4[d].w*w;
        }
        float4 r;
        r.x = bos[j] + sc.x*o.x; r.y = bos[j] + sc.y*o.y;
        r.z = bos[j] + sc.z*o.z; r.w = bos[j] + sc.w*o.w;
        *(float4*)(out + ((size_t)b*DD + j)*LL + l0) = r;
    }
}

extern "C" void kernel_launch(void* const* d_in, const int* in_sizes, int n_in,
                              void* d_out, int out_size){
    const float* x     = (const float*)d_in[0];
    const float* frame = (const float*)d_in[1];
    const float* wpre  = (const float*)d_in[2];
    const float* bpre  = (const float*)d_in[3];
    const float* gam   = (const float*)d_in[4];
    const float* bet   = (const float*)d_in[5];
    const float* mean  = (const float*)d_in[6];
    const float* var   = (const float*)d_in[7];
    const float* Tp    = (const float*)d_in[8];
    const float* wq    = (const float*)d_in[9];
    const float* bqc   = (const float*)d_in[10];
    const float* wkv   = (const float*)d_in[11];
    const float* bkvc  = (const float*)d_in[12];
    const float* fwq   = (const float*)d_in[13];
    const float* fbq   = (const float*)d_in[14];
    const float* fwk   = (const float*)d_in[15];
    const float* fbk   = (const float*)d_in[16];
    const float* fwv   = (const float*)d_in[17];
    const float* fbv   = (const float*)d_in[18];
    const float* fwo   = (const float*)d_in[19];
    const float* fbo   = (const float*)d_in[20];
    float* out = (float*)d_out;

    cudaFuncSetAttribute(k_conv1, cudaFuncAttributeMaxDynamicSharedMemorySize, C1_SMEM);
    cudaFuncSetAttribute(k_qkv2,  cudaFuncAttributeMaxDynamicSharedMemorySize, QKV_SMEM);

    k_init  <<<1, 1024>>>();
    k_msum  <<<dim3(168, Bn), 256>>>(frame);
    k_nop   <<<1, 32>>>();
    k_conv1 <<<dim3(32, 32, Bn), 256, C1_SMEM>>>(x, wpre, bpre, gam, bet, mean, var);
    k_qkv2  <<<dim3(4, FF, Bn), 256, QKV_SMEM>>>(wq, bqc, wkv, bkvc, frame, Tp,
                                                 fwq, fbq, fwk, fbk, fwv, fbv);
    k3   <<<dim3(168, Bn), 256>>>();
    k456 <<<dim3(96, Bn), 256>>>();
    kmm  <<<Bn, 144>>>(fwo);
    k7   <<<dim3(168, Bn), 256>>>(fbo, out);
    (void)in_sizes; (void)n_in; (void)out_size;
}

// round 11
// speedup vs baseline: 1.0770x; 1.0296x over previous
#include <cuda_runtime.h>
#include <math.h>

#define Bn 4
#define CIN 8
#define HH 252
#define WW 2048
#define CM 16
#define DD 12
#define FF 84
#define LL (FF*WW)          /* 172032 */
#define EPSf 1.01e-8f
#define HROW 2056           /* padded row: 4 zero cols each side */
#define HOFF 4
#define CSH 8.0f            /* fixed softmax shift */

typedef unsigned long long u64;

__device__ __forceinline__ u64 fma2(u64 a, u64 b, u64 c){
    u64 d; asm("fma.rn.f32x2 %0, %1, %2, %3;" : "=l"(d) : "l"(a), "l"(b), "l"(c)); return d;
}
__device__ __forceinline__ u64 pk2(float lo, float hi){
    u64 r; asm("mov.b64 %0, {%1, %2};" : "=l"(r) : "f"(lo), "f"(hi)); return r;
}
__device__ __forceinline__ void upk2(u64 v, float& lo, float& hi){
    asm("mov.b64 {%0, %1}, %2;" : "=f"(lo), "=f"(hi) : "l"(v));
}
__device__ __forceinline__ float wredsum(float v){
    #pragma unroll
    for (int o = 16; o > 0; o >>= 1) v += __shfl_xor_sync(0xffffffffu, v, o);
    return v;
}
__device__ __forceinline__ float sigm(float x){
    float t;
    asm("tanh.approx.f32 %0, %1;" : "=f"(t) : "f"(x*0.5f));
    return fmaf(0.5f, t, 0.5f);
}
__device__ __forceinline__ float lrelu(float v){ return v >= 0.f ? v : 0.01f*v; }

// ------------- scratch (device globals; zero-initialized at load) -------------
__device__ __align__(16) float g_h [(size_t)Bn*CM*HH*HROW];  // padded, borders stay 0
// channel-major: [b][d][L]
__device__ __align__(16) float g_q [(size_t)Bn*DD*LL];
__device__ __align__(16) float g_k [(size_t)Bn*DD*LL];
__device__ __align__(16) float g_v [(size_t)Bn*DD*LL];
__device__ float g_msum[Bn], g_sumexp[Bn];
__device__ float g_qsum[Bn][DD], g_ksum[Bn][DD], g_sq[Bn][DD], g_skv[Bn][DD];
__device__ float g_kvm[Bn][DD*DD];
__device__ float g_M[Bn][DD*DD];

// ------------- K0: zero accumulators -------------
__global__ void k_init(){
    int t = threadIdx.x;
    if (t < Bn){ g_msum[t]=0.f; g_sumexp[t]=0.f; }
    if (t < Bn*DD){
        ((float*)g_qsum)[t]=0.f; ((float*)g_ksum)[t]=0.f;
        ((float*)g_sq)[t]=0.f;   ((float*)g_skv)[t]=0.f;
    }
    if (t < Bn*DD*DD) ((float*)g_kvm)[t]=0.f;
}

// ------------- nop: keeps profile capture window on k_conv1 -------------
__global__ void k_nop(){}

// ------------- mask sum per batch -------------
__global__ void __launch_bounds__(256) k_msum(const float* __restrict__ frame){
    int b = blockIdx.y;
    int i = (blockIdx.x*256 + threadIdx.x)*4;
    float4 v = *(const float4*)(frame + (size_t)b*LL + i);
    float s = v.x + v.y + v.z + v.w;
    s = wredsum(s);
    __shared__ float sr;
    if (threadIdx.x == 0) sr = 0.f;
    __syncthreads();
    if ((threadIdx.x & 31) == 0) atomicAdd(&sr, s);
    __syncthreads();
    if (threadIdx.x == 0) atomicAdd(&g_msum[b], sr);
}

// ------------- K1: conv5x5 + BN + LeakyReLU, ROW-PAIR f32x2 packing -------------
// grid (16, 32, 4), block 256, tile 8 rows x 128 cols.
// Each f32x2 lane pair = output rows (r, r+4): all operands load as aligned u64,
// zero repacking MOVs. halves: half 0 -> oc 0-7, half 1 -> oc 8-15.
// thread: 1 pair-row (rows prow, prow+4) x 4 cols x 8 oc.
#define C1_SMEM (8448*8 + 3200*8 + 32*4)
__global__ void __launch_bounds__(256,2) k_conv1(
    const float* __restrict__ x, const float* __restrict__ wpre,
    const float* __restrict__ bpre, const float* __restrict__ gam,
    const float* __restrict__ bet,  const float* __restrict__ mean,
    const float* __restrict__ var)
{
    extern __shared__ __align__(16) char smc1[];
    u64*   xp = (u64*)smc1;                // [8c][8pr][132] = 8448 u64
    u64*   ws = xp + 8448;                 // 3200 u64
    float* bns = (float*)(ws + 3200);      // 16
    float* bnc = bns + 16;                 // 16
    int b = blockIdx.z, r0 = blockIdx.y*8, c0 = blockIdx.x*128;
    int tid = threadIdx.x;

    for (int i = tid; i < 3200; i += 256){
        int o = i & 15, rest = i >> 4;
        int kw = rest % 5, kh = (rest/5) % 5, c = rest/25;
        float w = wpre[((o*CIN + c)*5 + kh)*5 + kw];
        ws[i] = pk2(w, w);
    }
    if (tid < 16){
        float s = gam[tid] * rsqrtf(var[tid] + 1e-5f);
        bns[tid] = s;
        bnc[tid] = bet[tid] + (bpre[tid] - mean[tid]) * s;
    }
    // fill xp: pair (x[r0-2+pr][gc], x[r0+2+pr][gc]), gc = c0-2+col
    for (int i = tid; i < 8448; i += 256){
        int col = i % 132; int t2 = i / 132; int pr = t2 & 7; int c = t2 >> 3;
        int gc = c0 - 2 + col;
        int rA = r0 - 2 + pr, rB = r0 + 2 + pr;
        float vA = 0.f, vB = 0.f;
        if (gc >= 0 && gc < WW){
            const float* xc = x + (((size_t)b*CIN + c)*HH)*WW + gc;
            if (rA >= 0 && rA < HH) vA = xc[(size_t)rA*WW];
            if (rB < HH)            vB = xc[(size_t)rB*WW];
        }
        xp[i] = pk2(vA, vB);
    }
    __syncthreads();

    int half = tid >> 7, lt = tid & 127;
    int prow = lt >> 5, lane = lt & 31, col0 = lane*4;
    u64 acc[8][4];
    #pragma unroll
    for (int o = 0; o < 8; o++)
        #pragma unroll
        for (int i = 0; i < 4; i++) acc[o][i] = 0ull;

    #pragma unroll 1
    for (int c = 0; c < CIN; c++){
        #pragma unroll
        for (int kh = 0; kh < 5; kh++){
            // X window: cols col0-2 .. col0+5 (8 u64), 16B-aligned base
            const u64* xr = xp + ((c*8 + prow + kh)*132) + 2 + col0 - 2;
            ulonglong2 x0 = ((const ulonglong2*)xr)[0];
            ulonglong2 x1 = ((const ulonglong2*)xr)[1];
            ulonglong2 x2 = ((const ulonglong2*)xr)[2];
            ulonglong2 x3 = ((const ulonglong2*)xr)[3];
            u64 X[8] = {x0.x, x0.y, x1.x, x1.y, x2.x, x2.y, x3.x, x3.y};
            const u64* wb = ws + ((c*5 + kh)*5)*16 + half*8;
            #pragma unroll
            for (int kw = 0; kw < 5; kw++){
                const ulonglong2* wv = (const ulonglong2*)(wb + kw*16);
                ulonglong2 w0 = wv[0], w1 = wv[1], w2 = wv[2], w3 = wv[3];
                #pragma unroll
                for (int cc = 0; cc < 4; cc++){
                    u64 xv = X[kw + cc];
                    acc[0][cc] = fma2(xv, w0.x, acc[0][cc]);
                    acc[1][cc] = fma2(xv, w0.y, acc[1][cc]);
                    acc[2][cc] = fma2(xv, w1.x, acc[2][cc]);
                    acc[3][cc] = fma2(xv, w1.y, acc[3][cc]);
                    acc[4][cc] = fma2(xv, w2.x, acc[4][cc]);
                    acc[5][cc] = fma2(xv, w2.y, acc[5][cc]);
                    acc[6][cc] = fma2(xv, w3.x, acc[6][cc]);
                    acc[7][cc] = fma2(xv, w3.y, acc[7][cc]);
                }
            }
        }
    }
    int rA = r0 + prow, rB = r0 + prow + 4;
    #pragma unroll
    for (int oc = 0; oc < 8; oc++){
        int o = half*8 + oc;
        float s = bns[o], c2 = bnc[o];
        float a0,b0,a1,b1,a2,b2,a3,b3;
        upk2(acc[oc][0], a0, b0); upk2(acc[oc][1], a1, b1);
        upk2(acc[oc][2], a2, b2); upk2(acc[oc][3], a3, b3);
        float* base = g_h + (((size_t)b*CM + o)*HH)*HROW + HOFF + c0 + col0;
        if (rA < HH)
            *(float4*)(base + (size_t)rA*HROW)
                = make_float4(lrelu(a0*s+c2), lrelu(a1*s+c2),
                              lrelu(a2*s+c2), lrelu(a3*s+c2));
        if (rB < HH)
            *(float4*)(base + (size_t)rB*HROW)
                = make_float4(lrelu(b0*s+c2), lrelu(b1*s+c2),
                              lrelu(b2*s+c2), lrelu(b3*s+c2));
    }
}

// ------------- K2: FUSED Q/KV convs + masknorm + projections + sums -------------
#define QKV_SMEM (3456*8 + 432*8 + 12288*4 + 96*4)
__global__ void __launch_bounds__(256,2) k_qkv2(
    const float* __restrict__ wq,  const float* __restrict__ bqc,
    const float* __restrict__ wkv, const float* __restrict__ bkvc,
    const float* __restrict__ frame, const float* __restrict__ Tp,
    const float* __restrict__ fwq, const float* __restrict__ fbq,
    const float* __restrict__ fwk, const float* __restrict__ fbk,
    const float* __restrict__ fwv, const float* __restrict__ fbv)
{
    extern __shared__ __align__(16) char smraw[];
    u64*   ws  = (u64*)smraw;                  // 3456
    u64*   fwT = ws + 3456;                    // 432
    float* ex  = (float*)(fwT + 432);          // 24*512 floats
    float* cbs = ex + 12288;                   // 24
    float* fbs = cbs + 24;                     // 36
    float* red = fbs + 36;                     // 24

    int b = blockIdx.z, f = blockIdx.y;
    int tid = threadIdx.x;

    for (int i = tid; i < 3456; i += 256){
        int half2 = i / 1728, rem = i % 1728;
        int d = rem % 12, r2 = rem / 12;
        int kw = r2 % 3, kh = (r2/3) % 3, c = r2/9;
        const float* srcw = half2 ? wkv : wq;
        float w = srcw[((d*CM + c)*3 + kh)*3 + kw];
        ws[i] = pk2(w, w);
    }
    for (int i = tid; i < 432; i += 256){
        int wsel = i / 144, rem = i % 144, j = rem / 12, d = rem % 12;
        float w = (wsel == 0 ? fwq : (wsel == 1 ? fwk : fwv))[d*12 + j];
        fwT[i] = pk2(w, w);
    }
    if (tid < 24) cbs[tid] = (tid < 12) ? bqc[tid] : bkvc[tid-12];
    if (tid < 36) fbs[tid] = (tid < 12) ? fbq[tid] : (tid < 24 ? fbk[tid-12] : fbv[tid-24]);
    if (tid < 24) red[tid] = 0.f;
    __syncthreads();

    // ---- Phase 1: conv, 4 positions/thread ----
    {
        int half = tid >> 7, pt = tid & 127, lane = tid & 31;
        int t0 = blockIdx.x*512 + pt*4;
        u64 acc[12][2];
        #pragma unroll
        for (int d = 0; d < 12; d++){
            u64 bb = pk2(cbs[half*12+d], cbs[half*12+d]);
            acc[d][0] = bb; acc[d][1] = bb;
        }
        const float* hb = g_h + (((size_t)b*CM)*HH + 3*f)*HROW + HOFF + t0;
        const u64* wsh = ws + half*1728;
        #pragma unroll 1
        for (int c = 0; c < 16; c++){
            #pragma unroll
            for (int kh = 0; kh < 3; kh++){
                const float* row = hb + ((size_t)c*HH + kh)*HROW;
                float4 F = *(const float4*)row;
                float xm1 = __shfl_up_sync(0xffffffffu, F.w, 1);
                if (lane == 0)  xm1 = row[-1];
                float xp4 = __shfl_down_sync(0xffffffffu, F.x, 1);
                if (lane == 31) xp4 = row[4];
                u64 P[3][2];
                P[0][0] = pk2(xm1, F.x); P[0][1] = pk2(F.y, F.z);
                P[1][0] = pk2(F.x, F.y); P[1][1] = pk2(F.z, F.w);
                P[2][0] = pk2(F.y, F.z); P[2][1] = pk2(F.w, xp4);
                const u64* wp = wsh + (c*3 + kh)*36;
                #pragma unroll
                for (int kw = 0; kw < 3; kw++){
                    const ulonglong2* w2 = (const ulonglong2*)(wp + kw*12);
                    #pragma unroll
                    for (int dp = 0; dp < 6; dp++){
                        ulonglong2 wv = w2[dp];
                        acc[2*dp  ][0] = fma2(P[kw][0], wv.x, acc[2*dp  ][0]);
                        acc[2*dp  ][1] = fma2(P[kw][1], wv.x, acc[2*dp  ][1]);
                        acc[2*dp+1][0] = fma2(P[kw][0], wv.y, acc[2*dp+1][0]);
                        acc[2*dp+1][1] = fma2(P[kw][1], wv.y, acc[2*dp+1][1]);
                    }
                }
            }
        }
        float* exb = ex + (half*12)*512 + pt*4;
        #pragma unroll
        for (int d = 0; d < 12; d++){
            float v0,v1,v2,v3;
            upk2(acc[d][0], v0, v1); upk2(acc[d][1], v2, v3);
            *(float4*)(exb + d*512) = make_float4(v0,v1,v2,v3);
        }
    }
    __syncthreads();

    // ---- Phase 2: masknorm + projections (2 positions/thread, packed) ----
    {
        int lp = tid*2;
        size_t l0 = (size_t)f*WW + blockIdx.x*512 + lp;
        u64 inq[12], ckv[12];
        #pragma unroll
        for (int d = 0; d < 12; d++) inq[d] = *(const u64*)(ex + d*512 + lp);
        u64 s2p = pk2(EPSf, EPSf);
        #pragma unroll
        for (int d = 0; d < 12; d++){
            ckv[d] = *(const u64*)(ex + (12+d)*512 + lp);
            s2p = fma2(ckv[d], ckv[d], s2p);
        }
        float s20, s21; upk2(s2p, s20, s21);
        float cf = Tp[0] / g_msum[b];
        float2 mk = *(const float2*)(frame + (size_t)b*LL + l0);
        u64 sc2 = pk2(mk.x*cf*rsqrtf(s20), mk.y*cf*rsqrtf(s21));

        // Q projection + sigmoid
        {
            float qs[12];
            #pragma unroll
            for (int j = 0; j < 12; j++){
                u64 a = pk2(fbs[j], fbs[j]);
                const ulonglong2* wv = (const ulonglong2*)(fwT + j*12);
                #pragma unroll
                for (int dp = 0; dp < 6; dp++){
                    ulonglong2 w = wv[dp];
                    a = fma2(inq[2*dp  ], w.x, a);
                    a = fma2(inq[2*dp+1], w.y, a);
                }
                float x0, x1; upk2(a, x0, x1);
                x0 = sigm(x0); x1 = sigm(x1);
                *(u64*)(g_q + ((size_t)b*DD + j)*LL + l0) = pk2(x0, x1);
                qs[j] = x0 + x1;
            }
            #pragma unroll
            for (int j = 0; j < 12; j++){
                float s = wredsum(qs[j]);
                if ((tid & 31) == 0) atomicAdd(&red[j], s);
            }
        }
        #pragma unroll
        for (int d = 0; d < 12; d++) ckv[d] = fma2(ckv[d], sc2, 0ull);
        // K projection + sigmoid
        {
            float ks[12];
            #pragma unroll
            for (int j = 0; j < 12; j++){
                u64 a = pk2(fbs[12+j], fbs[12+j]);
                const ulonglong2* wv = (const ulonglong2*)(fwT + 144 + j*12);
                #pragma unroll
                for (int dp = 0; dp < 6; dp++){
                    ulonglong2 w = wv[dp];
                    a = fma2(ckv[2*dp  ], w.x, a);
                    a = fma2(ckv[2*dp+1], w.y, a);
                }
                float x0, x1; upk2(a, x0, x1);
                x0 = sigm(x0); x1 = sigm(x1);
                *(u64*)(g_k + ((size_t)b*DD + j)*LL + l0) = pk2(x0, x1);
                ks[j] = x0 + x1;
            }
            #pragma unroll
            for (int j = 0; j < 12; j++){
                float s = wredsum(ks[j]);
                if ((tid & 31) == 0) atomicAdd(&red[12+j], s);
            }
        }
        // V projection
        #pragma unroll
        for (int j = 0; j < 12; j++){
            u64 a = pk2(fbs[24+j], fbs[24+j]);
            const ulonglong2* wv = (const ulonglong2*)(fwT + 288 + j*12);
            #pragma unroll
            for (int dp = 0; dp < 6; dp++){
                ulonglong2 w = wv[dp];
                a = fma2(ckv[2*dp  ], w.x, a);
                a = fma2(ckv[2*dp+1], w.y, a);
            }
            *(u64*)(g_v + ((size_t)b*DD + j)*LL + l0) = a;
        }
    }
    __syncthreads();
    if (tid < 12)       atomicAdd(&g_qsum[b][tid], red[tid]);
    else if (tid < 24)  atomicAdd(&g_ksum[b][tid-12], red[tid]);
}

// ------------- K3: sq/skv sums (4 pos/thread, coalesced) -------------
__global__ void __launch_bounds__(256) k3(){
    int b = blockIdx.y;
    int tid = threadIdx.x;
    int l0 = (blockIdx.x*256 + tid)*4;
    __shared__ float kE[12], qE[12], red[24];
    if (tid < 12){ kE[tid] = g_ksum[b][tid] + EPSf; qE[tid] = g_qsum[b][tid] + EPSf; }
    if (tid < 24) red[tid] = 0.f;
    __syncthreads();
    float4 q4[12], k4[12];
    #pragma unroll
    for (int d = 0; d < 12; d++){
        q4[d] = *(const float4*)(g_q + ((size_t)b*DD + d)*LL + l0);
        k4[d] = *(const float4*)(g_k + ((size_t)b*DD + d)*LL + l0);
    }
    float4 si = make_float4(0,0,0,0), so = make_float4(0,0,0,0);
    #pragma unroll
    for (int d = 0; d < 12; d++){
        si.x += (q4[d].x+EPSf)*kE[d]; si.y += (q4[d].y+EPSf)*kE[d];
        si.z += (q4[d].z+EPSf)*kE[d]; si.w += (q4[d].w+EPSf)*kE[d];
        so.x += (k4[d].x+EPSf)*qE[d]; so.y += (k4[d].y+EPSf)*qE[d];
        so.z += (k4[d].z+EPSf)*qE[d]; so.w += (k4[d].w+EPSf)*qE[d];
    }
    si.x = 1.f/si.x; si.y = 1.f/si.y; si.z = 1.f/si.z; si.w = 1.f/si.w;
    so.x = 1.f/so.x; so.y = 1.f/so.y; so.z = 1.f/so.z; so.w = 1.f/so.w;
    #pragma unroll
    for (int d = 0; d < 12; d++){
        float sqv  = q4[d].x*si.x + q4[d].y*si.y + q4[d].z*si.z + q4[d].w*si.w;
        float skvv = k4[d].x*so.x + k4[d].y*so.y + k4[d].z*so.z + k4[d].w*so.w;
        sqv = wredsum(sqv); skvv = wredsum(skvv);
        if ((tid & 31) == 0){ atomicAdd(&red[d], sqv); atomicAdd(&red[12+d], skvv); }
    }
    __syncthreads();
    if (tid < 12)      atomicAdd(&g_sq[b][tid], red[tid]);
    else if (tid < 24) atomicAdd(&g_skv[b][tid-12], red[tid]);
}

// ------------- K456: cons + exp(cons-CSH) + sumexp + kv outer product -------------
__global__ void __launch_bounds__(256,1) k456(){
    int b = blockIdx.y;
    int tid = threadIdx.x;
    __shared__ float sqE[12];
    if (tid < 12) sqE[tid] = g_sq[b][tid] + EPSf;
    __syncthreads();
    float acc[12][12];
    #pragma unroll
    for (int d = 0; d < 12; d++)
        #pragma unroll
        for (int m = 0; m < 12; m++) acc[d][m] = 0.f;
    float se = 0.f;

    for (int l = blockIdx.x*256 + tid; l < LL; l += 96*256){
        float k[12], v[12];
        #pragma unroll
        for (int d = 0; d < 12; d++){
            k[d] = g_k[((size_t)b*DD + d)*LL + l];
            v[d] = g_v[((size_t)b*DD + d)*LL + l];
        }
        float cons = 0.f;
        #pragma unroll
        for (int d = 0; d < 12; d++) cons += (k[d]+EPSf)*sqE[d];
        float e = __expf(cons - CSH);
        se += e;
        #pragma unroll
        for (int m = 0; m < 12; m++) v[m] *= e;
        #pragma unroll
        for (int d = 0; d < 12; d++)
            #pragma unroll
            for (int m = 0; m < 12; m++) acc[d][m] += k[d]*v[m];
    }
    __shared__ float red[144];
    __shared__ float sred;
    for (int i = tid; i < 144; i += 256) red[i] = 0.f;
    if (tid == 0) sred = 0.f;
    __syncthreads();
    se = wredsum(se);
    if ((tid & 31) == 0) atomicAdd(&sred, se);
    #pragma unroll
    for (int d = 0; d < 12; d++)
        #pragma unroll
        for (int m = 0; m < 12; m++){
            float v = wredsum(acc[d][m]);
            if ((tid & 31) == 0) atomicAdd(&red[d*12+m], v);
        }
    __syncthreads();
    if (tid < 144) atomicAdd(&g_kvm[b][tid], red[tid]);
    if (tid == 0)  atomicAdd(&g_sumexp[b], sred);
}

// ------------- Kmm: M = kv_norm @ Wo -------------
__global__ void kmm(const float* __restrict__ fwo){
    int b = blockIdx.x, tid = threadIdx.x;
    float norm = 172032.0f / g_sumexp[b];
    int d = tid/12, j = tid%12;
    float s = 0.f;
    #pragma unroll
    for (int m = 0; m < 12; m++) s += g_kvm[b][d*12+m]*fwo[m*12+j];
    g_M[b][tid] = s * norm;
}

// ------------- K7: epilogue (4 pos/thread, si recomputed inline) -------------
__global__ void __launch_bounds__(256) k7(const float* __restrict__ fbo, float* __restrict__ out){
    int b = blockIdx.y;
    int tid = threadIdx.x;
    int l0 = (blockIdx.x*256 + tid)*4;
    __shared__ float Ms[144], skvE[12], kE[12], bos[12];
    if (tid < 144) Ms[tid] = g_M[b][tid];
    if (tid < 12){
        skvE[tid] = g_skv[b][tid] + EPSf;
        kE[tid]   = g_ksum[b][tid] + EPSf;
        bos[tid]  = fbo[tid];
    }
    __syncthreads();
    float4 q4[12];
    #pragma unroll
    for (int d = 0; d < 12; d++)
        q4[d] = *(const float4*)(g_q + ((size_t)b*DD + d)*LL + l0);
    float4 cs = make_float4(0,0,0,0), si = make_float4(0,0,0,0);
    #pragma unroll
    for (int d = 0; d < 12; d++){
        cs.x += (q4[d].x+EPSf)*skvE[d]; cs.y += (q4[d].y+EPSf)*skvE[d];
        cs.z += (q4[d].z+EPSf)*skvE[d]; cs.w += (q4[d].w+EPSf)*skvE[d];
        si.x += (q4[d].x+EPSf)*kE[d];   si.y += (q4[d].y+EPSf)*kE[d];
        si.z += (q4[d].z+EPSf)*kE[d];   si.w += (q4[d].w+EPSf)*kE[d];
    }
    float4 sc;
    sc.x = sigm(cs.x)/si.x; sc.y = sigm(cs.y)/si.y;
    sc.z = sigm(cs.z)/si.z; sc.w = sigm(cs.w)/si.w;
    #pragma unroll
    for (int j = 0; j < 12; j++){
        float4 o = make_float4(0,0,0,0);
        #pragma unroll
        for (int d = 0; d < 12; d++){
            float w = Ms[d*12+j];
            o.x += q4[d].x*w; o.y += q4[d].y*w;
            o.z += q4[d].z*w; o.w += q4[d].w*w;
        }
        float4 r;
        r.x = bos[j] + sc.x*o.x; r.y = bos[j] + sc.y*o.y;
        r.z = bos[j] + sc.z*o.z; r.w = bos[j] + sc.w*o.w;
        *(float4*)(out + ((size_t)b*DD + j)*LL + l0) = r;
    }
}

extern "C" void kernel_launch(void* const* d_in, const int* in_sizes, int n_in,
                              void* d_out, int out_size){
    const float* x     = (const float*)d_in[0];
    const float* frame = (const float*)d_in[1];
    const float* wpre  = (const float*)d_in[2];
    const float* bpre  = (const float*)d_in[3];
    const float* gam   = (const float*)d_in[4];
    const float* bet   = (const float*)d_in[5];
    const float* mean  = (const float*)d_in[6];
    const float* var   = (const float*)d_in[7];
    const float* Tp    = (const float*)d_in[8];
    const float* wq    = (const float*)d_in[9];
    const float* bqc   = (const float*)d_in[10];
    const float* wkv   = (const float*)d_in[11];
    const float* bkvc  = (const float*)d_in[12];
    const float* fwq   = (const float*)d_in[13];
    const float* fbq   = (const float*)d_in[14];
    const float* fwk   = (const float*)d_in[15];
    const float* fbk   = (const float*)d_in[16];
    const float* fwv   = (const float*)d_in[17];
    const float* fbv   = (const float*)d_in[18];
    const float* fwo   = (const float*)d_in[19];
    const float* fbo   = (const float*)d_in[20];
    float* out = (float*)d_out;

    cudaFuncSetAttribute(k_conv1, cudaFuncAttributeMaxDynamicSharedMemorySize, C1_SMEM);
    cudaFuncSetAttribute(k_qkv2,  cudaFuncAttributeMaxDynamicSharedMemorySize, QKV_SMEM);

    k_init  <<<1, 1024>>>();
    k_msum  <<<dim3(168, Bn), 256>>>(frame);
    k_nop   <<<1, 32>>>();
    k_conv1 <<<dim3(16, 32, Bn), 256, C1_SMEM>>>(x, wpre, bpre, gam, bet, mean, var);
    k_qkv2  <<<dim3(4, FF, Bn), 256, QKV_SMEM>>>(wq, bqc, wkv, bkvc, frame, Tp,
                                                 fwq, fbq, fwk, fbk, fwv, fbv);
    k3   <<<dim3(168, Bn), 256>>>();
    k456 <<<dim3(96, Bn), 256>>>();
    kmm  <<<Bn, 144>>>(fwo);
    k7   <<<dim3(168, Bn), 256>>>(fbo, out);
    (void)in_sizes; (void)n_in; (void)out_size;
}

// round 12
// speedup vs baseline: 1.1032x; 1.0244x over previous
#include <cuda_runtime.h>
#include <math.h>

#define Bn 4
#define CIN 8
#define HH 252
#define WW 2048
#define CM 16
#define DD 12
#define FF 84
#define LL (FF*WW)          /* 172032 */
#define EPSf 1.01e-8f
#define HROW 2056           /* padded row: 4 zero cols each side */
#define HOFF 4
#define CSH 8.0f            /* fixed softmax shift */

typedef unsigned long long u64;

__device__ __forceinline__ u64 fma2(u64 a, u64 b, u64 c){
    u64 d; asm("fma.rn.f32x2 %0, %1, %2, %3;" : "=l"(d) : "l"(a), "l"(b), "l"(c)); return d;
}
__device__ __forceinline__ u64 pk2(float lo, float hi){
    u64 r; asm("mov.b64 %0, {%1, %2};" : "=l"(r) : "f"(lo), "f"(hi)); return r;
}
__device__ __forceinline__ void upk2(u64 v, float& lo, float& hi){
    asm("mov.b64 {%0, %1}, %2;" : "=f"(lo), "=f"(hi) : "l"(v));
}
__device__ __forceinline__ float wredsum(float v){
    #pragma unroll
    for (int o = 16; o > 0; o >>= 1) v += __shfl_xor_sync(0xffffffffu, v, o);
    return v;
}
__device__ __forceinline__ float sigm(float x){
    float t;
    asm("tanh.approx.f32 %0, %1;" : "=f"(t) : "f"(x*0.5f));
    return fmaf(0.5f, t, 0.5f);
}
__device__ __forceinline__ float lrelu(float v){ return v >= 0.f ? v : 0.01f*v; }

// ------------- scratch (device globals; zero-initialized at load) -------------
__device__ __align__(16) float g_h [(size_t)Bn*CM*HH*HROW];  // padded, borders stay 0
// channel-major: [b][d][L]
__device__ __align__(16) float g_q [(size_t)Bn*DD*LL];
__device__ __align__(16) float g_k [(size_t)Bn*DD*LL];
__device__ __align__(16) float g_v [(size_t)Bn*DD*LL];
__device__ float g_msum[Bn], g_sumexp[Bn];
__device__ float g_qsum[Bn][DD], g_ksum[Bn][DD], g_sq[Bn][DD], g_skv[Bn][DD];
__device__ float g_kvm[Bn][DD*DD];
__device__ float g_M[Bn][DD*DD];

// ------------- K0: zero accumulators -------------
__global__ void k_init(){
    int t = threadIdx.x;
    if (t < Bn){ g_msum[t]=0.f; g_sumexp[t]=0.f; }
    if (t < Bn*DD){
        ((float*)g_qsum)[t]=0.f; ((float*)g_ksum)[t]=0.f;
        ((float*)g_sq)[t]=0.f;   ((float*)g_skv)[t]=0.f;
    }
    if (t < Bn*DD*DD) ((float*)g_kvm)[t]=0.f;
}

// ------------- nop: keeps profile capture window on k_conv1 -------------
__global__ void k_nop(){}

// ------------- mask sum per batch -------------
__global__ void __launch_bounds__(256) k_msum(const float* __restrict__ frame){
    int b = blockIdx.y;
    int i = (blockIdx.x*256 + threadIdx.x)*4;
    float4 v = *(const float4*)(frame + (size_t)b*LL + i);
    float s = v.x + v.y + v.z + v.w;
    s = wredsum(s);
    __shared__ float sr;
    if (threadIdx.x == 0) sr = 0.f;
    __syncthreads();
    if ((threadIdx.x & 31) == 0) atomicAdd(&sr, s);
    __syncthreads();
    if (threadIdx.x == 0) atomicAdd(&g_msum[b], sr);
}

// ------------- K1: conv5x5 + BN + LeakyReLU, ROW-PAIR f32x2, 3 CTAs/SM -------------
// grid (32, 32, 4), block 256, tile 8 rows x 64 cols.
// f32x2 lane pair = output rows (r, r+4); all operands aligned u64, no repack MOVs.
// halves: half 0 -> oc 0-7, half 1 -> oc 8-15. thread: 1 pair-row x 2 cols x 8 oc.
#define C1_SMEM (4352*8 + 3200*8 + 32*4)
__global__ void __launch_bounds__(256,3) k_conv1(
    const float* __restrict__ x, const float* __restrict__ wpre,
    const float* __restrict__ bpre, const float* __restrict__ gam,
    const float* __restrict__ bet,  const float* __restrict__ mean,
    const float* __restrict__ var)
{
    extern __shared__ __align__(16) char smc1[];
    u64*   xp = (u64*)smc1;                // [8c][8pr][68] = 4352 u64
    u64*   ws = xp + 4352;                 // 3200 u64
    float* bns = (float*)(ws + 3200);      // 16
    float* bnc = bns + 16;                 // 16
    int b = blockIdx.z, r0 = blockIdx.y*8, c0 = blockIdx.x*64;
    int tid = threadIdx.x;

    for (int i = tid; i < 3200; i += 256){
        int o = i & 15, rest = i >> 4;
        int kw = rest % 5, kh = (rest/5) % 5, c = rest/25;
        float w = wpre[((o*CIN + c)*5 + kh)*5 + kw];
        ws[i] = pk2(w, w);
    }
    if (tid < 16){
        float s = gam[tid] * rsqrtf(var[tid] + 1e-5f);
        bns[tid] = s;
        bnc[tid] = bet[tid] + (bpre[tid] - mean[tid]) * s;
    }
    // fill xp: pair (x[r0-2+pr][gc], x[r0+2+pr][gc]), gc = c0-2+col
    for (int i = tid; i < 4352; i += 256){
        int col = i % 68; int t2 = i / 68; int pr = t2 & 7; int c = t2 >> 3;
        int gc = c0 - 2 + col;
        int rA = r0 - 2 + pr, rB = r0 + 2 + pr;
        float vA = 0.f, vB = 0.f;
        if (gc >= 0 && gc < WW){
            const float* xc = x + (((size_t)b*CIN + c)*HH)*WW + gc;
            if (rA >= 0 && rA < HH) vA = xc[(size_t)rA*WW];
            if (rB < HH)            vB = xc[(size_t)rB*WW];
        }
        xp[i] = pk2(vA, vB);
    }
    __syncthreads();

    int half = tid >> 7, lt = tid & 127;
    int prow = lt >> 5, lane = lt & 31, col0 = lane*2;
    u64 acc[8][2];
    #pragma unroll
    for (int o = 0; o < 8; o++){ acc[o][0] = 0ull; acc[o][1] = 0ull; }

    #pragma unroll 1
    for (int c = 0; c < CIN; c++){
        #pragma unroll
        for (int kh = 0; kh < 5; kh++){
            // X window: tile cols col0-2 .. col0+3 (6 u64), 16B-aligned base
            const u64* xr = xp + ((c*8 + prow + kh)*68) + col0;
            ulonglong2 x0 = ((const ulonglong2*)xr)[0];
            ulonglong2 x1 = ((const ulonglong2*)xr)[1];
            ulonglong2 x2 = ((const ulonglong2*)xr)[2];
            u64 X[6] = {x0.x, x0.y, x1.x, x1.y, x2.x, x2.y};
            const u64* wb = ws + ((c*5 + kh)*5)*16 + half*8;
            #pragma unroll
            for (int kw = 0; kw < 5; kw++){
                const ulonglong2* wv = (const ulonglong2*)(wb + kw*16);
                ulonglong2 w0 = wv[0], w1 = wv[1], w2 = wv[2], w3 = wv[3];
                #pragma unroll
                for (int cc = 0; cc < 2; cc++){
                    u64 xv = X[kw + cc];
                    acc[0][cc] = fma2(xv, w0.x, acc[0][cc]);
                    acc[1][cc] = fma2(xv, w0.y, acc[1][cc]);
                    acc[2][cc] = fma2(xv, w1.x, acc[2][cc]);
                    acc[3][cc] = fma2(xv, w1.y, acc[3][cc]);
                    acc[4][cc] = fma2(xv, w2.x, acc[4][cc]);
                    acc[5][cc] = fma2(xv, w2.y, acc[5][cc]);
                    acc[6][cc] = fma2(xv, w3.x, acc[6][cc]);
                    acc[7][cc] = fma2(xv, w3.y, acc[7][cc]);
                }
            }
        }
    }
    int rA = r0 + prow, rB = r0 + prow + 4;
    #pragma unroll
    for (int oc = 0; oc < 8; oc++){
        int o = half*8 + oc;
        float s = bns[o], c2 = bnc[o];
        float a0,b0,a1,b1;
        upk2(acc[oc][0], a0, b0); upk2(acc[oc][1], a1, b1);
        float* base = g_h + (((size_t)b*CM + o)*HH)*HROW + HOFF + c0 + col0;
        if (rA < HH)
            *(float2*)(base + (size_t)rA*HROW)
                = make_float2(lrelu(a0*s+c2), lrelu(a1*s+c2));
        if (rB < HH)
            *(float2*)(base + (size_t)rB*HROW)
                = make_float2(lrelu(b0*s+c2), lrelu(b1*s+c2));
    }
}

// ------------- K2: FUSED Q/KV convs + masknorm + projections + sums -------------
#define QKV_SMEM (3456*8 + 432*8 + 12288*4 + 96*4)
__global__ void __launch_bounds__(256,2) k_qkv2(
    const float* __restrict__ wq,  const float* __restrict__ bqc,
    const float* __restrict__ wkv, const float* __restrict__ bkvc,
    const float* __restrict__ frame, const float* __restrict__ Tp,
    const float* __restrict__ fwq, const float* __restrict__ fbq,
    const float* __restrict__ fwk, const float* __restrict__ fbk,
    const float* __restrict__ fwv, const float* __restrict__ fbv)
{
    extern __shared__ __align__(16) char smraw[];
    u64*   ws  = (u64*)smraw;                  // 3456
    u64*   fwT = ws + 3456;                    // 432
    float* ex  = (float*)(fwT + 432);          // 24*512 floats
    float* cbs = ex + 12288;                   // 24
    float* fbs = cbs + 24;                     // 36
    float* red = fbs + 36;                     // 24

    int b = blockIdx.z, f = blockIdx.y;
    int tid = threadIdx.x;

    for (int i = tid; i < 3456; i += 256){
        int half2 = i / 1728, rem = i % 1728;
        int d = rem % 12, r2 = rem / 12;
        int kw = r2 % 3, kh = (r2/3) % 3, c = r2/9;
        const float* srcw = half2 ? wkv : wq;
        float w = srcw[((d*CM + c)*3 + kh)*3 + kw];
        ws[i] = pk2(w, w);
    }
    for (int i = tid; i < 432; i += 256){
        int wsel = i / 144, rem = i % 144, j = rem / 12, d = rem % 12;
        float w = (wsel == 0 ? fwq : (wsel == 1 ? fwk : fwv))[d*12 + j];
        fwT[i] = pk2(w, w);
    }
    if (tid < 24) cbs[tid] = (tid < 12) ? bqc[tid] : bkvc[tid-12];
    if (tid < 36) fbs[tid] = (tid < 12) ? fbq[tid] : (tid < 24 ? fbk[tid-12] : fbv[tid-24]);
    if (tid < 24) red[tid] = 0.f;
    __syncthreads();

    // ---- Phase 1: conv, 4 positions/thread ----
    {
        int half = tid >> 7, pt = tid & 127, lane = tid & 31;
        int t0 = blockIdx.x*512 + pt*4;
        u64 acc[12][2];
        #pragma unroll
        for (int d = 0; d < 12; d++){
            u64 bb = pk2(cbs[half*12+d], cbs[half*12+d]);
            acc[d][0] = bb; acc[d][1] = bb;
        }
        const float* hb = g_h + (((size_t)b*CM)*HH + 3*f)*HROW + HOFF + t0;
        const u64* wsh = ws + half*1728;
        #pragma unroll 1
        for (int c = 0; c < 16; c++){
            #pragma unroll
            for (int kh = 0; kh < 3; kh++){
                const float* row = hb + ((size_t)c*HH + kh)*HROW;
                float4 F = *(const float4*)row;
                float xm1 = __shfl_up_sync(0xffffffffu, F.w, 1);
                if (lane == 0)  xm1 = row[-1];
                float xp4 = __shfl_down_sync(0xffffffffu, F.x, 1);
                if (lane == 31) xp4 = row[4];
                u64 P[3][2];
                P[0][0] = pk2(xm1, F.x); P[0][1] = pk2(F.y, F.z);
                P[1][0] = pk2(F.x, F.y); P[1][1] = pk2(F.z, F.w);
                P[2][0] = pk2(F.y, F.z); P[2][1] = pk2(F.w, xp4);
                const u64* wp = wsh + (c*3 + kh)*36;
                #pragma unroll
                for (int kw = 0; kw < 3; kw++){
                    const ulonglong2* w2 = (const ulonglong2*)(wp + kw*12);
                    #pragma unroll
                    for (int dp = 0; dp < 6; dp++){
                        ulonglong2 wv = w2[dp];
                        acc[2*dp  ][0] = fma2(P[kw][0], wv.x, acc[2*dp  ][0]);
                        acc[2*dp  ][1] = fma2(P[kw][1], wv.x, acc[2*dp  ][1]);
                        acc[2*dp+1][0] = fma2(P[kw][0], wv.y, acc[2*dp+1][0]);
                        acc[2*dp+1][1] = fma2(P[kw][1], wv.y, acc[2*dp+1][1]);
                    }
                }
            }
        }
        float* exb = ex + (half*12)*512 + pt*4;
        #pragma unroll
        for (int d = 0; d < 12; d++){
            float v0,v1,v2,v3;
            upk2(acc[d][0], v0, v1); upk2(acc[d][1], v2, v3);
            *(float4*)(exb + d*512) = make_float4(v0,v1,v2,v3);
        }
    }
    __syncthreads();

    // ---- Phase 2: masknorm + projections (2 positions/thread, packed) ----
    {
        int lp = tid*2;
        size_t l0 = (size_t)f*WW + blockIdx.x*512 + lp;
        u64 inq[12], ckv[12];
        #pragma unroll
        for (int d = 0; d < 12; d++) inq[d] = *(const u64*)(ex + d*512 + lp);
        u64 s2p = pk2(EPSf, EPSf);
        #pragma unroll
        for (int d = 0; d < 12; d++){
            ckv[d] = *(const u64*)(ex + (12+d)*512 + lp);
            s2p = fma2(ckv[d], ckv[d], s2p);
        }
        float s20, s21; upk2(s2p, s20, s21);
        float cf = Tp[0] / g_msum[b];
        float2 mk = *(const float2*)(frame + (size_t)b*LL + l0);
        u64 sc2 = pk2(mk.x*cf*rsqrtf(s20), mk.y*cf*rsqrtf(s21));

        // Q projection + sigmoid
        {
            float qs[12];
            #pragma unroll
            for (int j = 0; j < 12; j++){
                u64 a = pk2(fbs[j], fbs[j]);
                const ulonglong2* wv = (const ulonglong2*)(fwT + j*12);
                #pragma unroll
                for (int dp = 0; dp < 6; dp++){
                    ulonglong2 w = wv[dp];
                    a = fma2(inq[2*dp  ], w.x, a);
                    a = fma2(inq[2*dp+1], w.y, a);
                }
                float x0, x1; upk2(a, x0, x1);
                x0 = sigm(x0); x1 = sigm(x1);
                *(u64*)(g_q + ((size_t)b*DD + j)*LL + l0) = pk2(x0, x1);
                qs[j] = x0 + x1;
            }
            #pragma unroll
            for (int j = 0; j < 12; j++){
                float s = wredsum(qs[j]);
                if ((tid & 31) == 0) atomicAdd(&red[j], s);
            }
        }
        #pragma unroll
        for (int d = 0; d < 12; d++) ckv[d] = fma2(ckv[d], sc2, 0ull);
        // K projection + sigmoid
        {
            float ks[12];
            #pragma unroll
            for (int j = 0; j < 12; j++){
                u64 a = pk2(fbs[12+j], fbs[12+j]);
                const ulonglong2* wv = (const ulonglong2*)(fwT + 144 + j*12);
                #pragma unroll
                for (int dp = 0; dp < 6; dp++){
                    ulonglong2 w = wv[dp];
                    a = fma2(ckv[2*dp  ], w.x, a);
                    a = fma2(ckv[2*dp+1], w.y, a);
                }
                float x0, x1; upk2(a, x0, x1);
                x0 = sigm(x0); x1 = sigm(x1);
                *(u64*)(g_k + ((size_t)b*DD + j)*LL + l0) = pk2(x0, x1);
                ks[j] = x0 + x1;
            }
            #pragma unroll
            for (int j = 0; j < 12; j++){
                float s = wredsum(ks[j]);
                if ((tid & 31) == 0) atomicAdd(&red[12+j], s);
            }
        }
        // V projection
        #pragma unroll
        for (int j = 0; j < 12; j++){
            u64 a = pk2(fbs[24+j], fbs[24+j]);
            const ulonglong2* wv = (const ulonglong2*)(fwT + 288 + j*12);
            #pragma unroll
            for (int dp = 0; dp < 6; dp++){
                ulonglong2 w = wv[dp];
                a = fma2(ckv[2*dp  ], w.x, a);
                a = fma2(ckv[2*dp+1], w.y, a);
            }
            *(u64*)(g_v + ((size_t)b*DD + j)*LL + l0) = a;
        }
    }
    __syncthreads();
    if (tid < 12)       atomicAdd(&g_qsum[b][tid], red[tid]);
    else if (tid < 24)  atomicAdd(&g_ksum[b][tid-12], red[tid]);
}

// ------------- K3: sq/skv sums (4 pos/thread, coalesced) -------------
__global__ void __launch_bounds__(256) k3(){
    int b = blockIdx.y;
    int tid = threadIdx.x;
    int l0 = (blockIdx.x*256 + tid)*4;
    __shared__ float kE[12], qE[12], red[24];
    if (tid < 12){ kE[tid] = g_ksum[b][tid] + EPSf; qE[tid] = g_qsum[b][tid] + EPSf; }
    if (tid < 24) red[tid] = 0.f;
    __syncthreads();
    float4 q4[12], k4[12];
    #pragma unroll
    for (int d = 0; d < 12; d++){
        q4[d] = *(const float4*)(g_q + ((size_t)b*DD + d)*LL + l0);
        k4[d] = *(const float4*)(g_k + ((size_t)b*DD + d)*LL + l0);
    }
    float4 si = make_float4(0,0,0,0), so = make_float4(0,0,0,0);
    #pragma unroll
    for (int d = 0; d < 12; d++){
        si.x += (q4[d].x+EPSf)*kE[d]; si.y += (q4[d].y+EPSf)*kE[d];
        si.z += (q4[d].z+EPSf)*kE[d]; si.w += (q4[d].w+EPSf)*kE[d];
        so.x += (k4[d].x+EPSf)*qE[d]; so.y += (k4[d].y+EPSf)*qE[d];
        so.z += (k4[d].z+EPSf)*qE[d]; so.w += (k4[d].w+EPSf)*qE[d];
    }
    si.x = 1.f/si.x; si.y = 1.f/si.y; si.z = 1.f/si.z; si.w = 1.f/si.w;
    so.x = 1.f/so.x; so.y = 1.f/so.y; so.z = 1.f/so.z; so.w = 1.f/so.w;
    #pragma unroll
    for (int d = 0; d < 12; d++){
        float sqv  = q4[d].x*si.x + q4[d].y*si.y + q4[d].z*si.z + q4[d].w*si.w;
        float skvv = k4[d].x*so.x + k4[d].y*so.y + k4[d].z*so.z + k4[d].w*so.w;
        sqv = wredsum(sqv); skvv = wredsum(skvv);
        if ((tid & 31) == 0){ atomicAdd(&red[d], sqv); atomicAdd(&red[12+d], skvv); }
    }
    __syncthreads();
    if (tid < 12)      atomicAdd(&g_sq[b][tid], red[tid]);
    else if (tid < 24) atomicAdd(&g_skv[b][tid-12], red[tid]);
}

// ------------- K456: cons + exp(cons-CSH) + sumexp + kv outer product -------------
__global__ void __launch_bounds__(256,1) k456(){
    int b = blockIdx.y;
    int tid = threadIdx.x;
    __shared__ float sqE[12];
    if (tid < 12) sqE[tid] = g_sq[b][tid] + EPSf;
    __syncthreads();
    float acc[12][12];
    #pragma unroll
    for (int d = 0; d < 12; d++)
        #pragma unroll
        for (int m = 0; m < 12; m++) acc[d][m] = 0.f;
    float se = 0.f;

    for (int l = blockIdx.x*256 + tid; l < LL; l += 96*256){
        float k[12], v[12];
        #pragma unroll
        for (int d = 0; d < 12; d++){
            k[d] = g_k[((size_t)b*DD + d)*LL + l];
            v[d] = g_v[((size_t)b*DD + d)*LL + l];
        }
        float cons = 0.f;
        #pragma unroll
        for (int d = 0; d < 12; d++) cons += (k[d]+EPSf)*sqE[d];
        float e = __expf(cons - CSH);
        se += e;
        #pragma unroll
        for (int m = 0; m < 12; m++) v[m] *= e;
        #pragma unroll
        for (int d = 0; d < 12; d++)
            #pragma unroll
            for (int m = 0; m < 12; m++) acc[d][m] += k[d]*v[m];
    }
    __shared__ float red[144];
    __shared__ float sred;
    for (int i = tid; i < 144; i += 256) red[i] = 0.f;
    if (tid == 0) sred = 0.f;
    __syncthreads();
    se = wredsum(se);
    if ((tid & 31) == 0) atomicAdd(&sred, se);
    #pragma unroll
    for (int d = 0; d < 12; d++)
        #pragma unroll
        for (int m = 0; m < 12; m++){
            float v = wredsum(acc[d][m]);
            if ((tid & 31) == 0) atomicAdd(&red[d*12+m], v);
        }
    __syncthreads();
    if (tid < 144) atomicAdd(&g_kvm[b][tid], red[tid]);
    if (tid == 0)  atomicAdd(&g_sumexp[b], sred);
}

// ------------- Kmm: M = kv_norm @ Wo -------------
__global__ void kmm(const float* __restrict__ fwo){
    int b = blockIdx.x, tid = threadIdx.x;
    float norm = 172032.0f / g_sumexp[b];
    int d = tid/12, j = tid%12;
    float s = 0.f;
    #pragma unroll
    for (int m = 0; m < 12; m++) s += g_kvm[b][d*12+m]*fwo[m*12+j];
    g_M[b][tid] = s * norm;
}

// ------------- K7: epilogue (4 pos/thread, si recomputed inline) -------------
__global__ void __launch_bounds__(256) k7(const float* __restrict__ fbo, float* __restrict__ out){
    int b = blockIdx.y;
    int tid = threadIdx.x;
    int l0 = (blockIdx.x*256 + tid)*4;
    __shared__ float Ms[144], skvE[12], kE[12], bos[12];
    if (tid < 144) Ms[tid] = g_M[b][tid];
    if (tid < 12){
        skvE[tid] = g_skv[b][tid] + EPSf;
        kE[tid]   = g_ksum[b][tid] + EPSf;
        bos[tid]  = fbo[tid];
    }
    __syncthreads();
    float4 q4[12];
    #pragma unroll
    for (int d = 0; d < 12; d++)
        q4[d] = *(const float4*)(g_q + ((size_t)b*DD + d)*LL + l0);
    float4 cs = make_float4(0,0,0,0), si = make_float4(0,0,0,0);
    #pragma unroll
    for (int d = 0; d < 12; d++){
        cs.x += (q4[d].x+EPSf)*skvE[d]; cs.y += (q4[d].y+EPSf)*skvE[d];
        cs.z += (q4[d].z+EPSf)*skvE[d]; cs.w += (q4[d].w+EPSf)*skvE[d];
        si.x += (q4[d].x+EPSf)*kE[d];   si.y += (q4[d].y+EPSf)*kE[d];
        si.z += (q4[d].z+EPSf)*kE[d];   si.w += (q4[d].w+EPSf)*kE[d];
    }
    float4 sc;
    sc.x = sigm(cs.x)/si.x; sc.y = sigm(cs.y)/si.y;
    sc.z = sigm(cs.z)/si.z; sc.w = sigm(cs.w)/si.w;
    #pragma unroll
    for (int j = 0; j < 12; j++){
        float4 o = make_float4(0,0,0,0);
        #pragma unroll
        for (int d = 0; d < 12; d++){
            float w = Ms[d*12+j];
            o.x += q4[d].x*w; o.y += q4[d].y*w;
            o.z += q4[d].z*w; o.w += q4[d].w*w;
        }
        float4 r;
        r.x = bos[j] + sc.x*o.x; r.y = bos[j] + sc.y*o.y;
        r.z = bos[j] + sc.z*o.z; r.w = bos[j] + sc.w*o.w;
        *(float4*)(out + ((size_t)b*DD + j)*LL + l0) = r;
    }
}

extern "C" void kernel_launch(void* const* d_in, const int* in_sizes, int n_in,
                              void* d_out, int out_size){
    const float* x     = (const float*)d_in[0];
    const float* frame = (const float*)d_in[1];
    const float* wpre  = (const float*)d_in[2];
    const float* bpre  = (const float*)d_in[3];
    const float* gam   = (const float*)d_in[4];
    const float* bet   = (const float*)d_in[5];
    const float* mean  = (const float*)d_in[6];
    const float* var   = (const float*)d_in[7];
    const float* Tp    = (const float*)d_in[8];
    const float* wq    = (const float*)d_in[9];
    const float* bqc   = (const float*)d_in[10];
    const float* wkv   = (const float*)d_in[11];
    const float* bkvc  = (const float*)d_in[12];
    const float* fwq   = (const float*)d_in[13];
    const float* fbq   = (const float*)d_in[14];
    const float* fwk   = (const float*)d_in[15];
    const float* fbk   = (const float*)d_in[16];
    const float* fwv   = (const float*)d_in[17];
    const float* fbv   = (const float*)d_in[18];
    const float* fwo   = (const float*)d_in[19];
    const float* fbo   = (const float*)d_in[20];
    float* out = (float*)d_out;

    cudaFuncSetAttribute(k_conv1, cudaFuncAttributeMaxDynamicSharedMemorySize, C1_SMEM);
    cudaFuncSetAttribute(k_qkv2,  cudaFuncAttributeMaxDynamicSharedMemorySize, QKV_SMEM);

    k_init  <<<1, 1024>>>();
    k_msum  <<<dim3(168, Bn), 256>>>(frame);
    k_nop   <<<1, 32>>>();
    k_conv1 <<<dim3(32, 32, Bn), 256, C1_SMEM>>>(x, wpre, bpre, gam, bet, mean, var);
    k_qkv2  <<<dim3(4, FF, Bn), 256, QKV_SMEM>>>(wq, bqc, wkv, bkvc, frame, Tp,
                                                 fwq, fbq, fwk, fbk, fwv, fbv);
    k3   <<<dim3(168, Bn), 256>>>();
    k456 <<<dim3(96, Bn), 256>>>();
    kmm  <<<Bn, 144>>>(fwo);
    k7   <<<dim3(168, Bn), 256>>>(fbo, out);
    (void)in_sizes; (void)n_in; (void)out_size;
}

// round 13
// speedup vs baseline: 1.2249x; 1.1102x over previous
#include <cuda_runtime.h>
#include <math.h>

#define Bn 4
#define CIN 8
#define HH 252
#define WW 2048
#define CM 16
#define DD 12
#define FF 84
#define LL (FF*WW)          /* 172032 */
#define EPSf 1.01e-8f
#define HROW 2056           /* padded row: 4 zero cols each side */
#define HOFF 4
#define CSH 8.0f            /* fixed softmax shift */

typedef unsigned long long u64;

__device__ __forceinline__ u64 fma2(u64 a, u64 b, u64 c){
    u64 d; asm("fma.rn.f32x2 %0, %1, %2, %3;" : "=l"(d) : "l"(a), "l"(b), "l"(c)); return d;
}
__device__ __forceinline__ u64 pk2(float lo, float hi){
    u64 r; asm("mov.b64 %0, {%1, %2};" : "=l"(r) : "f"(lo), "f"(hi)); return r;
}
__device__ __forceinline__ void upk2(u64 v, float& lo, float& hi){
    asm("mov.b64 {%0, %1}, %2;" : "=f"(lo), "=f"(hi) : "l"(v));
}
__device__ __forceinline__ float wredsum(float v){
    #pragma unroll
    for (int o = 16; o > 0; o >>= 1) v += __shfl_xor_sync(0xffffffffu, v, o);
    return v;
}
__device__ __forceinline__ float sigm(float x){
    float t;
    asm("tanh.approx.f32 %0, %1;" : "=f"(t) : "f"(x*0.5f));
    return fmaf(0.5f, t, 0.5f);
}
__device__ __forceinline__ float lrelu(float v){ return v >= 0.f ? v : 0.01f*v; }

// ------------- scratch (device globals; zero-initialized at load) -------------
__device__ __align__(16) float g_h [(size_t)Bn*CM*HH*HROW];  // padded, borders stay 0
// channel-major: [b][d][L]
__device__ __align__(16) float g_q [(size_t)Bn*DD*LL];
__device__ __align__(16) float g_k [(size_t)Bn*DD*LL];
__device__ __align__(16) float g_v [(size_t)Bn*DD*LL];
__device__ float g_msum[Bn], g_sumexp[Bn];
__device__ float g_qsum[Bn][DD], g_ksum[Bn][DD], g_sq[Bn][DD], g_skv[Bn][DD];
__device__ float g_kvm[Bn][DD*DD];
__device__ float g_M[Bn][DD*DD];

// ------------- K0: zero accumulators -------------
__global__ void k_init(){
    int t = threadIdx.x;
    if (t < Bn){ g_msum[t]=0.f; g_sumexp[t]=0.f; }
    if (t < Bn*DD){
        ((float*)g_qsum)[t]=0.f; ((float*)g_ksum)[t]=0.f;
        ((float*)g_sq)[t]=0.f;   ((float*)g_skv)[t]=0.f;
    }
    if (t < Bn*DD*DD) ((float*)g_kvm)[t]=0.f;
}

// ------------- nop: keeps profile capture window on k_conv1 -------------
__global__ void k_nop(){}

// ------------- mask sum per batch -------------
__global__ void __launch_bounds__(256) k_msum(const float* __restrict__ frame){
    int b = blockIdx.y;
    int i = (blockIdx.x*256 + threadIdx.x)*4;
    float4 v = *(const float4*)(frame + (size_t)b*LL + i);
    float s = v.x + v.y + v.z + v.w;
    s = wredsum(s);
    __shared__ float sr;
    if (threadIdx.x == 0) sr = 0.f;
    __syncthreads();
    if ((threadIdx.x & 31) == 0) atomicAdd(&sr, s);
    __syncthreads();
    if (threadIdx.x == 0) atomicAdd(&g_msum[b], sr);
}

// ------------- K1: conv5x5 + BN + LeakyReLU, ROW-PAIR f32x2, 4 CTAs/SM -------------
// grid (32, 32, 4), block 256, tile 8 rows x 64 cols.
// f32x2 lane pair = output rows (r, r+4); x operands aligned u64 from smem,
// weights stored as FLOATS in smem (halved footprint + wavefronts), pk2'd on the fly.
// halves: half 0 -> oc 0-7, half 1 -> oc 8-15. thread: 1 pair-row x 2 cols x 8 oc.
#define C1_SMEM (4352*8 + 3200*4 + 32*4)
__global__ void __launch_bounds__(256,4) k_conv1(
    const float* __restrict__ x, const float* __restrict__ wpre,
    const float* __restrict__ bpre, const float* __restrict__ gam,
    const float* __restrict__ bet,  const float* __restrict__ mean,
    const float* __restrict__ var)
{
    extern __shared__ __align__(16) char smc1[];
    u64*   xp  = (u64*)smc1;               // [8c][8pr][68] = 4352 u64
    float* wsf = (float*)(xp + 4352);      // 3200 floats [c][kh][kw][16oc]
    float* bns = wsf + 3200;               // 16
    float* bnc = bns + 16;                 // 16
    int b = blockIdx.z, r0 = blockIdx.y*8, c0 = blockIdx.x*64;
    int tid = threadIdx.x;

    for (int i = tid; i < 3200; i += 256){
        int o = i & 15, rest = i >> 4;
        int kw = rest % 5, kh = (rest/5) % 5, c = rest/25;
        wsf[i] = wpre[((o*CIN + c)*5 + kh)*5 + kw];
    }
    if (tid < 16){
        float s = gam[tid] * rsqrtf(var[tid] + 1e-5f);
        bns[tid] = s;
        bnc[tid] = bet[tid] + (bpre[tid] - mean[tid]) * s;
    }
    // fill xp: pair (x[r0-2+pr][gc], x[r0+2+pr][gc]), gc = c0-2+col
    for (int i = tid; i < 4352; i += 256){
        int col = i % 68; int t2 = i / 68; int pr = t2 & 7; int c = t2 >> 3;
        int gc = c0 - 2 + col;
        int rA = r0 - 2 + pr, rB = r0 + 2 + pr;
        float vA = 0.f, vB = 0.f;
        if (gc >= 0 && gc < WW){
            const float* xc = x + (((size_t)b*CIN + c)*HH)*WW + gc;
            if (rA >= 0 && rA < HH) vA = xc[(size_t)rA*WW];
            if (rB < HH)            vB = xc[(size_t)rB*WW];
        }
        xp[i] = pk2(vA, vB);
    }
    __syncthreads();

    int half = tid >> 7, lt = tid & 127;
    int prow = lt >> 5, lane = lt & 31, col0 = lane*2;
    u64 acc[8][2];
    #pragma unroll
    for (int o = 0; o < 8; o++){ acc[o][0] = 0ull; acc[o][1] = 0ull; }

    #pragma unroll 1
    for (int c = 0; c < CIN; c++){
        #pragma unroll
        for (int kh = 0; kh < 5; kh++){
            // X window: tile cols col0-2 .. col0+3 (6 u64), 16B-aligned base
            const u64* xr = xp + ((c*8 + prow + kh)*68) + col0;
            ulonglong2 x0 = ((const ulonglong2*)xr)[0];
            ulonglong2 x1 = ((const ulonglong2*)xr)[1];
            ulonglong2 x2 = ((const ulonglong2*)xr)[2];
            u64 X[6] = {x0.x, x0.y, x1.x, x1.y, x2.x, x2.y};
            const float4* wb4 = (const float4*)(wsf + (c*5 + kh)*80 + half*8);
            #pragma unroll
            for (int kw = 0; kw < 5; kw++){
                float4 wa = wb4[kw*4];
                float4 wc = wb4[kw*4 + 1];
                u64 xv0 = X[kw], xv1 = X[kw+1];
                u64 w;
                w = pk2(wa.x, wa.x);
                acc[0][0] = fma2(xv0, w, acc[0][0]); acc[0][1] = fma2(xv1, w, acc[0][1]);
                w = pk2(wa.y, wa.y);
                acc[1][0] = fma2(xv0, w, acc[1][0]); acc[1][1] = fma2(xv1, w, acc[1][1]);
                w = pk2(wa.z, wa.z);
                acc[2][0] = fma2(xv0, w, acc[2][0]); acc[2][1] = fma2(xv1, w, acc[2][1]);
                w = pk2(wa.w, wa.w);
                acc[3][0] = fma2(xv0, w, acc[3][0]); acc[3][1] = fma2(xv1, w, acc[3][1]);
                w = pk2(wc.x, wc.x);
                acc[4][0] = fma2(xv0, w, acc[4][0]); acc[4][1] = fma2(xv1, w, acc[4][1]);
                w = pk2(wc.y, wc.y);
                acc[5][0] = fma2(xv0, w, acc[5][0]); acc[5][1] = fma2(xv1, w, acc[5][1]);
                w = pk2(wc.z, wc.z);
                acc[6][0] = fma2(xv0, w, acc[6][0]); acc[6][1] = fma2(xv1, w, acc[6][1]);
                w = pk2(wc.w, wc.w);
                acc[7][0] = fma2(xv0, w, acc[7][0]); acc[7][1] = fma2(xv1, w, acc[7][1]);
            }
        }
    }
    int rA = r0 + prow, rB = r0 + prow + 4;
    #pragma unroll
    for (int oc = 0; oc < 8; oc++){
        int o = half*8 + oc;
        float s = bns[o], c2 = bnc[o];
        float a0,b0,a1,b1;
        upk2(acc[oc][0], a0, b0); upk2(acc[oc][1], a1, b1);
        float* base = g_h + (((size_t)b*CM + o)*HH)*HROW + HOFF + c0 + col0;
        if (rA < HH)
            *(float2*)(base + (size_t)rA*HROW)
                = make_float2(lrelu(a0*s+c2), lrelu(a1*s+c2));
        if (rB < HH)
            *(float2*)(base + (size_t)rB*HROW)
                = make_float2(lrelu(b0*s+c2), lrelu(b1*s+c2));
    }
}

// ------------- K2: FUSED Q/KV convs + masknorm + projections + sums -------------
#define QKV_SMEM (3456*8 + 432*8 + 12288*4 + 96*4)
__global__ void __launch_bounds__(256,2) k_qkv2(
    const float* __restrict__ wq,  const float* __restrict__ bqc,
    const float* __restrict__ wkv, const float* __restrict__ bkvc,
    const float* __restrict__ frame, const float* __restrict__ Tp,
    const float* __restrict__ fwq, const float* __restrict__ fbq,
    const float* __restrict__ fwk, const float* __restrict__ fbk,
    const float* __restrict__ fwv, const float* __restrict__ fbv)
{
    extern __shared__ __align__(16) char smraw[];
    u64*   ws  = (u64*)smraw;                  // 3456
    u64*   fwT = ws + 3456;                    // 432
    float* ex  = (float*)(fwT + 432);          // 24*512 floats
    float* cbs = ex + 12288;                   // 24
    float* fbs = cbs + 24;                     // 36
    float* red = fbs + 36;                     // 24

    int b = blockIdx.z, f = blockIdx.y;
    int tid = threadIdx.x;

    for (int i = tid; i < 3456; i += 256){
        int half2 = i / 1728, rem = i % 1728;
        int d = rem % 12, r2 = rem / 12;
        int kw = r2 % 3, kh = (r2/3) % 3, c = r2/9;
        const float* srcw = half2 ? wkv : wq;
        float w = srcw[((d*CM + c)*3 + kh)*3 + kw];
        ws[i] = pk2(w, w);
    }
    for (int i = tid; i < 432; i += 256){
        int wsel = i / 144, rem = i % 144, j = rem / 12, d = rem % 12;
        float w = (wsel == 0 ? fwq : (wsel == 1 ? fwk : fwv))[d*12 + j];
        fwT[i] = pk2(w, w);
    }
    if (tid < 24) cbs[tid] = (tid < 12) ? bqc[tid] : bkvc[tid-12];
    if (tid < 36) fbs[tid] = (tid < 12) ? fbq[tid] : (tid < 24 ? fbk[tid-12] : fbv[tid-24]);
    if (tid < 24) red[tid] = 0.f;
    __syncthreads();

    // ---- Phase 1: conv, 4 positions/thread ----
    {
        int half = tid >> 7, pt = tid & 127, lane = tid & 31;
        int t0 = blockIdx.x*512 + pt*4;
        u64 acc[12][2];
        #pragma unroll
        for (int d = 0; d < 12; d++){
            u64 bb = pk2(cbs[half*12+d], cbs[half*12+d]);
            acc[d][0] = bb; acc[d][1] = bb;
        }
        const float* hb = g_h + (((size_t)b*CM)*HH + 3*f)*HROW + HOFF + t0;
        const u64* wsh = ws + half*1728;
        #pragma unroll 1
        for (int c = 0; c < 16; c++){
            #pragma unroll
            for (int kh = 0; kh < 3; kh++){
                const float* row = hb + ((size_t)c*HH + kh)*HROW;
                float4 F = *(const float4*)row;
                float xm1 = __shfl_up_sync(0xffffffffu, F.w, 1);
                if (lane == 0)  xm1 = row[-1];
                float xp4 = __shfl_down_sync(0xffffffffu, F.x, 1);
                if (lane == 31) xp4 = row[4];
                u64 P[3][2];
                P[0][0] = pk2(xm1, F.x); P[0][1] = pk2(F.y, F.z);
                P[1][0] = pk2(F.x, F.y); P[1][1] = pk2(F.z, F.w);
                P[2][0] = pk2(F.y, F.z); P[2][1] = pk2(F.w, xp4);
                const u64* wp = wsh + (c*3 + kh)*36;
                #pragma unroll
                for (int kw = 0; kw < 3; kw++){
                    const ulonglong2* w2 = (const ulonglong2*)(wp + kw*12);
                    #pragma unroll
                    for (int dp = 0; dp < 6; dp++){
                        ulonglong2 wv = w2[dp];
                        acc[2*dp  ][0] = fma2(P[kw][0], wv.x, acc[2*dp  ][0]);
                        acc[2*dp  ][1] = fma2(P[kw][1], wv.x, acc[2*dp  ][1]);
                        acc[2*dp+1][0] = fma2(P[kw][0], wv.y, acc[2*dp+1][0]);
                        acc[2*dp+1][1] = fma2(P[kw][1], wv.y, acc[2*dp+1][1]);
                    }
                }
            }
        }
        float* exb = ex + (half*12)*512 + pt*4;
        #pragma unroll
        for (int d = 0; d < 12; d++){
            float v0,v1,v2,v3;
            upk2(acc[d][0], v0, v1); upk2(acc[d][1], v2, v3);
            *(float4*)(exb + d*512) = make_float4(v0,v1,v2,v3);
        }
    }
    __syncthreads();

    // ---- Phase 2: masknorm + projections (2 positions/thread, packed) ----
    {
        int lp = tid*2;
        size_t l0 = (size_t)f*WW + blockIdx.x*512 + lp;
        u64 inq[12], ckv[12];
        #pragma unroll
        for (int d = 0; d < 12; d++) inq[d] = *(const u64*)(ex + d*512 + lp);
        u64 s2p = pk2(EPSf, EPSf);
        #pragma unroll
        for (int d = 0; d < 12; d++){
            ckv[d] = *(const u64*)(ex + (12+d)*512 + lp);
            s2p = fma2(ckv[d], ckv[d], s2p);
        }
        float s20, s21; upk2(s2p, s20, s21);
        float cf = Tp[0] / g_msum[b];
        float2 mk = *(const float2*)(frame + (size_t)b*LL + l0);
        u64 sc2 = pk2(mk.x*cf*rsqrtf(s20), mk.y*cf*rsqrtf(s21));

        // Q projection + sigmoid
        {
            float qs[12];
            #pragma unroll
            for (int j = 0; j < 12; j++){
                u64 a = pk2(fbs[j], fbs[j]);
                const ulonglong2* wv = (const ulonglong2*)(fwT + j*12);
                #pragma unroll
                for (int dp = 0; dp < 6; dp++){
                    ulonglong2 w = wv[dp];
                    a = fma2(inq[2*dp  ], w.x, a);
                    a = fma2(inq[2*dp+1], w.y, a);
                }
                float x0, x1; upk2(a, x0, x1);
                x0 = sigm(x0); x1 = sigm(x1);
                *(u64*)(g_q + ((size_t)b*DD + j)*LL + l0) = pk2(x0, x1);
                qs[j] = x0 + x1;
            }
            #pragma unroll
            for (int j = 0; j < 12; j++){
                float s = wredsum(qs[j]);
                if ((tid & 31) == 0) atomicAdd(&red[j], s);
            }
        }
        #pragma unroll
        for (int d = 0; d < 12; d++) ckv[d] = fma2(ckv[d], sc2, 0ull);
        // K projection + sigmoid
        {
            float ks[12];
            #pragma unroll
            for (int j = 0; j < 12; j++){
                u64 a = pk2(fbs[12+j], fbs[12+j]);
                const ulonglong2* wv = (const ulonglong2*)(fwT + 144 + j*12);
                #pragma unroll
                for (int dp = 0; dp < 6; dp++){
                    ulonglong2 w = wv[dp];
                    a = fma2(ckv[2*dp  ], w.x, a);
                    a = fma2(ckv[2*dp+1], w.y, a);
                }
                float x0, x1; upk2(a, x0, x1);
                x0 = sigm(x0); x1 = sigm(x1);
                *(u64*)(g_k + ((size_t)b*DD + j)*LL + l0) = pk2(x0, x1);
                ks[j] = x0 + x1;
            }
            #pragma unroll
            for (int j = 0; j < 12; j++){
                float s = wredsum(ks[j]);
                if ((tid & 31) == 0) atomicAdd(&red[12+j], s);
            }
        }
        // V projection
        #pragma unroll
        for (int j = 0; j < 12; j++){
            u64 a = pk2(fbs[24+j], fbs[24+j]);
            const ulonglong2* wv = (const ulonglong2*)(fwT + 288 + j*12);
            #pragma unroll
            for (int dp = 0; dp < 6; dp++){
                ulonglong2 w = wv[dp];
                a = fma2(ckv[2*dp  ], w.x, a);
                a = fma2(ckv[2*dp+1], w.y, a);
            }
            *(u64*)(g_v + ((size_t)b*DD + j)*LL + l0) = a;
        }
    }
    __syncthreads();
    if (tid < 12)       atomicAdd(&g_qsum[b][tid], red[tid]);
    else if (tid < 24)  atomicAdd(&g_ksum[b][tid-12], red[tid]);
}

// ------------- K3: sq/skv sums (4 pos/thread, coalesced) -------------
__global__ void __launch_bounds__(256) k3(){
    int b = blockIdx.y;
    int tid = threadIdx.x;
    int l0 = (blockIdx.x*256 + tid)*4;
    __shared__ float kE[12], qE[12], red[24];
    if (tid < 12){ kE[tid] = g_ksum[b][tid] + EPSf; qE[tid] = g_qsum[b][tid] + EPSf; }
    if (tid < 24) red[tid] = 0.f;
    __syncthreads();
    float4 q4[12], k4[12];
    #pragma unroll
    for (int d = 0; d < 12; d++){
        q4[d] = *(const float4*)(g_q + ((size_t)b*DD + d)*LL + l0);
        k4[d] = *(const float4*)(g_k + ((size_t)b*DD + d)*LL + l0);
    }
    float4 si = make_float4(0,0,0,0), so = make_float4(0,0,0,0);
    #pragma unroll
    for (int d = 0; d < 12; d++){
        si.x += (q4[d].x+EPSf)*kE[d]; si.y += (q4[d].y+EPSf)*kE[d];
        si.z += (q4[d].z+EPSf)*kE[d]; si.w += (q4[d].w+EPSf)*kE[d];
        so.x += (k4[d].x+EPSf)*qE[d]; so.y += (k4[d].y+EPSf)*qE[d];
        so.z += (k4[d].z+EPSf)*qE[d]; so.w += (k4[d].w+EPSf)*qE[d];
    }
    si.x = 1.f/si.x; si.y = 1.f/si.y; si.z = 1.f/si.z; si.w = 1.f/si.w;
    so.x = 1.f/so.x; so.y = 1.f/so.y; so.z = 1.f/so.z; so.w = 1.f/so.w;
    #pragma unroll
    for (int d = 0; d < 12; d++){
        float sqv  = q4[d].x*si.x + q4[d].y*si.y + q4[d].z*si.z + q4[d].w*si.w;
        float skvv = k4[d].x*so.x + k4[d].y*so.y + k4[d].z*so.z + k4[d].w*so.w;
        sqv = wredsum(sqv); skvv = wredsum(skvv);
        if ((tid & 31) == 0){ atomicAdd(&red[d], sqv); atomicAdd(&red[12+d], skvv); }
    }
    __syncthreads();
    if (tid < 12)      atomicAdd(&g_sq[b][tid], red[tid]);
    else if (tid < 24) atomicAdd(&g_skv[b][tid-12], red[tid]);
}

// ------------- K456: cons + exp(cons-CSH) + sumexp + kv outer product -------------
__global__ void __launch_bounds__(256,1) k456(){
    int b = blockIdx.y;
    int tid = threadIdx.x;
    __shared__ float sqE[12];
    if (tid < 12) sqE[tid] = g_sq[b][tid] + EPSf;
    __syncthreads();
    float acc[12][12];
    #pragma unroll
    for (int d = 0; d < 12; d++)
        #pragma unroll
        for (int m = 0; m < 12; m++) acc[d][m] = 0.f;
    float se = 0.f;

    for (int l = blockIdx.x*256 + tid; l < LL; l += 96*256){
        float k[12], v[12];
        #pragma unroll
        for (int d = 0; d < 12; d++){
            k[d] = g_k[((size_t)b*DD + d)*LL + l];
            v[d] = g_v[((size_t)b*DD + d)*LL + l];
        }
        float cons = 0.f;
        #pragma unroll
        for (int d = 0; d < 12; d++) cons += (k[d]+EPSf)*sqE[d];
        float e = __expf(cons - CSH);
        se += e;
        #pragma unroll
        for (int m = 0; m < 12; m++) v[m] *= e;
        #pragma unroll
        for (int d = 0; d < 12; d++)
            #pragma unroll
            for (int m = 0; m < 12; m++) acc[d][m] += k[d]*v[m];
    }
    __shared__ float red[144];
    __shared__ float sred;
    for (int i = tid; i < 144; i += 256) red[i] = 0.f;
    if (tid == 0) sred = 0.f;
    __syncthreads();
    se = wredsum(se);
    if ((tid & 31) == 0) atomicAdd(&sred, se);
    #pragma unroll
    for (int d = 0; d < 12; d++)
        #pragma unroll
        for (int m = 0; m < 12; m++){
            float v = wredsum(acc[d][m]);
            if ((tid & 31) == 0) atomicAdd(&red[d*12+m], v);
        }
    __syncthreads();
    if (tid < 144) atomicAdd(&g_kvm[b][tid], red[tid]);
    if (tid == 0)  atomicAdd(&g_sumexp[b], sred);
}

// ------------- Kmm: M = kv_norm @ Wo -------------
__global__ void kmm(const float* __restrict__ fwo){
    int b = blockIdx.x, tid = threadIdx.x;
    float norm = 172032.0f / g_sumexp[b];
    int d = tid/12, j = tid%12;
    float s = 0.f;
    #pragma unroll
    for (int m = 0; m < 12; m++) s += g_kvm[b][d*12+m]*fwo[m*12+j];
    g_M[b][tid] = s * norm;
}

// ------------- K7: epilogue (4 pos/thread, si recomputed inline) -------------
__global__ void __launch_bounds__(256) k7(const float* __restrict__ fbo, float* __restrict__ out){
    int b = blockIdx.y;
    int tid = threadIdx.x;
    int l0 = (blockIdx.x*256 + tid)*4;
    __shared__ float Ms[144], skvE[12], kE[12], bos[12];
    if (tid < 144) Ms[tid] = g_M[b][tid];
    if (tid < 12){
        skvE[tid] = g_skv[b][tid] + EPSf;
        kE[tid]   = g_ksum[b][tid] + EPSf;
        bos[tid]  = fbo[tid];
    }
    __syncthreads();
    float4 q4[12];
    #pragma unroll
    for (int d = 0; d < 12; d++)
        q4[d] = *(const float4*)(g_q + ((size_t)b*DD + d)*LL + l0);
    float4 cs = make_float4(0,0,0,0), si = make_float4(0,0,0,0);
    #pragma unroll
    for (int d = 0; d < 12; d++){
        cs.x += (q4[d].x+EPSf)*skvE[d]; cs.y += (q4[d].y+EPSf)*skvE[d];
        cs.z += (q4[d].z+EPSf)*skvE[d]; cs.w += (q4[d].w+EPSf)*skvE[d];
        si.x += (q4[d].x+EPSf)*kE[d];   si.y += (q4[d].y+EPSf)*kE[d];
        si.z += (q4[d].z+EPSf)*kE[d];   si.w += (q4[d].w+EPSf)*kE[d];
    }
    float4 sc;
    sc.x = sigm(cs.x)/si.x; sc.y = sigm(cs.y)/si.y;
    sc.z = sigm(cs.z)/si.z; sc.w = sigm(cs.w)/si.w;
    #pragma unroll
    for (int j = 0; j < 12; j++){
        float4 o = make_float4(0,0,0,0);
        #pragma unroll
        for (int d = 0; d < 12; d++){
            float w = Ms[d*12+j];
            o.x += q4[d].x*w; o.y += q4[d].y*w;
            o.z += q4[d].z*w; o.w += q4[d].w*w;
        }
        float4 r;
        r.x = bos[j] + sc.x*o.x; r.y = bos[j] + sc.y*o.y;
        r.z = bos[j] + sc.z*o.z; r.w = bos[j] + sc.w*o.w;
        *(float4*)(out + ((size_t)b*DD + j)*LL + l0) = r;
    }
}

extern "C" void kernel_launch(void* const* d_in, const int* in_sizes, int n_in,
                              void* d_out, int out_size){
    const float* x     = (const float*)d_in[0];
    const float* frame = (const float*)d_in[1];
    const float* wpre  = (const float*)d_in[2];
    const float* bpre  = (const float*)d_in[3];
    const float* gam   = (const float*)d_in[4];
    const float* bet   = (const float*)d_in[5];
    const float* mean  = (const float*)d_in[6];
    const float* var   = (const float*)d_in[7];
    const float* Tp    = (const float*)d_in[8];
    const float* wq    = (const float*)d_in[9];
    const float* bqc   = (const float*)d_in[10];
    const float* wkv   = (const float*)d_in[11];
    const float* bkvc  = (const float*)d_in[12];
    const float* fwq   = (const float*)d_in[13];
    const float* fbq   = (const float*)d_in[14];
    const float* fwk   = (const float*)d_in[15];
    const float* fbk   = (const float*)d_in[16];
    const float* fwv   = (const float*)d_in[17];
    const float* fbv   = (const float*)d_in[18];
    const float* fwo   = (const float*)d_in[19];
    const float* fbo   = (const float*)d_in[20];
    float* out = (float*)d_out;

    cudaFuncSetAttribute(k_conv1, cudaFuncAttributeMaxDynamicSharedMemorySize, C1_SMEM);
    cudaFuncSetAttribute(k_qkv2,  cudaFuncAttributeMaxDynamicSharedMemorySize, QKV_SMEM);

    k_init  <<<1, 1024>>>();
    k_msum  <<<dim3(168, Bn), 256>>>(frame);
    k_nop   <<<1, 32>>>();
    k_conv1 <<<dim3(32, 32, Bn), 256, C1_SMEM>>>(x, wpre, bpre, gam, bet, mean, var);
    k_qkv2  <<<dim3(4, FF, Bn), 256, QKV_SMEM>>>(wq, bqc, wkv, bkvc, frame, Tp,
                                                 fwq, fbq, fwk, fbk, fwv, fbv);
    k3   <<<dim3(168, Bn), 256>>>();
    k456 <<<dim3(96, Bn), 256>>>();
    kmm  <<<Bn, 144>>>(fwo);
    k7   <<<dim3(168, Bn), 256>>>(fbo, out);
    (void)in_sizes; (void)n_in; (void)out_size;
}

// round 14
// speedup vs baseline: 1.2311x; 1.0051x over previous
#include <cuda_runtime.h>
#include <math.h>

#define Bn 4
#define CIN 8
#define HH 252
#define WW 2048
#define CM 16
#define DD 12
#define FF 84
#define LL (FF*WW)          /* 172032 */
#define EPSf 1.01e-8f
#define HROW 2056           /* padded row: 4 zero cols each side */
#define HOFF 4
#define CSH 8.0f            /* fixed softmax shift */

typedef unsigned long long u64;

__device__ __forceinline__ u64 fma2(u64 a, u64 b, u64 c){
    u64 d; asm("fma.rn.f32x2 %0, %1, %2, %3;" : "=l"(d) : "l"(a), "l"(b), "l"(c)); return d;
}
__device__ __forceinline__ u64 pk2(float lo, float hi){
    u64 r; asm("mov.b64 %0, {%1, %2};" : "=l"(r) : "f"(lo), "f"(hi)); return r;
}
__device__ __forceinline__ void upk2(u64 v, float& lo, float& hi){
    asm("mov.b64 {%0, %1}, %2;" : "=f"(lo), "=f"(hi) : "l"(v));
}
__device__ __forceinline__ float wredsum(float v){
    #pragma unroll
    for (int o = 16; o > 0; o >>= 1) v += __shfl_xor_sync(0xffffffffu, v, o);
    return v;
}
__device__ __forceinline__ float sigm(float x){
    float t;
    asm("tanh.approx.f32 %0, %1;" : "=f"(t) : "f"(x*0.5f));
    return fmaf(0.5f, t, 0.5f);
}
__device__ __forceinline__ float lrelu(float v){ return v >= 0.f ? v : 0.01f*v; }

// ------------- scratch (device globals; zero-initialized at load) -------------
__device__ __align__(16) float g_h [(size_t)Bn*CM*HH*HROW];  // padded, borders stay 0
// channel-major: [b][d][L]
__device__ __align__(16) float g_q [(size_t)Bn*DD*LL];
__device__ __align__(16) float g_k [(size_t)Bn*DD*LL];
__device__ __align__(16) float g_v [(size_t)Bn*DD*LL];
__device__ float g_msum[Bn], g_sumexp[Bn];
__device__ float g_qsum[Bn][DD], g_ksum[Bn][DD], g_sq[Bn][DD], g_skv[Bn][DD];
__device__ float g_kvm[Bn][DD*DD];
__device__ float g_M[Bn][DD*DD];

// ------------- K0: zero accumulators -------------
__global__ void k_init(){
    int t = threadIdx.x;
    if (t < Bn){ g_msum[t]=0.f; g_sumexp[t]=0.f; }
    if (t < Bn*DD){
        ((float*)g_qsum)[t]=0.f; ((float*)g_ksum)[t]=0.f;
        ((float*)g_sq)[t]=0.f;   ((float*)g_skv)[t]=0.f;
    }
    if (t < Bn*DD*DD) ((float*)g_kvm)[t]=0.f;
}

// ------------- nop: keeps profile capture window on k_conv1 -------------
__global__ void k_nop(){}

// ------------- mask sum per batch -------------
__global__ void __launch_bounds__(256) k_msum(const float* __restrict__ frame){
    int b = blockIdx.y;
    int i = (blockIdx.x*256 + threadIdx.x)*4;
    float4 v = *(const float4*)(frame + (size_t)b*LL + i);
    float s = v.x + v.y + v.z + v.w;
    s = wredsum(s);
    __shared__ float sr;
    if (threadIdx.x == 0) sr = 0.f;
    __syncthreads();
    if ((threadIdx.x & 31) == 0) atomicAdd(&sr, s);
    __syncthreads();
    if (threadIdx.x == 0) atomicAdd(&g_msum[b], sr);
}

// ------------- K1: conv5x5 + BN + LeakyReLU, ROW-PAIR f32x2, 4 CTAs/SM -------------
#define C1_SMEM (4352*8 + 3200*4 + 32*4)
__global__ void __launch_bounds__(256,4) k_conv1(
    const float* __restrict__ x, const float* __restrict__ wpre,
    const float* __restrict__ bpre, const float* __restrict__ gam,
    const float* __restrict__ bet,  const float* __restrict__ mean,
    const float* __restrict__ var)
{
    extern __shared__ __align__(16) char smc1[];
    u64*   xp  = (u64*)smc1;               // [8c][8pr][68] = 4352 u64
    float* wsf = (float*)(xp + 4352);      // 3200 floats [c][kh][kw][16oc]
    float* bns = wsf + 3200;               // 16
    float* bnc = bns + 16;                 // 16
    int b = blockIdx.z, r0 = blockIdx.y*8, c0 = blockIdx.x*64;
    int tid = threadIdx.x;

    for (int i = tid; i < 3200; i += 256){
        int o = i & 15, rest = i >> 4;
        int kw = rest % 5, kh = (rest/5) % 5, c = rest/25;
        wsf[i] = wpre[((o*CIN + c)*5 + kh)*5 + kw];
    }
    if (tid < 16){
        float s = gam[tid] * rsqrtf(var[tid] + 1e-5f);
        bns[tid] = s;
        bnc[tid] = bet[tid] + (bpre[tid] - mean[tid]) * s;
    }
    for (int i = tid; i < 4352; i += 256){
        int col = i % 68; int t2 = i / 68; int pr = t2 & 7; int c = t2 >> 3;
        int gc = c0 - 2 + col;
        int rA = r0 - 2 + pr, rB = r0 + 2 + pr;
        float vA = 0.f, vB = 0.f;
        if (gc >= 0 && gc < WW){
            const float* xc = x + (((size_t)b*CIN + c)*HH)*WW + gc;
            if (rA >= 0 && rA < HH) vA = xc[(size_t)rA*WW];
            if (rB < HH)            vB = xc[(size_t)rB*WW];
        }
        xp[i] = pk2(vA, vB);
    }
    __syncthreads();

    int half = tid >> 7, lt = tid & 127;
    int prow = lt >> 5, lane = lt & 31, col0 = lane*2;
    u64 acc[8][2];
    #pragma unroll
    for (int o = 0; o < 8; o++){ acc[o][0] = 0ull; acc[o][1] = 0ull; }

    #pragma unroll 1
    for (int c = 0; c < CIN; c++){
        #pragma unroll
        for (int kh = 0; kh < 5; kh++){
            const u64* xr = xp + ((c*8 + prow + kh)*68) + col0;
            ulonglong2 x0 = ((const ulonglong2*)xr)[0];
            ulonglong2 x1 = ((const ulonglong2*)xr)[1];
            ulonglong2 x2 = ((const ulonglong2*)xr)[2];
            u64 X[6] = {x0.x, x0.y, x1.x, x1.y, x2.x, x2.y};
            const float4* wb4 = (const float4*)(wsf + (c*5 + kh)*80 + half*8);
            #pragma unroll
            for (int kw = 0; kw < 5; kw++){
                float4 wa = wb4[kw*4];
                float4 wc = wb4[kw*4 + 1];
                u64 xv0 = X[kw], xv1 = X[kw+1];
                u64 w;
                w = pk2(wa.x, wa.x);
                acc[0][0] = fma2(xv0, w, acc[0][0]); acc[0][1] = fma2(xv1, w, acc[0][1]);
                w = pk2(wa.y, wa.y);
                acc[1][0] = fma2(xv0, w, acc[1][0]); acc[1][1] = fma2(xv1, w, acc[1][1]);
                w = pk2(wa.z, wa.z);
                acc[2][0] = fma2(xv0, w, acc[2][0]); acc[2][1] = fma2(xv1, w, acc[2][1]);
                w = pk2(wa.w, wa.w);
                acc[3][0] = fma2(xv0, w, acc[3][0]); acc[3][1] = fma2(xv1, w, acc[3][1]);
                w = pk2(wc.x, wc.x);
                acc[4][0] = fma2(xv0, w, acc[4][0]); acc[4][1] = fma2(xv1, w, acc[4][1]);
                w = pk2(wc.y, wc.y);
                acc[5][0] = fma2(xv0, w, acc[5][0]); acc[5][1] = fma2(xv1, w, acc[5][1]);
                w = pk2(wc.z, wc.z);
                acc[6][0] = fma2(xv0, w, acc[6][0]); acc[6][1] = fma2(xv1, w, acc[6][1]);
                w = pk2(wc.w, wc.w);
                acc[7][0] = fma2(xv0, w, acc[7][0]); acc[7][1] = fma2(xv1, w, acc[7][1]);
            }
        }
    }
    int rA = r0 + prow, rB = r0 + prow + 4;
    #pragma unroll
    for (int oc = 0; oc < 8; oc++){
        int o = half*8 + oc;
        float s = bns[o], c2 = bnc[o];
        float a0,b0,a1,b1;
        upk2(acc[oc][0], a0, b0); upk2(acc[oc][1], a1, b1);
        float* base = g_h + (((size_t)b*CM + o)*HH)*HROW + HOFF + c0 + col0;
        if (rA < HH)
            *(float2*)(base + (size_t)rA*HROW)
                = make_float2(lrelu(a0*s+c2), lrelu(a1*s+c2));
        if (rB < HH)
            *(float2*)(base + (size_t)rB*HROW)
                = make_float2(lrelu(b0*s+c2), lrelu(b1*s+c2));
    }
}

// ------------- K2: FUSED Q/KV convs + masknorm + projections + sums -------------
// float weights (pk2 on the fly), 3 CTAs/SM, phase-2 register diet.
#define QKV_SMEM (3456*4 + 432*8 + 12288*4 + 96*4)
__global__ void __launch_bounds__(256,3) k_qkv2(
    const float* __restrict__ wq,  const float* __restrict__ bqc,
    const float* __restrict__ wkv, const float* __restrict__ bkvc,
    const float* __restrict__ frame, const float* __restrict__ Tp,
    const float* __restrict__ fwq, const float* __restrict__ fbq,
    const float* __restrict__ fwk, const float* __restrict__ fbk,
    const float* __restrict__ fwv, const float* __restrict__ fbv)
{
    extern __shared__ __align__(16) char smraw[];
    float* wsf = (float*)smraw;                // 3456 floats
    u64*   fwT = (u64*)(wsf + 3456);           // 432
    float* ex  = (float*)(fwT + 432);          // 24*512 floats
    float* cbs = ex + 12288;                   // 24
    float* fbs = cbs + 24;                     // 36
    float* red = fbs + 36;                     // 24

    int b = blockIdx.z, f = blockIdx.y;
    int tid = threadIdx.x;

    for (int i = tid; i < 3456; i += 256){
        int half2 = i / 1728, rem = i % 1728;
        int d = rem % 12, r2 = rem / 12;
        int kw = r2 % 3, kh = (r2/3) % 3, c = r2/9;
        const float* srcw = half2 ? wkv : wq;
        wsf[i] = srcw[((d*CM + c)*3 + kh)*3 + kw];
    }
    for (int i = tid; i < 432; i += 256){
        int wsel = i / 144, rem = i % 144, j = rem / 12, d = rem % 12;
        float w = (wsel == 0 ? fwq : (wsel == 1 ? fwk : fwv))[d*12 + j];
        fwT[i] = pk2(w, w);
    }
    if (tid < 24) cbs[tid] = (tid < 12) ? bqc[tid] : bkvc[tid-12];
    if (tid < 36) fbs[tid] = (tid < 12) ? fbq[tid] : (tid < 24 ? fbk[tid-12] : fbv[tid-24]);
    if (tid < 24) red[tid] = 0.f;
    __syncthreads();

    // ---- Phase 1: conv, 4 positions/thread ----
    {
        int half = tid >> 7, pt = tid & 127, lane = tid & 31;
        int t0 = blockIdx.x*512 + pt*4;
        u64 acc[12][2];
        #pragma unroll
        for (int d = 0; d < 12; d++){
            u64 bb = pk2(cbs[half*12+d], cbs[half*12+d]);
            acc[d][0] = bb; acc[d][1] = bb;
        }
        const float* hb = g_h + (((size_t)b*CM)*HH + 3*f)*HROW + HOFF + t0;
        const float* wsh = wsf + half*1728;
        #pragma unroll 1
        for (int c = 0; c < 16; c++){
            #pragma unroll
            for (int kh = 0; kh < 3; kh++){
                const float* row = hb + ((size_t)c*HH + kh)*HROW;
                float4 F = *(const float4*)row;
                float xm1 = __shfl_up_sync(0xffffffffu, F.w, 1);
                if (lane == 0)  xm1 = row[-1];
                float xp4 = __shfl_down_sync(0xffffffffu, F.x, 1);
                if (lane == 31) xp4 = row[4];
                u64 P[3][2];
                P[0][0] = pk2(xm1, F.x); P[0][1] = pk2(F.y, F.z);
                P[1][0] = pk2(F.x, F.y); P[1][1] = pk2(F.z, F.w);
                P[2][0] = pk2(F.y, F.z); P[2][1] = pk2(F.w, xp4);
                const float4* wp4 = (const float4*)(wsh + (c*3 + kh)*36);
                #pragma unroll
                for (int kw = 0; kw < 3; kw++){
                    float4 wa = wp4[kw*3], wbv = wp4[kw*3+1], wc = wp4[kw*3+2];
                    float wf[12] = {wa.x,wa.y,wa.z,wa.w, wbv.x,wbv.y,wbv.z,wbv.w,
                                    wc.x,wc.y,wc.z,wc.w};
                    #pragma unroll
                    for (int d = 0; d < 12; d++){
                        u64 w2 = pk2(wf[d], wf[d]);
                        acc[d][0] = fma2(P[kw][0], w2, acc[d][0]);
                        acc[d][1] = fma2(P[kw][1], w2, acc[d][1]);
                    }
                }
            }
        }
        float* exb = ex + (half*12)*512 + pt*4;
        #pragma unroll
        for (int d = 0; d < 12; d++){
            float v0,v1,v2,v3;
            upk2(acc[d][0], v0, v1); upk2(acc[d][1], v2, v3);
            *(float4*)(exb + d*512) = make_float4(v0,v1,v2,v3);
        }
    }
    __syncthreads();

    // ---- Phase 2: projections (2 positions/thread; Q first, then kv) ----
    {
        int lp = tid*2;
        size_t l0 = (size_t)f*WW + blockIdx.x*512 + lp;
        u64 cin[12];

        // Q projection + sigmoid
        #pragma unroll
        for (int d = 0; d < 12; d++) cin[d] = *(const u64*)(ex + d*512 + lp);
        {
            float qs[12];
            #pragma unroll
            for (int j = 0; j < 12; j++){
                u64 a = pk2(fbs[j], fbs[j]);
                const ulonglong2* wv = (const ulonglong2*)(fwT + j*12);
                #pragma unroll
                for (int dp = 0; dp < 6; dp++){
                    ulonglong2 w = wv[dp];
                    a = fma2(cin[2*dp  ], w.x, a);
                    a = fma2(cin[2*dp+1], w.y, a);
                }
                float x0, x1; upk2(a, x0, x1);
                x0 = sigm(x0); x1 = sigm(x1);
                *(u64*)(g_q + ((size_t)b*DD + j)*LL + l0) = pk2(x0, x1);
                qs[j] = x0 + x1;
            }
            #pragma unroll
            for (int j = 0; j < 12; j++){
                float s = wredsum(qs[j]);
                if ((tid & 31) == 0) atomicAdd(&red[j], s);
            }
        }
        // load kv conv outputs, masknorm scale
        u64 s2p = pk2(EPSf, EPSf);
        #pragma unroll
        for (int d = 0; d < 12; d++){
            cin[d] = *(const u64*)(ex + (12+d)*512 + lp);
            s2p = fma2(cin[d], cin[d], s2p);
        }
        {
            float s20, s21; upk2(s2p, s20, s21);
            float cf = Tp[0] / g_msum[b];
            float2 mk = *(const float2*)(frame + (size_t)b*LL + l0);
            u64 sc2 = pk2(mk.x*cf*rsqrtf(s20), mk.y*cf*rsqrtf(s21));
            #pragma unroll
            for (int d = 0; d < 12; d++) cin[d] = fma2(cin[d], sc2, 0ull);
        }
        // K projection + sigmoid
        {
            float ks[12];
            #pragma unroll
            for (int j = 0; j < 12; j++){
                u64 a = pk2(fbs[12+j], fbs[12+j]);
                const ulonglong2* wv = (const ulonglong2*)(fwT + 144 + j*12);
                #pragma unroll
                for (int dp = 0; dp < 6; dp++){
                    ulonglong2 w = wv[dp];
                    a = fma2(cin[2*dp  ], w.x, a);
                    a = fma2(cin[2*dp+1], w.y, a);
                }
                float x0, x1; upk2(a, x0, x1);
                x0 = sigm(x0); x1 = sigm(x1);
                *(u64*)(g_k + ((size_t)b*DD + j)*LL + l0) = pk2(x0, x1);
                ks[j] = x0 + x1;
            }
            #pragma unroll
            for (int j = 0; j < 12; j++){
                float s = wredsum(ks[j]);
                if ((tid & 31) == 0) atomicAdd(&red[12+j], s);
            }
        }
        // V projection
        #pragma unroll
        for (int j = 0; j < 12; j++){
            u64 a = pk2(fbs[24+j], fbs[24+j]);
            const ulonglong2* wv = (const ulonglong2*)(fwT + 288 + j*12);
            #pragma unroll
            for (int dp = 0; dp < 6; dp++){
                ulonglong2 w = wv[dp];
                a = fma2(cin[2*dp  ], w.x, a);
                a = fma2(cin[2*dp+1], w.y, a);
            }
            *(u64*)(g_v + ((size_t)b*DD + j)*LL + l0) = a;
        }
    }
    __syncthreads();
    if (tid < 12)       atomicAdd(&g_qsum[b][tid], red[tid]);
    else if (tid < 24)  atomicAdd(&g_ksum[b][tid-12], red[tid]);
}

// ------------- K3: sq/skv sums (4 pos/thread, coalesced) -------------
__global__ void __launch_bounds__(256) k3(){
    int b = blockIdx.y;
    int tid = threadIdx.x;
    int l0 = (blockIdx.x*256 + tid)*4;
    __shared__ float kE[12], qE[12], red[24];
    if (tid < 12){ kE[tid] = g_ksum[b][tid] + EPSf; qE[tid] = g_qsum[b][tid] + EPSf; }
    if (tid < 24) red[tid] = 0.f;
    __syncthreads();
    float4 q4[12], k4[12];
    #pragma unroll
    for (int d = 0; d < 12; d++){
        q4[d] = *(const float4*)(g_q + ((size_t)b*DD + d)*LL + l0);
        k4[d] = *(const float4*)(g_k + ((size_t)b*DD + d)*LL + l0);
    }
    float4 si = make_float4(0,0,0,0), so = make_float4(0,0,0,0);
    #pragma unroll
    for (int d = 0; d < 12; d++){
        si.x += (q4[d].x+EPSf)*kE[d]; si.y += (q4[d].y+EPSf)*kE[d];
        si.z += (q4[d].z+EPSf)*kE[d]; si.w += (q4[d].w+EPSf)*kE[d];
        so.x += (k4[d].x+EPSf)*qE[d]; so.y += (k4[d].y+EPSf)*qE[d];
        so.z += (k4[d].z+EPSf)*qE[d]; so.w += (k4[d].w+EPSf)*qE[d];
    }
    si.x = 1.f/si.x; si.y = 1.f/si.y; si.z = 1.f/si.z; si.w = 1.f/si.w;
    so.x = 1.f/so.x; so.y = 1.f/so.y; so.z = 1.f/so.z; so.w = 1.f/so.w;
    #pragma unroll
    for (int d = 0; d < 12; d++){
        float sqv  = q4[d].x*si.x + q4[d].y*si.y + q4[d].z*si.z + q4[d].w*si.w;
        float skvv = k4[d].x*so.x + k4[d].y*so.y + k4[d].z*so.z + k4[d].w*so.w;
        sqv = wredsum(sqv); skvv = wredsum(skvv);
        if ((tid & 31) == 0){ atomicAdd(&red[d], sqv); atomicAdd(&red[12+d], skvv); }
    }
    __syncthreads();
    if (tid < 12)      atomicAdd(&g_sq[b][tid], red[tid]);
    else if (tid < 24) atomicAdd(&g_skv[b][tid-12], red[tid]);
}

// ------------- K456: cons + exp(cons-CSH) + sumexp + kv outer product -------------
__global__ void __launch_bounds__(256,1) k456(){
    int b = blockIdx.y;
    int tid = threadIdx.x;
    __shared__ float sqE[12];
    if (tid < 12) sqE[tid] = g_sq[b][tid] + EPSf;
    __syncthreads();
    float acc[12][12];
    #pragma unroll
    for (int d = 0; d < 12; d++)
        #pragma unroll
        for (int m = 0; m < 12; m++) acc[d][m] = 0.f;
    float se = 0.f;

    for (int l = blockIdx.x*256 + tid; l < LL; l += 96*256){
        float k[12], v[12];
        #pragma unroll
        for (int d = 0; d < 12; d++){
            k[d] = g_k[((size_t)b*DD + d)*LL + l];
            v[d] = g_v[((size_t)b*DD + d)*LL + l];
        }
        float cons = 0.f;
        #pragma unroll
        for (int d = 0; d < 12; d++) cons += (k[d]+EPSf)*sqE[d];
        float e = __expf(cons - CSH);
        se += e;
        #pragma unroll
        for (int m = 0; m < 12; m++) v[m] *= e;
        #pragma unroll
        for (int d = 0; d < 12; d++)
            #pragma unroll
            for (int m = 0; m < 12; m++) acc[d][m] += k[d]*v[m];
    }
    __shared__ float red[144];
    __shared__ float sred;
    for (int i = tid; i < 144; i += 256) red[i] = 0.f;
    if (tid == 0) sred = 0.f;
    __syncthreads();
    se = wredsum(se);
    if ((tid & 31) == 0) atomicAdd(&sred, se);
    #pragma unroll
    for (int d = 0; d < 12; d++)
        #pragma unroll
        for (int m = 0; m < 12; m++){
            float v = wredsum(acc[d][m]);
            if ((tid & 31) == 0) atomicAdd(&red[d*12+m], v);
        }
    __syncthreads();
    if (tid < 144) atomicAdd(&g_kvm[b][tid], red[tid]);
    if (tid == 0)  atomicAdd(&g_sumexp[b], sred);
}

// ------------- Kmm: M = kv_norm @ Wo -------------
__global__ void kmm(const float* __restrict__ fwo){
    int b = blockIdx.x, tid = threadIdx.x;
    float norm = 172032.0f / g_sumexp[b];
    int d = tid/12, j = tid%12;
    float s = 0.f;
    #pragma unroll
    for (int m = 0; m < 12; m++) s += g_kvm[b][d*12+m]*fwo[m*12+j];
    g_M[b][tid] = s * norm;
}

// ------------- K7: epilogue (4 pos/thread, si recomputed inline) -------------
__global__ void __launch_bounds__(256) k7(const float* __restrict__ fbo, float* __restrict__ out){
    int b = blockIdx.y;
    int tid = threadIdx.x;
    int l0 = (blockIdx.x*256 + tid)*4;
    __shared__ float Ms[144], skvE[12], kE[12], bos[12];
    if (tid < 144) Ms[tid] = g_M[b][tid];
    if (tid < 12){
        skvE[tid] = g_skv[b][tid] + EPSf;
        kE[tid]   = g_ksum[b][tid] + EPSf;
        bos[tid]  = fbo[tid];
    }
    __syncthreads();
    float4 q4[12];
    #pragma unroll
    for (int d = 0; d < 12; d++)
        q4[d] = *(const float4*)(g_q + ((size_t)b*DD + d)*LL + l0);
    float4 cs = make_float4(0,0,0,0), si = make_float4(0,0,0,0);
    #pragma unroll
    for (int d = 0; d < 12; d++){
        cs.x += (q4[d].x+EPSf)*skvE[d]; cs.y += (q4[d].y+EPSf)*skvE[d];
        cs.z += (q4[d].z+EPSf)*skvE[d]; cs.w += (q4[d].w+EPSf)*skvE[d];
        si.x += (q4[d].x+EPSf)*kE[d];   si.y += (q4[d].y+EPSf)*kE[d];
        si.z += (q4[d].z+EPSf)*kE[d];   si.w += (q4[d].w+EPSf)*kE[d];
    }
    float4 sc;
    sc.x = sigm(cs.x)/si.x; sc.y = sigm(cs.y)/si.y;
    sc.z = sigm(cs.z)/si.z; sc.w = sigm(cs.w)/si.w;
    #pragma unroll
    for (int j = 0; j < 12; j++){
        float4 o = make_float4(0,0,0,0);
        #pragma unroll
        for (int d = 0; d < 12; d++){
            float w = Ms[d*12+j];
            o.x += q4[d].x*w; o.y += q4[d].y*w;
            o.z += q4[d].z*w; o.w += q4[d].w*w;
        }
        float4 r;
        r.x = bos[j] + sc.x*o.x; r.y = bos[j] + sc.y*o.y;
        r.z = bos[j] + sc.z*o.z; r.w = bos[j] + sc.w*o.w;
        *(float4*)(out + ((size_t)b*DD + j)*LL + l0) = r;
    }
}

extern "C" void kernel_launch(void* const* d_in, const int* in_sizes, int n_in,
                              void* d_out, int out_size){
    const float* x     = (const float*)d_in[0];
    const float* frame = (const float*)d_in[1];
    const float* wpre  = (const float*)d_in[2];
    const float* bpre  = (const float*)d_in[3];
    const float* gam   = (const float*)d_in[4];
    const float* bet   = (const float*)d_in[5];
    const float* mean  = (const float*)d_in[6];
    const float* var   = (const float*)d_in[7];
    const float* Tp    = (const float*)d_in[8];
    const float* wq    = (const float*)d_in[9];
    const float* bqc   = (const float*)d_in[10];
    const float* wkv   = (const float*)d_in[11];
    const float* bkvc  = (const float*)d_in[12];
    const float* fwq   = (const float*)d_in[13];
    const float* fbq   = (const float*)d_in[14];
    const float* fwk   = (const float*)d_in[15];
    const float* fbk   = (const float*)d_in[16];
    const float* fwv   = (const float*)d_in[17];
    const float* fbv   = (const float*)d_in[18];
    const float* fwo   = (const float*)d_in[19];
    const float* fbo   = (const float*)d_in[20];
    float* out = (float*)d_out;

    cudaFuncSetAttribute(k_conv1, cudaFuncAttributeMaxDynamicSharedMemorySize, C1_SMEM);
    cudaFuncSetAttribute(k_qkv2,  cudaFuncAttributeMaxDynamicSharedMemorySize, QKV_SMEM);

    k_init  <<<1, 1024>>>();
    k_msum  <<<dim3(168, Bn), 256>>>(frame);
    k_nop   <<<1, 32>>>();
    k_conv1 <<<dim3(32, 32, Bn), 256, C1_SMEM>>>(x, wpre, bpre, gam, bet, mean, var);
    k_qkv2  <<<dim3(4, FF, Bn), 256, QKV_SMEM>>>(wq, bqc, wkv, bkvc, frame, Tp,
                                                 fwq, fbq, fwk, fbk, fwv, fbv);
    k3   <<<dim3(168, Bn), 256>>>();
    k456 <<<dim3(96, Bn), 256>>>();
    kmm  <<<Bn, 144>>>(fwo);
    k7   <<<dim3(168, Bn), 256>>>(fbo, out);
    (void)in_sizes; (void)n_in; (void)out_size;
}

// round 16
// speedup vs baseline: 1.2430x; 1.0096x over previous
#include <cuda_runtime.h>
#include <math.h>

#define Bn 4
#define CIN 8
#define HH 252
#define WW 2048
#define CM 16
#define DD 12
#define FF 84
#define LL (FF*WW)          /* 172032 */
#define EPSf 1.01e-8f
#define HROW 2056           /* padded row: 4 zero cols each side */
#define HOFF 4
#define CSH 8.0f            /* fixed softmax shift */

typedef unsigned long long u64;

__device__ __forceinline__ u64 fma2(u64 a, u64 b, u64 c){
    u64 d; asm("fma.rn.f32x2 %0, %1, %2, %3;" : "=l"(d) : "l"(a), "l"(b), "l"(c)); return d;
}
__device__ __forceinline__ u64 pk2(float lo, float hi){
    u64 r; asm("mov.b64 %0, {%1, %2};" : "=l"(r) : "f"(lo), "f"(hi)); return r;
}
__device__ __forceinline__ void upk2(u64 v, float& lo, float& hi){
    asm("mov.b64 {%0, %1}, %2;" : "=f"(lo), "=f"(hi) : "l"(v));
}
__device__ __forceinline__ float wredsum(float v){
    #pragma unroll
    for (int o = 16; o > 0; o >>= 1) v += __shfl_xor_sync(0xffffffffu, v, o);
    return v;
}
__device__ __forceinline__ float sigm(float x){
    float t;
    asm("tanh.approx.f32 %0, %1;" : "=f"(t) : "f"(x*0.5f));
    return fmaf(0.5f, t, 0.5f);
}
__device__ __forceinline__ float lrelu(float v){ return v >= 0.f ? v : 0.01f*v; }

// ------------- scratch (device globals; zero-initialized at load) -------------
__device__ __align__(16) float g_h [(size_t)Bn*CM*HH*HROW];  // padded, borders stay 0
// channel-major: [b][d][L]
__device__ __align__(16) float g_q [(size_t)Bn*DD*LL];
__device__ __align__(16) float g_k [(size_t)Bn*DD*LL];
__device__ __align__(16) float g_v [(size_t)Bn*DD*LL];
__device__ float g_msum[Bn], g_sumexp[Bn];
__device__ float g_qsum[Bn][DD], g_ksum[Bn][DD], g_sq[Bn][DD], g_skv[Bn][DD];
__device__ float g_kvm[Bn][DD*DD];
__device__ float g_M[Bn][DD*DD];

// ------------- K0: zero accumulators -------------
__global__ void k_init(){
    int t = threadIdx.x;
    if (t < Bn){ g_msum[t]=0.f; g_sumexp[t]=0.f; }
    if (t < Bn*DD){
        ((float*)g_qsum)[t]=0.f; ((float*)g_ksum)[t]=0.f;
        ((float*)g_sq)[t]=0.f;   ((float*)g_skv)[t]=0.f;
    }
    if (t < Bn*DD*DD) ((float*)g_kvm)[t]=0.f;
}

// ------------- mask sum per batch -------------
__global__ void __launch_bounds__(256) k_msum(const float* __restrict__ frame){
    int b = blockIdx.y;
    int i = (blockIdx.x*256 + threadIdx.x)*4;
    float4 v = *(const float4*)(frame + (size_t)b*LL + i);
    float s = v.x + v.y + v.z + v.w;
    s = wredsum(s);
    __shared__ float sr;
    if (threadIdx.x == 0) sr = 0.f;
    __syncthreads();
    if ((threadIdx.x & 31) == 0) atomicAdd(&sr, s);
    __syncthreads();
    if (threadIdx.x == 0) atomicAdd(&g_msum[b], sr);
}

// ------------- K1: conv5x5 + BN + LeakyReLU, ROW-PAIR f32x2, quarter oc-split -------------
// grid (32, 32, 4), block 256 = 4 quarters x 64 threads. tile 8 rows x 64 cols.
// quarter q -> oc 4q..4q+3; thread: 1 pair-row (prow in 0..3) x 4 cols x 4 oc.
// Per 80 FMA2: 4 x-LDS.128 + 5 w-LDS.128 + 20 pk2.
#define C1_SMEM (4352*8 + 3200*4 + 32*4)
__global__ void __launch_bounds__(256,4) k_conv1(
    const float* __restrict__ x, const float* __restrict__ wpre,
    const float* __restrict__ bpre, const float* __restrict__ gam,
    const float* __restrict__ bet,  const float* __restrict__ mean,
    const float* __restrict__ var)
{
    extern __shared__ __align__(16) char smc1[];
    u64*   xp  = (u64*)smc1;               // [8c][8pr][68] = 4352 u64
    float* wsf = (float*)(xp + 4352);      // 3200 floats [c][kh][kw][16oc]
    float* bns = wsf + 3200;               // 16
    float* bnc = bns + 16;                 // 16
    int b = blockIdx.z, r0 = blockIdx.y*8, c0 = blockIdx.x*64;
    int tid = threadIdx.x;

    for (int i = tid; i < 3200; i += 256){
        int o = i & 15, rest = i >> 4;
        int kw = rest % 5, kh = (rest/5) % 5, c = rest/25;
        wsf[i] = wpre[((o*CIN + c)*5 + kh)*5 + kw];
    }
    if (tid < 16){
        float s = gam[tid] * rsqrtf(var[tid] + 1e-5f);
        bns[tid] = s;
        bnc[tid] = bet[tid] + (bpre[tid] - mean[tid]) * s;
    }
    // fill xp: pair (x[r0-2+pr][gc], x[r0+2+pr][gc]), gc = c0-2+col
    for (int i = tid; i < 4352; i += 256){
        int col = i % 68; int t2 = i / 68; int pr = t2 & 7; int c = t2 >> 3;
        int gc = c0 - 2 + col;
        int rA = r0 - 2 + pr, rB = r0 + 2 + pr;
        float vA = 0.f, vB = 0.f;
        if (gc >= 0 && gc < WW){
            const float* xc = x + (((size_t)b*CIN + c)*HH)*WW + gc;
            if (rA >= 0 && rA < HH) vA = xc[(size_t)rA*WW];
            if (rB < HH)            vB = xc[(size_t)rB*WW];
        }
        xp[i] = pk2(vA, vB);
    }
    __syncthreads();

    int quarter = tid >> 6, lt = tid & 63;
    int prow = lt >> 4, cg = lt & 15, col0 = cg*4;
    int oc0 = quarter*4;
    u64 acc[4][4];
    #pragma unroll
    for (int o = 0; o < 4; o++)
        #pragma unroll
        for (int i = 0; i < 4; i++) acc[o][i] = 0ull;

    #pragma unroll 1
    for (int c = 0; c < CIN; c++){
        #pragma unroll
        for (int kh = 0; kh < 5; kh++){
            const u64* xr = xp + ((c*8 + prow + kh)*68) + col0;
            ulonglong2 x0 = ((const ulonglong2*)xr)[0];
            ulonglong2 x1 = ((const ulonglong2*)xr)[1];
            ulonglong2 x2 = ((const ulonglong2*)xr)[2];
            ulonglong2 x3 = ((const ulonglong2*)xr)[3];
            u64 X[8] = {x0.x, x0.y, x1.x, x1.y, x2.x, x2.y, x3.x, x3.y};
            const float* wb = wsf + (c*5 + kh)*80 + oc0;
            #pragma unroll
            for (int kw = 0; kw < 5; kw++){
                float4 w4 = *(const float4*)(wb + kw*16);
                u64 w;
                w = pk2(w4.x, w4.x);
                acc[0][0]=fma2(X[kw  ],w,acc[0][0]); acc[0][1]=fma2(X[kw+1],w,acc[0][1]);
                acc[0][2]=fma2(X[kw+2],w,acc[0][2]); acc[0][3]=fma2(X[kw+3],w,acc[0][3]);
                w = pk2(w4.y, w4.y);
                acc[1][0]=fma2(X[kw  ],w,acc[1][0]); acc[1][1]=fma2(X[kw+1],w,acc[1][1]);
                acc[1][2]=fma2(X[kw+2],w,acc[1][2]); acc[1][3]=fma2(X[kw+3],w,acc[1][3]);
                w = pk2(w4.z, w4.z);
                acc[2][0]=fma2(X[kw  ],w,acc[2][0]); acc[2][1]=fma2(X[kw+1],w,acc[2][1]);
                acc[2][2]=fma2(X[kw+2],w,acc[2][2]); acc[2][3]=fma2(X[kw+3],w,acc[2][3]);
                w = pk2(w4.w, w4.w);
                acc[3][0]=fma2(X[kw  ],w,acc[3][0]); acc[3][1]=fma2(X[kw+1],w,acc[3][1]);
                acc[3][2]=fma2(X[kw+2],w,acc[3][2]); acc[3][3]=fma2(X[kw+3],w,acc[3][3]);
            }
        }
    }
    int rA = r0 + prow, rB = r0 + prow + 4;
    #pragma unroll
    for (int oc = 0; oc < 4; oc++){
        int o = oc0 + oc;
        float s = bns[o], c2 = bnc[o];
        float a0,b0,a1,b1,a2,b2,a3,b3;
        upk2(acc[oc][0], a0, b0); upk2(acc[oc][1], a1, b1);
        upk2(acc[oc][2], a2, b2); upk2(acc[oc][3], a3, b3);
        float* base = g_h + (((size_t)b*CM + o)*HH)*HROW + HOFF + c0 + col0;
        if (rA < HH)
            *(float4*)(base + (size_t)rA*HROW)
                = make_float4(lrelu(a0*s+c2), lrelu(a1*s+c2),
                              lrelu(a2*s+c2), lrelu(a3*s+c2));
        if (rB < HH)
            *(float4*)(base + (size_t)rB*HROW)
                = make_float4(lrelu(b0*s+c2), lrelu(b1*s+c2),
                              lrelu(b2*s+c2), lrelu(b3*s+c2));
    }
}

// ------------- K2: FUSED Q/KV convs + masknorm + projections + sums -------------
// float weights (pk2 on the fly), 3 CTAs/SM, phase-2 register diet.
#define QKV_SMEM (3456*4 + 432*8 + 12288*4 + 96*4)
__global__ void __launch_bounds__(256,3) k_qkv2(
    const float* __restrict__ wq,  const float* __restrict__ bqc,
    const float* __restrict__ wkv, const float* __restrict__ bkvc,
    const float* __restrict__ frame, const float* __restrict__ Tp,
    const float* __restrict__ fwq, const float* __restrict__ fbq,
    const float* __restrict__ fwk, const float* __restrict__ fbk,
    const float* __restrict__ fwv, const float* __restrict__ fbv)
{
    extern __shared__ __align__(16) char smraw[];
    float* wsf = (float*)smraw;                // 3456 floats
    u64*   fwT = (u64*)(wsf + 3456);           // 432
    float* ex  = (float*)(fwT + 432);          // 24*512 floats
    float* cbs = ex + 12288;                   // 24
    float* fbs = cbs + 24;                     // 36
    float* red = fbs + 36;                     // 24

    int b = blockIdx.z, f = blockIdx.y;
    int tid = threadIdx.x;

    for (int i = tid; i < 3456; i += 256){
        int half2 = i / 1728, rem = i % 1728;
        int d = rem % 12, r2 = rem / 12;
        int kw = r2 % 3, kh = (r2/3) % 3, c = r2/9;
        const float* srcw = half2 ? wkv : wq;
        wsf[i] = srcw[((d*CM + c)*3 + kh)*3 + kw];
    }
    for (int i = tid; i < 432; i += 256){
        int wsel = i / 144, rem = i % 144, j = rem / 12, d = rem % 12;
        float w = (wsel == 0 ? fwq : (wsel == 1 ? fwk : fwv))[d*12 + j];
        fwT[i] = pk2(w, w);
    }
    if (tid < 24) cbs[tid] = (tid < 12) ? bqc[tid] : bkvc[tid-12];
    if (tid < 36) fbs[tid] = (tid < 12) ? fbq[tid] : (tid < 24 ? fbk[tid-12] : fbv[tid-24]);
    if (tid < 24) red[tid] = 0.f;
    __syncthreads();

    // ---- Phase 1: conv, 4 positions/thread ----
    {
        int half = tid >> 7, pt = tid & 127, lane = tid & 31;
        int t0 = blockIdx.x*512 + pt*4;
        u64 acc[12][2];
        #pragma unroll
        for (int d = 0; d < 12; d++){
            u64 bb = pk2(cbs[half*12+d], cbs[half*12+d]);
            acc[d][0] = bb; acc[d][1] = bb;
        }
        const float* hb = g_h + (((size_t)b*CM)*HH + 3*f)*HROW + HOFF + t0;
        const float* wsh = wsf + half*1728;
        #pragma unroll 1
        for (int c = 0; c < 16; c++){
            #pragma unroll
            for (int kh = 0; kh < 3; kh++){
                const float* row = hb + ((size_t)c*HH + kh)*HROW;
                float4 F = *(const float4*)row;
                float xm1 = __shfl_up_sync(0xffffffffu, F.w, 1);
                if (lane == 0)  xm1 = row[-1];
                float xp4 = __shfl_down_sync(0xffffffffu, F.x, 1);
                if (lane == 31) xp4 = row[4];
                u64 P[3][2];
                P[0][0] = pk2(xm1, F.x); P[0][1] = pk2(F.y, F.z);
                P[1][0] = pk2(F.x, F.y); P[1][1] = pk2(F.z, F.w);
                P[2][0] = pk2(F.y, F.z); P[2][1] = pk2(F.w, xp4);
                const float4* wp4 = (const float4*)(wsh + (c*3 + kh)*36);
                #pragma unroll
                for (int kw = 0; kw < 3; kw++){
                    float4 wa = wp4[kw*3], wbv = wp4[kw*3+1], wc = wp4[kw*3+2];
                    float wf[12] = {wa.x,wa.y,wa.z,wa.w, wbv.x,wbv.y,wbv.z,wbv.w,
                                    wc.x,wc.y,wc.z,wc.w};
                    #pragma unroll
                    for (int d = 0; d < 12; d++){
                        u64 w2 = pk2(wf[d], wf[d]);
                        acc[d][0] = fma2(P[kw][0], w2, acc[d][0]);
                        acc[d][1] = fma2(P[kw][1], w2, acc[d][1]);
                    }
                }
            }
        }
        float* exb = ex + (half*12)*512 + pt*4;
        #pragma unroll
        for (int d = 0; d < 12; d++){
            float v0,v1,v2,v3;
            upk2(acc[d][0], v0, v1); upk2(acc[d][1], v2, v3);
            *(float4*)(exb + d*512) = make_float4(v0,v1,v2,v3);
        }
    }
    __syncthreads();

    // ---- Phase 2: projections (2 positions/thread; Q first, then kv) ----
    {
        int lp = tid*2;
        size_t l0 = (size_t)f*WW + blockIdx.x*512 + lp;
        u64 cin[12];

        // Q projection + sigmoid
        #pragma unroll
        for (int d = 0; d < 12; d++) cin[d] = *(const u64*)(ex + d*512 + lp);
        {
            float qs[12];
            #pragma unroll
            for (int j = 0; j < 12; j++){
                u64 a = pk2(fbs[j], fbs[j]);
                const ulonglong2* wv = (const ulonglong2*)(fwT + j*12);
                #pragma unroll
                for (int dp = 0; dp < 6; dp++){
                    ulonglong2 w = wv[dp];
                    a = fma2(cin[2*dp  ], w.x, a);
                    a = fma2(cin[2*dp+1], w.y, a);
                }
                float x0, x1; upk2(a, x0, x1);
                x0 = sigm(x0); x1 = sigm(x1);
                *(u64*)(g_q + ((size_t)b*DD + j)*LL + l0) = pk2(x0, x1);
                qs[j] = x0 + x1;
            }
            #pragma unroll
            for (int j = 0; j < 12; j++){
                float s = wredsum(qs[j]);
                if ((tid & 31) == 0) atomicAdd(&red[j], s);
            }
        }
        // load kv conv outputs, masknorm scale
        u64 s2p = pk2(EPSf, EPSf);
        #pragma unroll
        for (int d = 0; d < 12; d++){
            cin[d] = *(const u64*)(ex + (12+d)*512 + lp);
            s2p = fma2(cin[d], cin[d], s2p);
        }
        {
            float s20, s21; upk2(s2p, s20, s21);
            float cf = Tp[0] / g_msum[b];
            float2 mk = *(const float2*)(frame + (size_t)b*LL + l0);
            u64 sc2 = pk2(mk.x*cf*rsqrtf(s20), mk.y*cf*rsqrtf(s21));
            #pragma unroll
            for (int d = 0; d < 12; d++) cin[d] = fma2(cin[d], sc2, 0ull);
        }
        // K projection + sigmoid
        {
            float ks[12];
            #pragma unroll
            for (int j = 0; j < 12; j++){
                u64 a = pk2(fbs[12+j], fbs[12+j]);
                const ulonglong2* wv = (const ulonglong2*)(fwT + 144 + j*12);
                #pragma unroll
                for (int dp = 0; dp < 6; dp++){
                    ulonglong2 w = wv[dp];
                    a = fma2(cin[2*dp  ], w.x, a);
                    a = fma2(cin[2*dp+1], w.y, a);
                }
                float x0, x1; upk2(a, x0, x1);
                x0 = sigm(x0); x1 = sigm(x1);
                *(u64*)(g_k + ((size_t)b*DD + j)*LL + l0) = pk2(x0, x1);
                ks[j] = x0 + x1;
            }
            #pragma unroll
            for (int j = 0; j < 12; j++){
                float s = wredsum(ks[j]);
                if ((tid & 31) == 0) atomicAdd(&red[12+j], s);
            }
        }
        // V projection
        #pragma unroll
        for (int j = 0; j < 12; j++){
            u64 a = pk2(fbs[24+j], fbs[24+j]);
            const ulonglong2* wv = (const ulonglong2*)(fwT + 288 + j*12);
            #pragma unroll
            for (int dp = 0; dp < 6; dp++){
                ulonglong2 w = wv[dp];
                a = fma2(cin[2*dp  ], w.x, a);
                a = fma2(cin[2*dp+1], w.y, a);
            }
            *(u64*)(g_v + ((size_t)b*DD + j)*LL + l0) = a;
        }
    }
    __syncthreads();
    if (tid < 12)       atomicAdd(&g_qsum[b][tid], red[tid]);
    else if (tid < 24)  atomicAdd(&g_ksum[b][tid-12], red[tid]);
}

// ------------- K3: sq/skv sums (4 pos/thread, coalesced) -------------
__global__ void __launch_bounds__(256) k3(){
    int b = blockIdx.y;
    int tid = threadIdx.x;
    int l0 = (blockIdx.x*256 + tid)*4;
    __shared__ float kE[12], qE[12], red[24];
    if (tid < 12){ kE[tid] = g_ksum[b][tid] + EPSf; qE[tid] = g_qsum[b][tid] + EPSf; }
    if (tid < 24) red[tid] = 0.f;
    __syncthreads();
    float4 q4[12], k4[12];
    #pragma unroll
    for (int d = 0; d < 12; d++){
        q4[d] = *(const float4*)(g_q + ((size_t)b*DD + d)*LL + l0);
        k4[d] = *(const float4*)(g_k + ((size_t)b*DD + d)*LL + l0);
    }
    float4 si = make_float4(0,0,0,0), so = make_float4(0,0,0,0);
    #pragma unroll
    for (int d = 0; d < 12; d++){
        si.x += (q4[d].x+EPSf)*kE[d]; si.y += (q4[d].y+EPSf)*kE[d];
        si.z += (q4[d].z+EPSf)*kE[d]; si.w += (q4[d].w+EPSf)*kE[d];
        so.x += (k4[d].x+EPSf)*qE[d]; so.y += (k4[d].y+EPSf)*qE[d];
        so.z += (k4[d].z+EPSf)*qE[d]; so.w += (k4[d].w+EPSf)*qE[d];
    }
    si.x = 1.f/si.x; si.y = 1.f/si.y; si.z = 1.f/si.z; si.w = 1.f/si.w;
    so.x = 1.f/so.x; so.y = 1.f/so.y; so.z = 1.f/so.z; so.w = 1.f/so.w;
    #pragma unroll
    for (int d = 0; d < 12; d++){
        float sqv  = q4[d].x*si.x + q4[d].y*si.y + q4[d].z*si.z + q4[d].w*si.w;
        float skvv = k4[d].x*so.x + k4[d].y*so.y + k4[d].z*so.z + k4[d].w*so.w;
        sqv = wredsum(sqv); skvv = wredsum(skvv);
        if ((tid & 31) == 0){ atomicAdd(&red[d], sqv); atomicAdd(&red[12+d], skvv); }
    }
    __syncthreads();
    if (tid < 12)      atomicAdd(&g_sq[b][tid], red[tid]);
    else if (tid < 24) atomicAdd(&g_skv[b][tid-12], red[tid]);
}

// ------------- K456: cons + exp(cons-CSH) + sumexp + kv outer product -------------
__global__ void __launch_bounds__(256,1) k456(){
    int b = blockIdx.y;
    int tid = threadIdx.x;
    __shared__ float sqE[12];
    if (tid < 12) sqE[tid] = g_sq[b][tid] + EPSf;
    __syncthreads();
    float acc[12][12];
    #pragma unroll
    for (int d = 0; d < 12; d++)
        #pragma unroll
        for (int m = 0; m < 12; m++) acc[d][m] = 0.f;
    float se = 0.f;

    for (int l = blockIdx.x*256 + tid; l < LL; l += 96*256){
        float k[12], v[12];
        #pragma unroll
        for (int d = 0; d < 12; d++){
            k[d] = g_k[((size_t)b*DD + d)*LL + l];
            v[d] = g_v[((size_t)b*DD + d)*LL + l];
        }
        float cons = 0.f;
        #pragma unroll
        for (int d = 0; d < 12; d++) cons += (k[d]+EPSf)*sqE[d];
        float e = __expf(cons - CSH);
        se += e;
        #pragma unroll
        for (int m = 0; m < 12; m++) v[m] *= e;
        #pragma unroll
        for (int d = 0; d < 12; d++)
            #pragma unroll
            for (int m = 0; m < 12; m++) acc[d][m] += k[d]*v[m];
    }
    __shared__ float red[144];
    __shared__ float sred;
    for (int i = tid; i < 144; i += 256) red[i] = 0.f;
    if (tid == 0) sred = 0.f;
    __syncthreads();
    se = wredsum(se);
    if ((tid & 31) == 0) atomicAdd(&sred, se);
    #pragma unroll
    for (int d = 0; d < 12; d++)
        #pragma unroll
        for (int m = 0; m < 12; m++){
            float v = wredsum(acc[d][m]);
            if ((tid & 31) == 0) atomicAdd(&red[d*12+m], v);
        }
    __syncthreads();
    if (tid < 144) atomicAdd(&g_kvm[b][tid], red[tid]);
    if (tid == 0)  atomicAdd(&g_sumexp[b], sred);
}

// ------------- Kmm: M = kv_norm @ Wo -------------
__global__ void kmm(const float* __restrict__ fwo){
    int b = blockIdx.x, tid = threadIdx.x;
    float norm = 172032.0f / g_sumexp[b];
    int d = tid/12, j = tid%12;
    float s = 0.f;
    #pragma unroll
    for (int m = 0; m < 12; m++) s += g_kvm[b][d*12+m]*fwo[m*12+j];
    g_M[b][tid] = s * norm;
}

// ------------- K7: epilogue (4 pos/thread, si recomputed inline) -------------
__global__ void __launch_bounds__(256) k7(const float* __restrict__ fbo, float* __restrict__ out){
    int b = blockIdx.y;
    int tid = threadIdx.x;
    int l0 = (blockIdx.x*256 + tid)*4;
    __shared__ float Ms[144], skvE[12], kE[12], bos[12];
    if (tid < 144) Ms[tid] = g_M[b][tid];
    if (tid < 12){
        skvE[tid] = g_skv[b][tid] + EPSf;
        kE[tid]   = g_ksum[b][tid] + EPSf;
        bos[tid]  = fbo[tid];
    }
    __syncthreads();
    float4 q4[12];
    #pragma unroll
    for (int d = 0; d < 12; d++)
        q4[d] = *(const float4*)(g_q + ((size_t)b*DD + d)*LL + l0);
    float4 cs = make_float4(0,0,0,0), si = make_float4(0,0,0,0);
    #pragma unroll
    for (int d = 0; d < 12; d++){
        cs.x += (q4[d].x+EPSf)*skvE[d]; cs.y += (q4[d].y+EPSf)*skvE[d];
        cs.z += (q4[d].z+EPSf)*skvE[d]; cs.w += (q4[d].w+EPSf)*skvE[d];
        si.x += (q4[d].x+EPSf)*kE[d];   si.y += (q4[d].y+EPSf)*kE[d];
        si.z += (q4[d].z+EPSf)*kE[d];   si.w += (q4[d].w+EPSf)*kE[d];
    }
    float4 sc;
    sc.x = sigm(cs.x)/si.x; sc.y = sigm(cs.y)/si.y;
    sc.z = sigm(cs.z)/si.z; sc.w = sigm(cs.w)/si.w;
    #pragma unroll
    for (int j = 0; j < 12; j++){
        float4 o = make_float4(0,0,0,0);
        #pragma unroll
        for (int d = 0; d < 12; d++){
            float w = Ms[d*12+j];
            o.x += q4[d].x*w; o.y += q4[d].y*w;
            o.z += q4[d].z*w; o.w += q4[d].w*w;
        }
        float4 r;
        r.x = bos[j] + sc.x*o.x; r.y = bos[j] + sc.y*o.y;
        r.z = bos[j] + sc.z*o.z; r.w = bos[j] + sc.w*o.w;
        *(float4*)(out + ((size_t)b*DD + j)*LL + l0) = r;
    }
}

extern "C" void kernel_launch(void* const* d_in, const int* in_sizes, int n_in,
                              void* d_out, int out_size){
    const float* x     = (const float*)d_in[0];
    const float* frame = (const float*)d_in[1];
    const float* wpre  = (const float*)d_in[2];
    const float* bpre  = (const float*)d_in[3];
    const float* gam   = (const float*)d_in[4];
    const float* bet   = (const float*)d_in[5];
    const float* mean  = (const float*)d_in[6];
    const float* var   = (const float*)d_in[7];
    const float* Tp    = (const float*)d_in[8];
    const float* wq    = (const float*)d_in[9];
    const float* bqc   = (const float*)d_in[10];
    const float* wkv   = (const float*)d_in[11];
    const float* bkvc  = (const float*)d_in[12];
    const float* fwq   = (const float*)d_in[13];
    const float* fbq   = (const float*)d_in[14];
    const float* fwk   = (const float*)d_in[15];
    const float* fbk   = (const float*)d_in[16];
    const float* fwv   = (const float*)d_in[17];
    const float* fbv   = (const float*)d_in[18];
    const float* fwo   = (const float*)d_in[19];
    const float* fbo   = (const float*)d_in[20];
    float* out = (float*)d_out;

    cudaFuncSetAttribute(k_conv1, cudaFuncAttributeMaxDynamicSharedMemorySize, C1_SMEM);
    cudaFuncSetAttribute(k_qkv2,  cudaFuncAttributeMaxDynamicSharedMemorySize, QKV_SMEM);

    k_init  <<<1, 1024>>>();
    k_msum  <<<dim3(168, Bn), 256>>>(frame);
    k_conv1 <<<dim3(32, 32, Bn), 256, C1_SMEM>>>(x, wpre, bpre, gam, bet, mean, var);
    k_qkv2  <<<dim3(4, FF, Bn), 256, QKV_SMEM>>>(wq, bqc, wkv, bkvc, frame, Tp,
                                                 fwq, fbq, fwk, fbk, fwv, fbv);
    k3   <<<dim3(168, Bn), 256>>>();
    k456 <<<dim3(96, Bn), 256>>>();
    kmm  <<<Bn, 144>>>(fwo);
    k7   <<<dim3(168, Bn), 256>>>(fbo, out);
    (void)in_sizes; (void)n_in; (void)out_size;
}